// round 2
// baseline (speedup 1.0000x reference)
#include <cuda_runtime.h>
#include <cstddef>
#include <cstdint>

// Problem constants
#define PB 8
#define PL 1024
#define PD 512
#define PH 8
#define PDK 64
#define PDV 64
#define BLD (PB*PL)            // 8192 rows

// ------------------------- scratch (device globals; no runtime alloc) -------
__device__ float g_Q  [BLD*PD];
__device__ float g_K  [BLD*PD];
__device__ float g_V  [BLD*PD];
__device__ float g_O  [BLD*PD];
__device__ float g_OFC[BLD*PD];
__device__ float g_HS [BLD*PD];
__device__ float g_H2 [BLD*PD];
__device__ float g_SS [PB*2*PD];

// ------------------------- generic SGEMM: C = A@W + bias --------------------
// A: [M,K] row-major, W: [K,N] row-major, C: [M,N]. M%128==0, N%128==0, K%8==0.
__global__ __launch_bounds__(256)
void sgemm_bias(const float* __restrict__ A, const float* __restrict__ W,
                const float* __restrict__ bias, float* __restrict__ C,
                int M, int N, int K) {
    __shared__ float As[8][128];
    __shared__ float Bs[8][128];
    const int bx = blockIdx.x, by = blockIdx.y;
    const int t  = threadIdx.x;
    const int tx = t & 15, ty = t >> 4;

    const float* Ab = A + (size_t)by * 128 * K;
    const float* Wb = W + (size_t)bx * 128;

    float acc[8][8];
    #pragma unroll
    for (int i = 0; i < 8; i++)
        #pragma unroll
        for (int j = 0; j < 8; j++) acc[i][j] = 0.f;

    const int a_row = t >> 1, a_col = (t & 1) * 4;
    const int w_row = t >> 5, w_col = (t & 31) * 4;

    for (int k0 = 0; k0 < K; k0 += 8) {
        float4 av = *(const float4*)&Ab[(size_t)a_row * K + k0 + a_col];
        float4 wv = *(const float4*)&Wb[(size_t)(k0 + w_row) * N + w_col];
        __syncthreads();
        As[a_col + 0][a_row] = av.x;
        As[a_col + 1][a_row] = av.y;
        As[a_col + 2][a_row] = av.z;
        As[a_col + 3][a_row] = av.w;
        *(float4*)&Bs[w_row][w_col] = wv;
        __syncthreads();
        #pragma unroll
        for (int k = 0; k < 8; k++) {
            float af[8], bf[8];
            *(float4*)&af[0] = *(float4*)&As[k][ty * 8];
            *(float4*)&af[4] = *(float4*)&As[k][ty * 8 + 4];
            *(float4*)&bf[0] = *(float4*)&Bs[k][tx * 8];
            *(float4*)&bf[4] = *(float4*)&Bs[k][tx * 8 + 4];
            #pragma unroll
            for (int i = 0; i < 8; i++)
                #pragma unroll
                for (int j = 0; j < 8; j++)
                    acc[i][j] += af[i] * bf[j];
        }
    }
    const int row0 = by * 128 + ty * 8;
    const int col0 = bx * 128 + tx * 8;
    #pragma unroll
    for (int i = 0; i < 8; i++) {
        float4 o0, o1;
        o0.x = acc[i][0] + bias[col0 + 0];
        o0.y = acc[i][1] + bias[col0 + 1];
        o0.z = acc[i][2] + bias[col0 + 2];
        o0.w = acc[i][3] + bias[col0 + 3];
        o1.x = acc[i][4] + bias[col0 + 4];
        o1.y = acc[i][5] + bias[col0 + 5];
        o1.z = acc[i][6] + bias[col0 + 6];
        o1.w = acc[i][7] + bias[col0 + 7];
        *(float4*)&C[(size_t)(row0 + i) * N + col0]     = o0;
        *(float4*)&C[(size_t)(row0 + i) * N + col0 + 4] = o1;
    }
}

// ------------------------- FiLM scale/shift prep ----------------------------
// ss[b, 0:1024] = silu(latent[b]) @ Ws1 + bs1
__global__ __launch_bounds__(128)
void film_prep(const float* __restrict__ latent, const float* __restrict__ Ws1,
               const float* __restrict__ bs1, float* __restrict__ ss) {
    const int b = blockIdx.y;
    const int col = blockIdx.x * 128 + threadIdx.x;
    __shared__ float ls[512];
    for (int i = threadIdx.x; i < 512; i += 128) {
        float x = latent[(size_t)b * 512 + i];
        ls[i] = x / (1.f + __expf(-x));
    }
    __syncthreads();
    float sum = 0.f;
    #pragma unroll 8
    for (int k = 0; k < 512; k++) sum += ls[k] * Ws1[(size_t)k * 1024 + col];
    ss[(size_t)b * 1024 + col] = sum + bs1[col];
}

// ------------------------- block reduce helper ------------------------------
__device__ __forceinline__ float2 blockReduceSum2(float s1, float s2) {
    __shared__ float sh[8];
    #pragma unroll
    for (int off = 16; off; off >>= 1) {
        s1 += __shfl_xor_sync(0xffffffffu, s1, off);
        s2 += __shfl_xor_sync(0xffffffffu, s2, off);
    }
    const int w = threadIdx.x >> 5;
    if ((threadIdx.x & 31) == 0) { sh[w * 2] = s1; sh[w * 2 + 1] = s2; }
    __syncthreads();
    float a = 0.f, b = 0.f;
    const int nw = blockDim.x >> 5;
    for (int i = 0; i < nw; i++) { a += sh[i * 2]; b += sh[i * 2 + 1]; }
    return make_float2(a, b);
}

// ------------------------- FiLM apply: LN -> FiLM -> SiLU -------------------
__global__ __launch_bounds__(128)
void film_apply(const float* __restrict__ ofc, const float* __restrict__ ss,
                const float* __restrict__ g, const float* __restrict__ be,
                float* __restrict__ hs) {
    const int row = blockIdx.x;
    const int b = row >> 10;
    const int t = threadIdx.x;
    const float* xr = ofc + (size_t)row * 512;
    float x[4]; float s1 = 0.f, s2 = 0.f;
    #pragma unroll
    for (int i = 0; i < 4; i++) {
        x[i] = xr[t + i * 128];
        s1 += x[i]; s2 += x[i] * x[i];
    }
    float2 r = blockReduceSum2(s1, s2);
    const float mean = r.x * (1.f / 512.f);
    const float var  = r.y * (1.f / 512.f) - mean * mean;
    const float rstd = rsqrtf(var + 1e-5f);
    float* hr = hs + (size_t)row * 512;
    const float* ssb = ss + (size_t)b * 1024;
    #pragma unroll
    for (int i = 0; i < 4; i++) {
        const int c = t + i * 128;
        float ln = (x[i] - mean) * rstd * g[c] + be[c];
        float h = ln * (1.f + ssb[c]) + ssb[512 + c];
        hr[c] = h / (1.f + __expf(-h));
    }
}

// ------------------------- final: LN(h2 + residual) -------------------------
__global__ __launch_bounds__(128)
void final_ln(const float* __restrict__ h2, const float* __restrict__ resid,
              const float* __restrict__ g, const float* __restrict__ be,
              float* __restrict__ out) {
    const int row = blockIdx.x;
    const int t = threadIdx.x;
    const float* hr = h2 + (size_t)row * 512;
    const float* rr = resid + (size_t)row * 512;
    float x[4]; float s1 = 0.f, s2 = 0.f;
    #pragma unroll
    for (int i = 0; i < 4; i++) {
        x[i] = hr[t + i * 128] + rr[t + i * 128];
        s1 += x[i]; s2 += x[i] * x[i];
    }
    float2 r = blockReduceSum2(s1, s2);
    const float mean = r.x * (1.f / 512.f);
    const float var  = r.y * (1.f / 512.f) - mean * mean;
    const float rstd = rsqrtf(var + 1e-6f);
    float* orow = out + (size_t)row * 512;
    #pragma unroll
    for (int i = 0; i < 4; i++) {
        const int c = t + i * 128;
        orow[c] = (x[i] - mean) * rstd * g[c] + be[c];
    }
}

// ------------------------- fused attention ----------------------------------
// One CTA per (b, h, 32 q rows). Full 32x1024 score tile lives in smem:
// S = QK^T/8 -> softmax (write attn output once) -> O = P@V.
#define AT_SMEM ((32*1024 + 32*64 + 64*65) * 4)

__global__ __launch_bounds__(256, 1)
void attn_kernel(const float* __restrict__ Q, const float* __restrict__ K,
                 const float* __restrict__ V, float* __restrict__ attn,
                 float* __restrict__ O) {
    extern __shared__ float sm[];
    float* s_s  = sm;                  // [32][1024]
    float* q_s  = sm + 32 * 1024;      // [32][64]
    float* kv_s = q_s + 32 * 64;       // [64][65] (padded rows)

    const int b = blockIdx.z, h = blockIdx.y;
    const int q0 = blockIdx.x * 32;
    const int t = threadIdx.x;
    const int tq = t >> 4, tk = t & 15;

    // load Q tile [32,64]
    const float* Qb = Q + ((size_t)(b * 1024 + q0)) * 512 + h * 64;
    for (int i = t; i < 512; i += 256) {        // float4 units
        int r = i >> 4, c4 = i & 15;
        *(float4*)&q_s[r * 64 + c4 * 4] = *(const float4*)&Qb[(size_t)r * 512 + c4 * 4];
    }

    // ---- Phase 1: scores S = Q K^T * 0.125 ----
    const float* Kb = K + (size_t)b * 1024 * 512 + h * 64;
    for (int kc = 0; kc < 1024; kc += 64) {
        __syncthreads();
        for (int i = t; i < 1024; i += 256) {   // 64 rows x 16 float4
            int r = i >> 4, c4 = i & 15;
            float4 vv = *(const float4*)&Kb[(size_t)(kc + r) * 512 + c4 * 4];
            float* dst = &kv_s[r * 65 + c4 * 4];
            dst[0] = vv.x; dst[1] = vv.y; dst[2] = vv.z; dst[3] = vv.w;
        }
        __syncthreads();
        float acc0[4] = {0.f, 0.f, 0.f, 0.f};
        float acc1[4] = {0.f, 0.f, 0.f, 0.f};
        const float* qr0 = &q_s[(2 * tq) * 64];
        const float* qr1 = &q_s[(2 * tq + 1) * 64];
        #pragma unroll 8
        for (int d = 0; d < 64; d++) {
            float a0 = qr0[d], a1 = qr1[d];
            #pragma unroll
            for (int j = 0; j < 4; j++) {
                float kb = kv_s[(4 * tk + j) * 65 + d];
                acc0[j] += a0 * kb;
                acc1[j] += a1 * kb;
            }
        }
        #pragma unroll
        for (int j = 0; j < 4; j++) {
            s_s[(size_t)(2 * tq) * 1024 + kc + 4 * tk + j]     = acc0[j] * 0.125f;
            s_s[(size_t)(2 * tq + 1) * 1024 + kc + 4 * tk + j] = acc1[j] * 0.125f;
        }
    }
    __syncthreads();

    // ---- Phase 2: row softmax, write attn output ----
    const int w = t >> 5, lane = t & 31;
    float* attn_b = attn + (((size_t)(b * 8 + h)) * 1024 + q0) * 1024;
    for (int r = 4 * w; r < 4 * w + 4; r++) {
        float* srow = s_s + (size_t)r * 1024;
        float mx = -1e30f;
        for (int i = lane; i < 1024; i += 32) mx = fmaxf(mx, srow[i]);
        #pragma unroll
        for (int off = 16; off; off >>= 1)
            mx = fmaxf(mx, __shfl_xor_sync(0xffffffffu, mx, off));
        float sum = 0.f;
        for (int i = lane; i < 1024; i += 32) {
            float e = __expf(srow[i] - mx);
            srow[i] = e; sum += e;
        }
        #pragma unroll
        for (int off = 16; off; off >>= 1)
            sum += __shfl_xor_sync(0xffffffffu, sum, off);
        float inv = 1.f / sum;
        float* arow = attn_b + (size_t)r * 1024;
        for (int i = lane; i < 1024; i += 32) {
            float p = srow[i] * inv;
            srow[i] = p;
            arow[i] = p;
        }
    }
    __syncthreads();

    // ---- Phase 3: O = P @ V ----
    const float* Vb = V + (size_t)b * 1024 * 512 + h * 64;
    float o0[4] = {0.f, 0.f, 0.f, 0.f};
    float o1[4] = {0.f, 0.f, 0.f, 0.f};
    for (int kc = 0; kc < 1024; kc += 64) {
        __syncthreads();
        for (int i = t; i < 1024; i += 256) {
            int r = i >> 4, c4 = i & 15;
            float4 vv = *(const float4*)&Vb[(size_t)(kc + r) * 512 + c4 * 4];
            float* dst = &kv_s[r * 65 + c4 * 4];
            dst[0] = vv.x; dst[1] = vv.y; dst[2] = vv.z; dst[3] = vv.w;
        }
        __syncthreads();
        const float* p0 = &s_s[(size_t)(2 * tq) * 1024 + kc];
        const float* p1 = &s_s[(size_t)(2 * tq + 1) * 1024 + kc];
        #pragma unroll 8
        for (int kv = 0; kv < 64; kv++) {
            float x0 = p0[kv], x1 = p1[kv];
            #pragma unroll
            for (int j = 0; j < 4; j++) {
                float vb = kv_s[kv * 65 + 4 * tk + j];
                o0[j] += x0 * vb;
                o1[j] += x1 * vb;
            }
        }
    }
    float* Ob = O + ((size_t)(b * 1024 + q0)) * 512 + h * 64;
    #pragma unroll
    for (int j = 0; j < 4; j++) {
        Ob[(size_t)(2 * tq) * 512 + 4 * tk + j]     = o0[j];
        Ob[(size_t)(2 * tq + 1) * 512 + 4 * tk + j] = o1[j];
    }
}

// ------------------------- launch -------------------------------------------
extern "C" void kernel_launch(void* const* d_in, const int* in_sizes, int n_in,
                              void* d_out, int out_size) {
    const float* q      = (const float*)d_in[0];
    const float* k      = (const float*)d_in[1];
    const float* v      = (const float*)d_in[2];
    const float* latent = (const float*)d_in[3];
    const float* Wq     = (const float*)d_in[4];
    const float* bq     = (const float*)d_in[5];
    const float* Wk     = (const float*)d_in[6];
    const float* bk     = (const float*)d_in[7];
    const float* Wv     = (const float*)d_in[8];
    const float* bv     = (const float*)d_in[9];
    const float* Wfc    = (const float*)d_in[10];
    const float* bfc    = (const float*)d_in[11];
    const float* Ws1    = (const float*)d_in[12];
    const float* bs1    = (const float*)d_in[13];
    const float* Ws2    = (const float*)d_in[14];
    const float* bs2    = (const float*)d_in[15];
    const float* en_g   = (const float*)d_in[16];
    const float* en_b   = (const float*)d_in[17];
    const float* ln_g   = (const float*)d_in[18];
    const float* ln_b   = (const float*)d_in[19];

    float* out  = (float*)d_out;                       // [B,L,D]
    float* attn = out + (size_t)BLD * PD;              // [B,H,L,L]

    float *gQ, *gK, *gV, *gO, *gOFC, *gHS, *gH2, *gSS;
    cudaGetSymbolAddress((void**)&gQ,  g_Q);
    cudaGetSymbolAddress((void**)&gK,  g_K);
    cudaGetSymbolAddress((void**)&gV,  g_V);
    cudaGetSymbolAddress((void**)&gO,  g_O);
    cudaGetSymbolAddress((void**)&gOFC,g_OFC);
    cudaGetSymbolAddress((void**)&gHS, g_HS);
    cudaGetSymbolAddress((void**)&gH2, g_H2);
    cudaGetSymbolAddress((void**)&gSS, g_SS);

    cudaFuncSetAttribute(attn_kernel,
                         cudaFuncAttributeMaxDynamicSharedMemorySize, AT_SMEM);

    dim3 gGemm(PD / 128, BLD / 128);   // (4, 64)

    film_prep<<<dim3(8, PB), 128>>>(latent, Ws1, bs1, gSS);
    sgemm_bias<<<gGemm, 256>>>(q, Wq, bq, gQ, BLD, PD, PD);
    sgemm_bias<<<gGemm, 256>>>(k, Wk, bk, gK, BLD, PD, PD);
    sgemm_bias<<<gGemm, 256>>>(v, Wv, bv, gV, BLD, PD, PD);
    attn_kernel<<<dim3(PL / 32, PH, PB), 256, AT_SMEM>>>(gQ, gK, gV, attn, gO);
    sgemm_bias<<<gGemm, 256>>>(gO, Wfc, bfc, gOFC, BLD, PD, PD);
    film_apply<<<BLD, 128>>>(gOFC, gSS, en_g, en_b, gHS);
    sgemm_bias<<<gGemm, 256>>>(gHS, Ws2, bs2, gH2, BLD, PD, PD);
    final_ln<<<BLD, 128>>>(gH2, q, ln_g, ln_b, out);
}

// round 6
// speedup vs baseline: 1.4637x; 1.4637x over previous
#include <cuda_runtime.h>
#include <cstddef>
#include <cstdint>

typedef unsigned long long ull;

// Packed fp32x2 ops (sm_100+/PTX ISA 8.6). 2x FFMA issue rate vs 3-reg FFMA.
#define FMA2(d,a,b) asm("fma.rn.f32x2 %0, %1, %2, %0;" : "+l"(d) : "l"(a), "l"(b))
#define ADD2(d,a)   asm("add.rn.f32x2 %0, %0, %1;"     : "+l"(d) : "l"(a))
#define PACK2(out,f) asm("mov.b64 %0, {%1, %1};" : "=l"(out) : "r"(__float_as_uint(f)))

// Problem constants
#define PB 8
#define PL 1024
#define PD 512
#define PH 8
#define BLD (PB*PL)            // 8192 rows

// ------------------------- scratch (device globals; no runtime alloc) -------
__device__ float g_Q  [BLD*PD];
__device__ float g_K  [BLD*PD];
__device__ float g_V  [BLD*PD];
__device__ float g_O  [BLD*PD];
__device__ float g_OFC[BLD*PD];
__device__ float g_HS [BLD*PD];
__device__ float g_H2 [BLD*PD];
__device__ float g_SS [PB*2*PD];

// ------------------------- SGEMM (f32x2): C = A@W + bias --------------------
// A: [M,K] row-major, W: [K,N] row-major, C: [M,N]. M%128==0, N%128==0, K%16==0.
__global__ __launch_bounds__(256, 2)
void sgemm_bias(const float* __restrict__ A, const float* __restrict__ W,
                const float* __restrict__ bias, float* __restrict__ C,
                int M, int N, int K) {
    __shared__ float As[16][129];
    __shared__ float Bs[16][128];
    const int bx = blockIdx.x, by = blockIdx.y;
    const int t  = threadIdx.x;
    const int tx = t & 15, ty = t >> 4;

    const float* Ab = A + (size_t)by * 128 * K;
    const float* Wb = W + (size_t)bx * 128;

    ull acc[8][4];
    #pragma unroll
    for (int i = 0; i < 8; i++)
        #pragma unroll
        for (int j = 0; j < 4; j++) acc[i][j] = 0ULL;

    const int a_row = t >> 1, a_half = (t & 1) * 8;
    const int w_row = t >> 5, w_col = (t & 31) * 4;

    for (int k0 = 0; k0 < K; k0 += 16) {
        float4 av0 = *(const float4*)&Ab[(size_t)a_row * K + k0 + a_half];
        float4 av1 = *(const float4*)&Ab[(size_t)a_row * K + k0 + a_half + 4];
        float4 wv0 = *(const float4*)&Wb[(size_t)(k0 + w_row) * N + w_col];
        float4 wv1 = *(const float4*)&Wb[(size_t)(k0 + w_row + 8) * N + w_col];
        __syncthreads();
        As[a_half + 0][a_row] = av0.x;
        As[a_half + 1][a_row] = av0.y;
        As[a_half + 2][a_row] = av0.z;
        As[a_half + 3][a_row] = av0.w;
        As[a_half + 4][a_row] = av1.x;
        As[a_half + 5][a_row] = av1.y;
        As[a_half + 6][a_row] = av1.z;
        As[a_half + 7][a_row] = av1.w;
        *(float4*)&Bs[w_row][w_col]     = wv0;
        *(float4*)&Bs[w_row + 8][w_col] = wv1;
        __syncthreads();
        #pragma unroll
        for (int k = 0; k < 16; k++) {
            ulonglong2 bb0 = *(const ulonglong2*)&Bs[k][tx * 8];
            ulonglong2 bb1 = *(const ulonglong2*)&Bs[k][tx * 8 + 4];
            #pragma unroll
            for (int i = 0; i < 8; i++) {
                ull a2; PACK2(a2, As[k][ty * 8 + i]);
                FMA2(acc[i][0], a2, bb0.x);
                FMA2(acc[i][1], a2, bb0.y);
                FMA2(acc[i][2], a2, bb1.x);
                FMA2(acc[i][3], a2, bb1.y);
            }
        }
    }
    const int row0 = by * 128 + ty * 8;
    const int col0 = bx * 128 + tx * 8;
    float4 b0 = *(const float4*)&bias[col0];
    float4 b1 = *(const float4*)&bias[col0 + 4];
    #pragma unroll
    for (int i = 0; i < 8; i++) {
        float2 p0 = *(float2*)&acc[i][0];
        float2 p1 = *(float2*)&acc[i][1];
        float2 p2 = *(float2*)&acc[i][2];
        float2 p3 = *(float2*)&acc[i][3];
        float4 o0 = make_float4(p0.x + b0.x, p0.y + b0.y, p1.x + b0.z, p1.y + b0.w);
        float4 o1 = make_float4(p2.x + b1.x, p2.y + b1.y, p3.x + b1.z, p3.y + b1.w);
        *(float4*)&C[(size_t)(row0 + i) * N + col0]     = o0;
        *(float4*)&C[(size_t)(row0 + i) * N + col0 + 4] = o1;
    }
}

// ------------------------- FiLM scale/shift prep ----------------------------
__global__ __launch_bounds__(128)
void film_prep(const float* __restrict__ latent, const float* __restrict__ Ws1,
               const float* __restrict__ bs1, float* __restrict__ ss) {
    const int b = blockIdx.y;
    const int col = blockIdx.x * 128 + threadIdx.x;
    __shared__ float ls[512];
    for (int i = threadIdx.x; i < 512; i += 128) {
        float x = latent[(size_t)b * 512 + i];
        ls[i] = x / (1.f + __expf(-x));
    }
    __syncthreads();
    float sum = 0.f;
    #pragma unroll 8
    for (int k = 0; k < 512; k++) sum += ls[k] * Ws1[(size_t)k * 1024 + col];
    ss[(size_t)b * 1024 + col] = sum + bs1[col];
}

// ------------------------- block reduce helper ------------------------------
__device__ __forceinline__ float2 blockReduceSum2(float s1, float s2) {
    __shared__ float sh[8];
    #pragma unroll
    for (int off = 16; off; off >>= 1) {
        s1 += __shfl_xor_sync(0xffffffffu, s1, off);
        s2 += __shfl_xor_sync(0xffffffffu, s2, off);
    }
    const int w = threadIdx.x >> 5;
    if ((threadIdx.x & 31) == 0) { sh[w * 2] = s1; sh[w * 2 + 1] = s2; }
    __syncthreads();
    float a = 0.f, b = 0.f;
    const int nw = blockDim.x >> 5;
    for (int i = 0; i < nw; i++) { a += sh[i * 2]; b += sh[i * 2 + 1]; }
    return make_float2(a, b);
}

// ------------------------- FiLM apply: LN -> FiLM -> SiLU -------------------
__global__ __launch_bounds__(128)
void film_apply(const float* __restrict__ ofc, const float* __restrict__ ss,
                const float* __restrict__ g, const float* __restrict__ be,
                float* __restrict__ hs) {
    const int row = blockIdx.x;
    const int b = row >> 10;
    const int t = threadIdx.x;
    const float* xr = ofc + (size_t)row * 512;
    float x[4]; float s1 = 0.f, s2 = 0.f;
    #pragma unroll
    for (int i = 0; i < 4; i++) {
        x[i] = xr[t + i * 128];
        s1 += x[i]; s2 += x[i] * x[i];
    }
    float2 r = blockReduceSum2(s1, s2);
    const float mean = r.x * (1.f / 512.f);
    const float var  = r.y * (1.f / 512.f) - mean * mean;
    const float rstd = rsqrtf(var + 1e-5f);
    float* hr = hs + (size_t)row * 512;
    const float* ssb = ss + (size_t)b * 1024;
    #pragma unroll
    for (int i = 0; i < 4; i++) {
        const int c = t + i * 128;
        float ln = (x[i] - mean) * rstd * g[c] + be[c];
        float h = ln * (1.f + ssb[c]) + ssb[512 + c];
        hr[c] = h / (1.f + __expf(-h));
    }
}

// ------------------------- final: LN(h2 + residual) -------------------------
__global__ __launch_bounds__(128)
void final_ln(const float* __restrict__ h2, const float* __restrict__ resid,
              const float* __restrict__ g, const float* __restrict__ be,
              float* __restrict__ out) {
    const int row = blockIdx.x;
    const int t = threadIdx.x;
    const float* hr = h2 + (size_t)row * 512;
    const float* rr = resid + (size_t)row * 512;
    float x[4]; float s1 = 0.f, s2 = 0.f;
    #pragma unroll
    for (int i = 0; i < 4; i++) {
        x[i] = hr[t + i * 128] + rr[t + i * 128];
        s1 += x[i]; s2 += x[i] * x[i];
    }
    float2 r = blockReduceSum2(s1, s2);
    const float mean = r.x * (1.f / 512.f);
    const float var  = r.y * (1.f / 512.f) - mean * mean;
    const float rstd = rsqrtf(var + 1e-6f);
    float* orow = out + (size_t)row * 512;
    #pragma unroll
    for (int i = 0; i < 4; i++) {
        const int c = t + i * 128;
        orow[c] = (x[i] - mean) * rstd * g[c] + be[c];
    }
}

// ------------------------- fused attention (f32x2, tiled) -------------------
// One CTA per (b, h, 32 q rows). smem:
//   s_s   [32][1024]      score/prob tile          (32768 fl)
//   q_dup [64][64]        Q d-major, values duplicated for f32x2 (4096 fl)
//   rB    union:
//     phase1: kT [64][258]  K chunk transposed (d-major), 256 k-cols (16512 fl)
//     phase3: p_T[128][33] + v_s[128][66]                       (12672 fl)
#define AT_FL   (32*1024 + 64*64 + 64*258)
#define AT_SMEM (AT_FL * 4)

__global__ __launch_bounds__(256, 1)
void attn_kernel(const float* __restrict__ Q, const float* __restrict__ K,
                 const float* __restrict__ V, float* __restrict__ attn,
                 float* __restrict__ O) {
    extern __shared__ float sm[];
    float* s_s   = sm;                    // 32*1024
    float* q_dup = sm + 32 * 1024;        // 64*64
    float* rB    = q_dup + 64 * 64;       // 64*258 region

    const int b = blockIdx.z, h = blockIdx.y;
    const int q0 = blockIdx.x * 32;
    const int t = threadIdx.x;
    const int warp = t >> 5, lane = t & 31;

    // ---- load Q -> q_dup (d-major, each value duplicated as f32x2 pair) ----
    const float* Qb = Q + ((size_t)(b * 1024 + q0)) * 512 + h * 64;
    #pragma unroll
    for (int it = 0; it < 2; it++) {
        int u = t + it * 256;             // 0..511 float4 units
        int r = u >> 4, c4 = u & 15;
        float4 f = *(const float4*)&Qb[(size_t)r * 512 + 4 * c4];
        ull p0, p1, p2, p3;
        PACK2(p0, f.x); PACK2(p1, f.y); PACK2(p2, f.z); PACK2(p3, f.w);
        *(ull*)&q_dup[(4 * c4 + 0) * 64 + 2 * r] = p0;
        *(ull*)&q_dup[(4 * c4 + 1) * 64 + 2 * r] = p1;
        *(ull*)&q_dup[(4 * c4 + 2) * 64 + 2 * r] = p2;
        *(ull*)&q_dup[(4 * c4 + 3) * 64 + 2 * r] = p3;
    }

    // ---- Phase 1: S = Q K^T * 0.125 ----
    // warp = qg (4 q rows), lane = kg (8 k cols). Chunk = 256 k cols.
    const float* Kb = K + (size_t)b * 1024 * 512 + h * 64;
    for (int kc = 0; kc < 1024; kc += 256) {
        __syncthreads();
        #pragma unroll
        for (int it = 0; it < 16; it++) {
            int u = t + it * 256;          // 0..4095 float4 units
            int r = u >> 4, c4 = u & 15;   // r = k-pos in chunk, c4 = d/4
            float4 f = *(const float4*)&Kb[(size_t)(kc + r) * 512 + 4 * c4];
            rB[(4 * c4 + 0) * 258 + r] = f.x;
            rB[(4 * c4 + 1) * 258 + r] = f.y;
            rB[(4 * c4 + 2) * 258 + r] = f.z;
            rB[(4 * c4 + 3) * 258 + r] = f.w;
        }
        __syncthreads();
        ull acc[4][4];
        #pragma unroll
        for (int i = 0; i < 4; i++)
            #pragma unroll
            for (int j = 0; j < 4; j++) acc[i][j] = 0ULL;
        #pragma unroll 4
        for (int d = 0; d < 64; d++) {
            ulonglong2 aa = *(const ulonglong2*)&q_dup[d * 64 + 8 * warp];
            ulonglong2 ab = *(const ulonglong2*)&q_dup[d * 64 + 8 * warp + 4];
            const float* bp = &rB[d * 258 + 8 * lane];
            ull bv0 = *(const ull*)(bp + 0);
            ull bv1 = *(const ull*)(bp + 2);
            ull bv2 = *(const ull*)(bp + 4);
            ull bv3 = *(const ull*)(bp + 6);
            FMA2(acc[0][0], aa.x, bv0); FMA2(acc[0][1], aa.x, bv1);
            FMA2(acc[0][2], aa.x, bv2); FMA2(acc[0][3], aa.x, bv3);
            FMA2(acc[1][0], aa.y, bv0); FMA2(acc[1][1], aa.y, bv1);
            FMA2(acc[1][2], aa.y, bv2); FMA2(acc[1][3], aa.y, bv3);
            FMA2(acc[2][0], ab.x, bv0); FMA2(acc[2][1], ab.x, bv1);
            FMA2(acc[2][2], ab.x, bv2); FMA2(acc[2][3], ab.x, bv3);
            FMA2(acc[3][0], ab.y, bv0); FMA2(acc[3][1], ab.y, bv1);
            FMA2(acc[3][2], ab.y, bv2); FMA2(acc[3][3], ab.y, bv3);
        }
        #pragma unroll
        for (int i = 0; i < 4; i++) {
            float* dst = &s_s[(size_t)(4 * warp + i) * 1024 + kc + 8 * lane];
            #pragma unroll
            for (int j = 0; j < 4; j++) {
                float2 v = *(float2*)&acc[i][j];
                v.x *= 0.125f; v.y *= 0.125f;
                *(float2*)&dst[2 * j] = v;
            }
        }
    }

    // ---- Phase 2: row softmax, write attn output (warp owns its own rows) ----
    float* attn_b = attn + (((size_t)(b * 8 + h)) * 1024 + q0) * 1024;
    for (int r = 4 * warp; r < 4 * warp + 4; r++) {
        float* srow = s_s + (size_t)r * 1024;
        float mx = -1e30f;
        #pragma unroll 8
        for (int i = lane; i < 1024; i += 32) mx = fmaxf(mx, srow[i]);
        #pragma unroll
        for (int off = 16; off; off >>= 1)
            mx = fmaxf(mx, __shfl_xor_sync(0xffffffffu, mx, off));
        float sum = 0.f;
        #pragma unroll 8
        for (int i = lane; i < 1024; i += 32) {
            float e = __expf(srow[i] - mx);
            srow[i] = e; sum += e;
        }
        #pragma unroll
        for (int off = 16; off; off >>= 1)
            sum += __shfl_xor_sync(0xffffffffu, sum, off);
        float inv = 1.f / sum;
        float* arow = attn_b + (size_t)r * 1024;
        #pragma unroll 8
        for (int i = lane; i < 1024; i += 32) {
            float p = srow[i] * inv;
            srow[i] = p;
            arow[i] = p;
        }
    }

    // ---- Phase 3: O = P @ V ----
    // warp = vg (8 v cols at 8*warp). lane: qg = lane>>3 (8 q rows), ks = lane&7
    // (8-way k-split within warp, shfl-reduced at the end).
    float* p_T = rB;                 // [128][33]
    float* v_s = rB + 128 * 33;      // [128][66]
    const float* Vb = V + (size_t)b * 1024 * 512 + h * 64;
    const int vqg = lane >> 3;
    const int ks  = lane & 7;
    ull o2[8][4];
    #pragma unroll
    for (int i = 0; i < 8; i++)
        #pragma unroll
        for (int j = 0; j < 4; j++) o2[i][j] = 0ULL;

    for (int kc = 0; kc < 1024; kc += 128) {
        __syncthreads();
        // transpose P chunk: conflict-free scalar transpose
        {
            int k = t & 127, qh = (t >> 7) * 16;
            #pragma unroll
            for (int qq = 0; qq < 16; qq++)
                p_T[k * 33 + qh + qq] = s_s[(size_t)(qh + qq) * 1024 + kc + k];
        }
        // load V chunk (row-major, rows padded to 66)
        #pragma unroll
        for (int it = 0; it < 8; it++) {
            int u = t + it * 256;           // 0..2047 float4 units
            int r = u >> 4, c4 = u & 15;
            float4 f = *(const float4*)&Vb[(size_t)(kc + r) * 512 + 4 * c4];
            *(float2*)&v_s[r * 66 + 4 * c4]     = make_float2(f.x, f.y);
            *(float2*)&v_s[r * 66 + 4 * c4 + 2] = make_float2(f.z, f.w);
        }
        __syncthreads();
        #pragma unroll 2
        for (int it = 0; it < 16; it++) {
            int k = it * 8 + ks;
            const float* pp = &p_T[k * 33 + 8 * vqg];
            const float* vp = &v_s[k * 66 + 8 * warp];
            ull bv0 = *(const ull*)(vp + 0);
            ull bv1 = *(const ull*)(vp + 2);
            ull bv2 = *(const ull*)(vp + 4);
            ull bv3 = *(const ull*)(vp + 6);
            #pragma unroll
            for (int i = 0; i < 8; i++) {
                ull a2; PACK2(a2, pp[i]);
                FMA2(o2[i][0], a2, bv0);
                FMA2(o2[i][1], a2, bv1);
                FMA2(o2[i][2], a2, bv2);
                FMA2(o2[i][3], a2, bv3);
            }
        }
    }
    // reduce over the 8 ks lanes, then lane ks==0 writes
    #pragma unroll
    for (int off = 1; off < 8; off <<= 1) {
        #pragma unroll
        for (int i = 0; i < 8; i++)
            #pragma unroll
            for (int j = 0; j < 4; j++) {
                ull s = __shfl_xor_sync(0xffffffffu, o2[i][j], off);
                ADD2(o2[i][j], s);
            }
    }
    if (ks == 0) {
        float* Ob = O + ((size_t)(b * 1024 + q0 + 8 * vqg)) * 512 + h * 64 + 8 * warp;
        #pragma unroll
        for (int i = 0; i < 8; i++) {
            float2 p0 = *(float2*)&o2[i][0];
            float2 p1 = *(float2*)&o2[i][1];
            float2 p2 = *(float2*)&o2[i][2];
            float2 p3 = *(float2*)&o2[i][3];
            *(float4*)&Ob[(size_t)i * 512]     = make_float4(p0.x, p0.y, p1.x, p1.y);
            *(float4*)&Ob[(size_t)i * 512 + 4] = make_float4(p2.x, p2.y, p3.x, p3.y);
        }
    }
}

// ------------------------- launch -------------------------------------------
extern "C" void kernel_launch(void* const* d_in, const int* in_sizes, int n_in,
                              void* d_out, int out_size) {
    const float* q      = (const float*)d_in[0];
    const float* k      = (const float*)d_in[1];
    const float* v      = (const float*)d_in[2];
    const float* latent = (const float*)d_in[3];
    const float* Wq     = (const float*)d_in[4];
    const float* bq     = (const float*)d_in[5];
    const float* Wk     = (const float*)d_in[6];
    const float* bk     = (const float*)d_in[7];
    const float* Wv     = (const float*)d_in[8];
    const float* bv     = (const float*)d_in[9];
    const float* Wfc    = (const float*)d_in[10];
    const float* bfc    = (const float*)d_in[11];
    const float* Ws1    = (const float*)d_in[12];
    const float* bs1    = (const float*)d_in[13];
    const float* Ws2    = (const float*)d_in[14];
    const float* bs2    = (const float*)d_in[15];
    const float* en_g   = (const float*)d_in[16];
    const float* en_b   = (const float*)d_in[17];
    const float* ln_g   = (const float*)d_in[18];
    const float* ln_b   = (const float*)d_in[19];

    float* out  = (float*)d_out;                       // [B,L,D]
    float* attn = out + (size_t)BLD * PD;              // [B,H,L,L]

    float *gQ, *gK, *gV, *gO, *gOFC, *gHS, *gH2, *gSS;
    cudaGetSymbolAddress((void**)&gQ,  g_Q);
    cudaGetSymbolAddress((void**)&gK,  g_K);
    cudaGetSymbolAddress((void**)&gV,  g_V);
    cudaGetSymbolAddress((void**)&gO,  g_O);
    cudaGetSymbolAddress((void**)&gOFC,g_OFC);
    cudaGetSymbolAddress((void**)&gHS, g_HS);
    cudaGetSymbolAddress((void**)&gH2, g_H2);
    cudaGetSymbolAddress((void**)&gSS, g_SS);

    cudaFuncSetAttribute(attn_kernel,
                         cudaFuncAttributeMaxDynamicSharedMemorySize, AT_SMEM);

    dim3 gGemm(PD / 128, BLD / 128);   // (4, 64)

    film_prep<<<dim3(8, PB), 128>>>(latent, Ws1, bs1, gSS);
    sgemm_bias<<<gGemm, 256>>>(q, Wq, bq, gQ, BLD, PD, PD);
    sgemm_bias<<<gGemm, 256>>>(k, Wk, bk, gK, BLD, PD, PD);
    sgemm_bias<<<gGemm, 256>>>(v, Wv, bv, gV, BLD, PD, PD);
    attn_kernel<<<dim3(PL / 32, PH, PB), 256, AT_SMEM>>>(gQ, gK, gV, attn, gO);
    sgemm_bias<<<gGemm, 256>>>(gO, Wfc, bfc, gOFC, BLD, PD, PD);
    film_apply<<<BLD, 128>>>(gOFC, gSS, en_g, en_b, gHS);
    sgemm_bias<<<gGemm, 256>>>(gHS, Ws2, bs2, gH2, BLD, PD, PD);
    final_ln<<<BLD, 128>>>(gH2, q, ln_g, ln_b, out);
}

// round 10
// speedup vs baseline: 1.8818x; 1.2857x over previous
#include <cuda_runtime.h>
#include <cuda_bf16.h>
#include <cstddef>
#include <cstdint>

typedef unsigned long long ull;

// Packed fp32x2 ops (sm_100+). Used by the attention kernel.
#define FMA2(d,a,b) asm("fma.rn.f32x2 %0, %1, %2, %0;" : "+l"(d) : "l"(a), "l"(b))
#define ADD2(d,a)   asm("add.rn.f32x2 %0, %0, %1;"     : "+l"(d) : "l"(a))
#define PACK2(out,f) asm("mov.b64 %0, {%1, %1};" : "=l"(out) : "r"(__float_as_uint(f)))

// Problem constants
#define PB 8
#define PL 1024
#define PD 512
#define PH 8
#define BLD (PB*PL)            // 8192 rows

// ------------------------- scratch (device globals) -------------------------
__device__ float g_Q  [BLD*PD];
__device__ float g_K  [BLD*PD];
__device__ float g_V  [BLD*PD];
__device__ float g_OFC[BLD*PD];
__device__ float g_H2 [BLD*PD];
__device__ float g_SS [PB*2*PD];

// bf16 split operands
__device__ __nv_bfloat16 g_qh[BLD*PD], g_ql[BLD*PD];
__device__ __nv_bfloat16 g_kh[BLD*PD], g_kl[BLD*PD];
__device__ __nv_bfloat16 g_vh[BLD*PD], g_vl[BLD*PD];
__device__ __nv_bfloat16 g_Oh[BLD*PD], g_Ol[BLD*PD];
__device__ __nv_bfloat16 g_HSh[BLD*PD], g_HSl[BLD*PD];
// 5 transposed+split weights: [n][k] layout, 512*512 each
__device__ __nv_bfloat16 g_Wth[5*PD*PD], g_Wtl[5*PD*PD];

// ------------------------- helpers ------------------------------------------
static __device__ __forceinline__ uint32_t stoa(const void* p) {
    uint32_t a;
    asm("{ .reg .u64 t; cvta.to.shared.u64 t, %1; cvt.u32.u64 %0, t; }"
        : "=r"(a) : "l"(p));
    return a;
}
static __device__ __forceinline__ void bsplit(float x, ushort& h, ushort& l) {
    __nv_bfloat16 hb = __float2bfloat16_rn(x);
    h = __bfloat16_as_ushort(hb);
    float r = x - __bfloat162float(hb);
    l = __bfloat16_as_ushort(__float2bfloat16_rn(r));
}

#define LDSM4(r, addr) \
    asm volatile("ldmatrix.sync.aligned.m8n8.x4.shared.b16 {%0,%1,%2,%3}, [%4];" \
        : "=r"((r)[0]),"=r"((r)[1]),"=r"((r)[2]),"=r"((r)[3]) : "r"(addr))

#define MMABF16(d, a, b0, b1) \
    asm volatile("mma.sync.aligned.m16n8k16.row.col.f32.bf16.bf16.f32 " \
        "{%0,%1,%2,%3}, {%4,%5,%6,%7}, {%8,%9}, {%0,%1,%2,%3};" \
        : "+f"((d)[0]),"+f"((d)[1]),"+f"((d)[2]),"+f"((d)[3]) \
        : "r"((a)[0]),"r"((a)[1]),"r"((a)[2]),"r"((a)[3]), "r"(b0),"r"(b1))

#define CPA16(dst, src) \
    asm volatile("cp.async.ca.shared.global [%0], [%1], 16;" :: "r"(dst), "l"(src))
#define CPCOMMIT() asm volatile("cp.async.commit_group;" ::: "memory")
#define CPWAIT0()  asm volatile("cp.async.wait_group 0;"  ::: "memory")

// ==================== weight prep: W[k][n] -> Wt[n][k] hi/lo =================
__global__ __launch_bounds__(256)
void wprep(const float* __restrict__ W0, const float* __restrict__ W1,
           const float* __restrict__ W2, const float* __restrict__ W3,
           const float* __restrict__ W4,
           __nv_bfloat16* __restrict__ Wth, __nv_bfloat16* __restrict__ Wtl) {
    const int z = blockIdx.z;
    const float* W = z == 0 ? W0 : z == 1 ? W1 : z == 2 ? W2 : z == 3 ? W3 : W4;
    __nv_bfloat16* oh = Wth + (size_t)z * PD * PD;
    __nv_bfloat16* ol = Wtl + (size_t)z * PD * PD;
    __shared__ float tile[32][33];
    const int k0 = blockIdx.x * 32, n0 = blockIdx.y * 32;
    const int tx = threadIdx.x & 31, ty = threadIdx.x >> 5;
    #pragma unroll
    for (int i = 0; i < 4; i++)
        tile[ty + 8 * i][tx] = W[(size_t)(k0 + ty + 8 * i) * PD + n0 + tx];
    __syncthreads();
    #pragma unroll
    for (int i = 0; i < 4; i++) {
        int n = n0 + ty + 8 * i, k = k0 + tx;
        ushort h, l;
        bsplit(tile[tx][ty + 8 * i], h, l);
        oh[(size_t)n * PD + k] = __ushort_as_bfloat16(h);
        ol[(size_t)n * PD + k] = __ushort_as_bfloat16(l);
    }
}

// ==================== split q/k/v fp32 -> bf16 hi/lo =========================
__global__ __launch_bounds__(256)
void split3(const float* __restrict__ x0, const float* __restrict__ x1,
            const float* __restrict__ x2,
            __nv_bfloat16* __restrict__ h0, __nv_bfloat16* __restrict__ l0,
            __nv_bfloat16* __restrict__ h1, __nv_bfloat16* __restrict__ l1,
            __nv_bfloat16* __restrict__ h2, __nv_bfloat16* __restrict__ l2) {
    const int z = blockIdx.z;
    const float* in = z == 0 ? x0 : z == 1 ? x1 : x2;
    __nv_bfloat16* oh = z == 0 ? h0 : z == 1 ? h1 : h2;
    __nv_bfloat16* ol = z == 0 ? l0 : z == 1 ? l1 : l2;
    size_t i = ((size_t)blockIdx.x * 256 + threadIdx.x) * 4;
    float4 f = *(const float4*)&in[i];
    ushort h[4], l[4];
    bsplit(f.x, h[0], l[0]); bsplit(f.y, h[1], l[1]);
    bsplit(f.z, h[2], l[2]); bsplit(f.w, h[3], l[3]);
    uint2 hv = make_uint2((uint32_t)h[0] | ((uint32_t)h[1] << 16),
                          (uint32_t)h[2] | ((uint32_t)h[3] << 16));
    uint2 lv = make_uint2((uint32_t)l[0] | ((uint32_t)l[1] << 16),
                          (uint32_t)l[2] | ((uint32_t)l[3] << 16));
    *(uint2*)&oh[i] = hv;
    *(uint2*)&ol[i] = lv;
}

// ==================== bf16-split mma.sync GEMM ===============================
// C = A@W + bias via 3 bf16 MMA terms. A splits [8192][512] row-major bf16,
// B splits [512 n][512 k] (transposed W). CTA tile 128x128, warp tile 64x32,
// K chunks of 32, cp.async double buffer.
// smem halves per buf: aHi[128*40] aLo bHi bLo  (row stride 40 halves = 80 B)
#define GS_ROW 40
#define GS_ARR (128*GS_ROW)                 // 5120 halves
#define GS_BUF (4*GS_ARR)                   // 20480 halves
#define SMEM_GEMM (2*GS_BUF*2)              // 81920 bytes

__global__ __launch_bounds__(256, 2)
void gemm_bf16(const __nv_bfloat16* __restrict__ Ah0, const __nv_bfloat16* __restrict__ Al0,
               const __nv_bfloat16* __restrict__ Ah1, const __nv_bfloat16* __restrict__ Al1,
               const __nv_bfloat16* __restrict__ Ah2, const __nv_bfloat16* __restrict__ Al2,
               const __nv_bfloat16* __restrict__ Bh0, const __nv_bfloat16* __restrict__ Bl0,
               const __nv_bfloat16* __restrict__ Bh1, const __nv_bfloat16* __restrict__ Bl1,
               const __nv_bfloat16* __restrict__ Bh2, const __nv_bfloat16* __restrict__ Bl2,
               const float* __restrict__ bias0, const float* __restrict__ bias1,
               const float* __restrict__ bias2,
               float* __restrict__ C0, float* __restrict__ C1, float* __restrict__ C2) {
    extern __shared__ __nv_bfloat16 hsm[];
    const int z = blockIdx.z;
    const __nv_bfloat16* Ah = z == 0 ? Ah0 : z == 1 ? Ah1 : Ah2;
    const __nv_bfloat16* Al = z == 0 ? Al0 : z == 1 ? Al1 : Al2;
    const __nv_bfloat16* Bh = z == 0 ? Bh0 : z == 1 ? Bh1 : Bh2;
    const __nv_bfloat16* Bl = z == 0 ? Bl0 : z == 1 ? Bl1 : Bl2;
    const float* bias = z == 0 ? bias0 : z == 1 ? bias1 : bias2;
    float* C          = z == 0 ? C0 : z == 1 ? C1 : C2;

    const int cb0 = blockIdx.x * 128;      // output col base
    const int rb0 = blockIdx.y * 128;      // output row base
    const int t = threadIdx.x;
    const int wid = t >> 5, lane = t & 31;
    const int wm = wid & 1, wn = wid >> 1; // 2 x 4 warp grid
    const uint32_t sb = stoa(hsm);

    // staging: thread t copies 16 halves (32B) per array
    const int srow = t >> 1, sh16 = (t & 1) * 16;
    const size_t aoff = (size_t)(rb0 + srow) * PD + sh16;
    const size_t boff = (size_t)(cb0 + srow) * PD + sh16;
    const uint32_t sdst = (uint32_t)(srow * GS_ROW + sh16) * 2;

    float d[4][4][4];
    #pragma unroll
    for (int i = 0; i < 4; i++)
        #pragma unroll
        for (int j = 0; j < 4; j++)
            #pragma unroll
            for (int r = 0; r < 4; r++) d[i][j][r] = 0.f;

    auto stage = [&](int c, int buf) {
        const uint32_t base = sb + (uint32_t)buf * GS_BUF * 2 + sdst;
        const __nv_bfloat16* s;
        s = Ah + aoff + c * 32;
        CPA16(base,                  s); CPA16(base + 16,                  s + 8);
        s = Al + aoff + c * 32;
        CPA16(base + GS_ARR*2,       s); CPA16(base + GS_ARR*2 + 16,       s + 8);
        s = Bh + boff + c * 32;
        CPA16(base + 2*GS_ARR*2,     s); CPA16(base + 2*GS_ARR*2 + 16,     s + 8);
        s = Bl + boff + c * 32;
        CPA16(base + 3*GS_ARR*2,     s); CPA16(base + 3*GS_ARR*2 + 16,     s + 8);
    };

    const uint32_t lro = (uint32_t)((lane & 15) * GS_ROW + (lane >> 4) * 8) * 2;

    stage(0, 0);
    CPCOMMIT();
    for (int c = 0; c < 16; c++) {
        CPWAIT0();
        __syncthreads();
        if (c < 15) { stage(c + 1, (c + 1) & 1); CPCOMMIT(); }
        const uint32_t ab = sb + (uint32_t)(c & 1) * GS_BUF * 2;
        const uint32_t bbh = ab + 2 * GS_ARR * 2;
        #pragma unroll
        for (int ks = 0; ks < 2; ks++) {
            uint32_t bh[4][2], bl[4][2];
            #pragma unroll
            for (int j2 = 0; j2 < 2; j2++) {
                uint32_t tb[4];
                uint32_t ba = bbh + (uint32_t)((wn*32 + j2*16) * GS_ROW + ks*16) * 2 + lro;
                LDSM4(tb, ba);
                bh[j2*2][0] = tb[0]; bh[j2*2][1] = tb[2];
                bh[j2*2+1][0] = tb[1]; bh[j2*2+1][1] = tb[3];
                LDSM4(tb, ba + GS_ARR*2);
                bl[j2*2][0] = tb[0]; bl[j2*2][1] = tb[2];
                bl[j2*2+1][0] = tb[1]; bl[j2*2+1][1] = tb[3];
            }
            #pragma unroll
            for (int mi = 0; mi < 4; mi++) {
                uint32_t ah[4], al[4];
                uint32_t aa = ab + (uint32_t)((wm*64 + mi*16) * GS_ROW + ks*16) * 2 + lro;
                LDSM4(ah, aa);
                LDSM4(al, aa + GS_ARR*2);
                #pragma unroll
                for (int nj = 0; nj < 4; nj++) {
                    MMABF16(d[mi][nj], ah, bh[nj][0], bh[nj][1]);
                    MMABF16(d[mi][nj], ah, bl[nj][0], bl[nj][1]);
                    MMABF16(d[mi][nj], al, bh[nj][0], bh[nj][1]);
                }
            }
        }
    }

    // epilogue: write fp32 C + bias
    const int g = lane >> 2, tq = lane & 3;
    #pragma unroll
    for (int mi = 0; mi < 4; mi++) {
        const int row = rb0 + wm*64 + mi*16 + g;
        #pragma unroll
        for (int nj = 0; nj < 4; nj++) {
            const int col = cb0 + wn*32 + nj*8 + tq*2;
            float2 bv = *(const float2*)&bias[col];
            float2 o0 = make_float2(d[mi][nj][0] + bv.x, d[mi][nj][1] + bv.y);
            float2 o1 = make_float2(d[mi][nj][2] + bv.x, d[mi][nj][3] + bv.y);
            *(float2*)&C[(size_t)row * PD + col]       = o0;
            *(float2*)&C[(size_t)(row + 8) * PD + col] = o1;
        }
    }
}

// ------------------------- FiLM scale/shift prep ----------------------------
__global__ __launch_bounds__(128)
void film_prep(const float* __restrict__ latent, const float* __restrict__ Ws1,
               const float* __restrict__ bs1, float* __restrict__ ss) {
    const int b = blockIdx.y;
    const int col = blockIdx.x * 128 + threadIdx.x;
    __shared__ float ls[512];
    for (int i = threadIdx.x; i < 512; i += 128) {
        float x = latent[(size_t)b * 512 + i];
        ls[i] = x / (1.f + __expf(-x));
    }
    __syncthreads();
    float sum = 0.f;
    #pragma unroll 8
    for (int k = 0; k < 512; k++) sum += ls[k] * Ws1[(size_t)k * 1024 + col];
    ss[(size_t)b * 1024 + col] = sum + bs1[col];
}

// ------------------------- block reduce helper ------------------------------
__device__ __forceinline__ float2 blockReduceSum2(float s1, float s2) {
    __shared__ float sh[8];
    #pragma unroll
    for (int off = 16; off; off >>= 1) {
        s1 += __shfl_xor_sync(0xffffffffu, s1, off);
        s2 += __shfl_xor_sync(0xffffffffu, s2, off);
    }
    const int w = threadIdx.x >> 5;
    if ((threadIdx.x & 31) == 0) { sh[w * 2] = s1; sh[w * 2 + 1] = s2; }
    __syncthreads();
    float a = 0.f, b = 0.f;
    const int nw = blockDim.x >> 5;
    for (int i = 0; i < nw; i++) { a += sh[i * 2]; b += sh[i * 2 + 1]; }
    return make_float2(a, b);
}

// --------- FiLM apply: LN -> FiLM -> SiLU, fused bf16 split output ----------
__global__ __launch_bounds__(128)
void film_apply(const float* __restrict__ ofc, const float* __restrict__ ss,
                const float* __restrict__ g, const float* __restrict__ be,
                __nv_bfloat16* __restrict__ hsh, __nv_bfloat16* __restrict__ hsl) {
    const int row = blockIdx.x;
    const int b = row >> 10;
    const int t = threadIdx.x;
    const float* xr = ofc + (size_t)row * 512;
    float x[4]; float s1 = 0.f, s2 = 0.f;
    #pragma unroll
    for (int i = 0; i < 4; i++) {
        x[i] = xr[t + i * 128];
        s1 += x[i]; s2 += x[i] * x[i];
    }
    float2 r = blockReduceSum2(s1, s2);
    const float mean = r.x * (1.f / 512.f);
    const float var  = r.y * (1.f / 512.f) - mean * mean;
    const float rstd = rsqrtf(var + 1e-5f);
    const float* ssb = ss + (size_t)b * 1024;
    #pragma unroll
    for (int i = 0; i < 4; i++) {
        const int c = t + i * 128;
        float ln = (x[i] - mean) * rstd * g[c] + be[c];
        float h = ln * (1.f + ssb[c]) + ssb[512 + c];
        h = h / (1.f + __expf(-h));
        ushort hh, ll;
        bsplit(h, hh, ll);
        hsh[(size_t)row * 512 + c] = __ushort_as_bfloat16(hh);
        hsl[(size_t)row * 512 + c] = __ushort_as_bfloat16(ll);
    }
}

// ------------------------- final: LN(h2 + residual) -------------------------
__global__ __launch_bounds__(128)
void final_ln(const float* __restrict__ h2, const float* __restrict__ resid,
              const float* __restrict__ g, const float* __restrict__ be,
              float* __restrict__ out) {
    const int row = blockIdx.x;
    const int t = threadIdx.x;
    const float* hr = h2 + (size_t)row * 512;
    const float* rr = resid + (size_t)row * 512;
    float x[4]; float s1 = 0.f, s2 = 0.f;
    #pragma unroll
    for (int i = 0; i < 4; i++) {
        x[i] = hr[t + i * 128] + rr[t + i * 128];
        s1 += x[i]; s2 += x[i] * x[i];
    }
    float2 r = blockReduceSum2(s1, s2);
    const float mean = r.x * (1.f / 512.f);
    const float var  = r.y * (1.f / 512.f) - mean * mean;
    const float rstd = rsqrtf(var + 1e-6f);
    float* orow = out + (size_t)row * 512;
    #pragma unroll
    for (int i = 0; i < 4; i++) {
        const int c = t + i * 128;
        orow[c] = (x[i] - mean) * rstd * g[c] + be[c];
    }
}

// ------------------------- fused attention (f32x2, tiled) -------------------
#define AT_FL   (32*1024 + 64*64 + 64*258)
#define AT_SMEM (AT_FL * 4)

__global__ __launch_bounds__(256, 1)
void attn_kernel(const float* __restrict__ Q, const float* __restrict__ K,
                 const float* __restrict__ V, float* __restrict__ attn,
                 __nv_bfloat16* __restrict__ Oh, __nv_bfloat16* __restrict__ Ol) {
    extern __shared__ float sm[];
    float* s_s   = sm;                    // 32*1024
    float* q_dup = sm + 32 * 1024;        // 64*64
    float* rB    = q_dup + 64 * 64;       // 64*258 region

    const int b = blockIdx.z, h = blockIdx.y;
    const int q0 = blockIdx.x * 32;
    const int t = threadIdx.x;
    const int warp = t >> 5, lane = t & 31;

    const float* Qb = Q + ((size_t)(b * 1024 + q0)) * 512 + h * 64;
    #pragma unroll
    for (int it = 0; it < 2; it++) {
        int u = t + it * 256;
        int r = u >> 4, c4 = u & 15;
        float4 f = *(const float4*)&Qb[(size_t)r * 512 + 4 * c4];
        ull p0, p1, p2, p3;
        PACK2(p0, f.x); PACK2(p1, f.y); PACK2(p2, f.z); PACK2(p3, f.w);
        *(ull*)&q_dup[(4 * c4 + 0) * 64 + 2 * r] = p0;
        *(ull*)&q_dup[(4 * c4 + 1) * 64 + 2 * r] = p1;
        *(ull*)&q_dup[(4 * c4 + 2) * 64 + 2 * r] = p2;
        *(ull*)&q_dup[(4 * c4 + 3) * 64 + 2 * r] = p3;
    }

    const float* Kb = K + (size_t)b * 1024 * 512 + h * 64;
    for (int kc = 0; kc < 1024; kc += 256) {
        __syncthreads();
        #pragma unroll
        for (int it = 0; it < 16; it++) {
            int u = t + it * 256;
            int r = u >> 4, c4 = u & 15;
            float4 f = *(const float4*)&Kb[(size_t)(kc + r) * 512 + 4 * c4];
            rB[(4 * c4 + 0) * 258 + r] = f.x;
            rB[(4 * c4 + 1) * 258 + r] = f.y;
            rB[(4 * c4 + 2) * 258 + r] = f.z;
            rB[(4 * c4 + 3) * 258 + r] = f.w;
        }
        __syncthreads();
        ull acc[4][4];
        #pragma unroll
        for (int i = 0; i < 4; i++)
            #pragma unroll
            for (int j = 0; j < 4; j++) acc[i][j] = 0ULL;
        #pragma unroll 4
        for (int d = 0; d < 64; d++) {
            ulonglong2 aa = *(const ulonglong2*)&q_dup[d * 64 + 8 * warp];
            ulonglong2 ab = *(const ulonglong2*)&q_dup[d * 64 + 8 * warp + 4];
            const float* bp = &rB[d * 258 + 8 * lane];
            ull bv0 = *(const ull*)(bp + 0);
            ull bv1 = *(const ull*)(bp + 2);
            ull bv2 = *(const ull*)(bp + 4);
            ull bv3 = *(const ull*)(bp + 6);
            FMA2(acc[0][0], aa.x, bv0); FMA2(acc[0][1], aa.x, bv1);
            FMA2(acc[0][2], aa.x, bv2); FMA2(acc[0][3], aa.x, bv3);
            FMA2(acc[1][0], aa.y, bv0); FMA2(acc[1][1], aa.y, bv1);
            FMA2(acc[1][2], aa.y, bv2); FMA2(acc[1][3], aa.y, bv3);
            FMA2(acc[2][0], ab.x, bv0); FMA2(acc[2][1], ab.x, bv1);
            FMA2(acc[2][2], ab.x, bv2); FMA2(acc[2][3], ab.x, bv3);
            FMA2(acc[3][0], ab.y, bv0); FMA2(acc[3][1], ab.y, bv1);
            FMA2(acc[3][2], ab.y, bv2); FMA2(acc[3][3], ab.y, bv3);
        }
        #pragma unroll
        for (int i = 0; i < 4; i++) {
            float* dst = &s_s[(size_t)(4 * warp + i) * 1024 + kc + 8 * lane];
            #pragma unroll
            for (int j = 0; j < 4; j++) {
                float2 v = *(float2*)&acc[i][j];
                v.x *= 0.125f; v.y *= 0.125f;
                *(float2*)&dst[2 * j] = v;
            }
        }
    }

    float* attn_b = attn + (((size_t)(b * 8 + h)) * 1024 + q0) * 1024;
    for (int r = 4 * warp; r < 4 * warp + 4; r++) {
        float* srow = s_s + (size_t)r * 1024;
        float mx = -1e30f;
        #pragma unroll 8
        for (int i = lane; i < 1024; i += 32) mx = fmaxf(mx, srow[i]);
        #pragma unroll
        for (int off = 16; off; off >>= 1)
            mx = fmaxf(mx, __shfl_xor_sync(0xffffffffu, mx, off));
        float sum = 0.f;
        #pragma unroll 8
        for (int i = lane; i < 1024; i += 32) {
            float e = __expf(srow[i] - mx);
            srow[i] = e; sum += e;
        }
        #pragma unroll
        for (int off = 16; off; off >>= 1)
            sum += __shfl_xor_sync(0xffffffffu, sum, off);
        float inv = 1.f / sum;
        float* arow = attn_b + (size_t)r * 1024;
        #pragma unroll 8
        for (int i = lane; i < 1024; i += 32) {
            float p = srow[i] * inv;
            srow[i] = p;
            arow[i] = p;
        }
    }

    float* p_T = rB;                 // [128][33]
    float* v_s = rB + 128 * 33;      // [128][66]
    const float* Vb = V + (size_t)b * 1024 * 512 + h * 64;
    const int vqg = lane >> 3;
    const int ks  = lane & 7;
    ull o2[8][4];
    #pragma unroll
    for (int i = 0; i < 8; i++)
        #pragma unroll
        for (int j = 0; j < 4; j++) o2[i][j] = 0ULL;

    for (int kc = 0; kc < 1024; kc += 128) {
        __syncthreads();
        {
            int k = t & 127, qh = (t >> 7) * 16;
            #pragma unroll
            for (int qq = 0; qq < 16; qq++)
                p_T[k * 33 + qh + qq] = s_s[(size_t)(qh + qq) * 1024 + kc + k];
        }
        #pragma unroll
        for (int it = 0; it < 8; it++) {
            int u = t + it * 256;
            int r = u >> 4, c4 = u & 15;
            float4 f = *(const float4*)&Vb[(size_t)(kc + r) * 512 + 4 * c4];
            *(float2*)&v_s[r * 66 + 4 * c4]     = make_float2(f.x, f.y);
            *(float2*)&v_s[r * 66 + 4 * c4 + 2] = make_float2(f.z, f.w);
        }
        __syncthreads();
        #pragma unroll 2
        for (int it = 0; it < 16; it++) {
            int k = it * 8 + ks;
            const float* pp = &p_T[k * 33 + 8 * vqg];
            const float* vp = &v_s[k * 66 + 8 * warp];
            ull bv0 = *(const ull*)(vp + 0);
            ull bv1 = *(const ull*)(vp + 2);
            ull bv2 = *(const ull*)(vp + 4);
            ull bv3 = *(const ull*)(vp + 6);
            #pragma unroll
            for (int i = 0; i < 8; i++) {
                ull a2; PACK2(a2, pp[i]);
                FMA2(o2[i][0], a2, bv0);
                FMA2(o2[i][1], a2, bv1);
                FMA2(o2[i][2], a2, bv2);
                FMA2(o2[i][3], a2, bv3);
            }
        }
    }
    #pragma unroll
    for (int off = 1; off < 8; off <<= 1) {
        #pragma unroll
        for (int i = 0; i < 8; i++)
            #pragma unroll
            for (int j = 0; j < 4; j++) {
                ull s = __shfl_xor_sync(0xffffffffu, o2[i][j], off);
                ADD2(o2[i][j], s);
            }
    }
    if (ks == 0) {
        const size_t ob = ((size_t)(b * 1024 + q0 + 8 * vqg)) * 512 + h * 64 + 8 * warp;
        #pragma unroll
        for (int i = 0; i < 8; i++) {
            float f[8];
            *(float2*)&f[0] = *(float2*)&o2[i][0];
            *(float2*)&f[2] = *(float2*)&o2[i][1];
            *(float2*)&f[4] = *(float2*)&o2[i][2];
            *(float2*)&f[6] = *(float2*)&o2[i][3];
            ushort hh[8], ll[8];
            #pragma unroll
            for (int j = 0; j < 8; j++) bsplit(f[j], hh[j], ll[j]);
            uint4 hv, lv;
            hv.x = (uint32_t)hh[0] | ((uint32_t)hh[1] << 16);
            hv.y = (uint32_t)hh[2] | ((uint32_t)hh[3] << 16);
            hv.z = (uint32_t)hh[4] | ((uint32_t)hh[5] << 16);
            hv.w = (uint32_t)hh[6] | ((uint32_t)hh[7] << 16);
            lv.x = (uint32_t)ll[0] | ((uint32_t)ll[1] << 16);
            lv.y = (uint32_t)ll[2] | ((uint32_t)ll[3] << 16);
            lv.z = (uint32_t)ll[4] | ((uint32_t)ll[5] << 16);
            lv.w = (uint32_t)ll[6] | ((uint32_t)ll[7] << 16);
            *(uint4*)&Oh[ob + (size_t)i * 512] = hv;
            *(uint4*)&Ol[ob + (size_t)i * 512] = lv;
        }
    }
}

// ------------------------- launch -------------------------------------------
extern "C" void kernel_launch(void* const* d_in, const int* in_sizes, int n_in,
                              void* d_out, int out_size) {
    const float* q      = (const float*)d_in[0];
    const float* k      = (const float*)d_in[1];
    const float* v      = (const float*)d_in[2];
    const float* latent = (const float*)d_in[3];
    const float* Wq     = (const float*)d_in[4];
    const float* bq     = (const float*)d_in[5];
    const float* Wk     = (const float*)d_in[6];
    const float* bk     = (const float*)d_in[7];
    const float* Wv     = (const float*)d_in[8];
    const float* bv     = (const float*)d_in[9];
    const float* Wfc    = (const float*)d_in[10];
    const float* bfc    = (const float*)d_in[11];
    const float* Ws1    = (const float*)d_in[12];
    const float* bs1    = (const float*)d_in[13];
    const float* Ws2    = (const float*)d_in[14];
    const float* bs2    = (const float*)d_in[15];
    const float* en_g   = (const float*)d_in[16];
    const float* en_b   = (const float*)d_in[17];
    const float* ln_g   = (const float*)d_in[18];
    const float* ln_b   = (const float*)d_in[19];

    float* out  = (float*)d_out;                       // [B,L,D]
    float* attn = out + (size_t)BLD * PD;              // [B,H,L,L]

    float *gQ, *gK, *gV, *gOFC, *gH2, *gSS;
    cudaGetSymbolAddress((void**)&gQ,  g_Q);
    cudaGetSymbolAddress((void**)&gK,  g_K);
    cudaGetSymbolAddress((void**)&gV,  g_V);
    cudaGetSymbolAddress((void**)&gOFC,g_OFC);
    cudaGetSymbolAddress((void**)&gH2, g_H2);
    cudaGetSymbolAddress((void**)&gSS, g_SS);

    __nv_bfloat16 *qh,*ql,*kh,*kl,*vh,*vl,*Oh,*Ol,*HSh,*HSl,*Wth,*Wtl;
    cudaGetSymbolAddress((void**)&qh, g_qh);  cudaGetSymbolAddress((void**)&ql, g_ql);
    cudaGetSymbolAddress((void**)&kh, g_kh);  cudaGetSymbolAddress((void**)&kl, g_kl);
    cudaGetSymbolAddress((void**)&vh, g_vh);  cudaGetSymbolAddress((void**)&vl, g_vl);
    cudaGetSymbolAddress((void**)&Oh, g_Oh);  cudaGetSymbolAddress((void**)&Ol, g_Ol);
    cudaGetSymbolAddress((void**)&HSh, g_HSh); cudaGetSymbolAddress((void**)&HSl, g_HSl);
    cudaGetSymbolAddress((void**)&Wth, g_Wth); cudaGetSymbolAddress((void**)&Wtl, g_Wtl);

    cudaFuncSetAttribute(attn_kernel,
                         cudaFuncAttributeMaxDynamicSharedMemorySize, AT_SMEM);
    cudaFuncSetAttribute(gemm_bf16,
                         cudaFuncAttributeMaxDynamicSharedMemorySize, SMEM_GEMM);

    const size_t WSZ = (size_t)PD * PD;

    // prep: transpose+split weights, split q/k/v, FiLM vector
    wprep<<<dim3(16, 16, 5), 256>>>(Wq, Wk, Wv, Wfc, Ws2, Wth, Wtl);
    split3<<<dim3(4096, 1, 3), 256>>>(q, k, v, qh, ql, kh, kl, vh, vl);
    film_prep<<<dim3(8, PB), 128>>>(latent, Ws1, bs1, gSS);

    // QKV projections (fused z=3)
    gemm_bf16<<<dim3(4, 64, 3), 256, SMEM_GEMM>>>(
        qh, ql, kh, kl, vh, vl,
        Wth, Wtl, Wth + WSZ, Wtl + WSZ, Wth + 2*WSZ, Wtl + 2*WSZ,
        bq, bk, bv, gQ, gK, gV);

    attn_kernel<<<dim3(PL / 32, PH, PB), 256, AT_SMEM>>>(gQ, gK, gV, attn, Oh, Ol);

    // FC
    gemm_bf16<<<dim3(4, 64, 1), 256, SMEM_GEMM>>>(
        Oh, Ol, Oh, Ol, Oh, Ol,
        Wth + 3*WSZ, Wtl + 3*WSZ, Wth + 3*WSZ, Wtl + 3*WSZ, Wth + 3*WSZ, Wtl + 3*WSZ,
        bfc, bfc, bfc, gOFC, gOFC, gOFC);

    film_apply<<<BLD, 128>>>(gOFC, gSS, en_g, en_b, HSh, HSl);

    // S2
    gemm_bf16<<<dim3(4, 64, 1), 256, SMEM_GEMM>>>(
        HSh, HSl, HSh, HSl, HSh, HSl,
        Wth + 4*WSZ, Wtl + 4*WSZ, Wth + 4*WSZ, Wtl + 4*WSZ, Wth + 4*WSZ, Wtl + 4*WSZ,
        bs2, bs2, bs2, gH2, gH2, gH2);

    final_ln<<<BLD, 128>>>(gH2, q, ln_g, ln_b, out);
}

// round 11
// speedup vs baseline: 2.7893x; 1.4822x over previous
#include <cuda_runtime.h>
#include <cuda_bf16.h>
#include <cstddef>
#include <cstdint>

// Problem constants
#define PB 8
#define PL 1024
#define PD 512
#define PH 8
#define BLD (PB*PL)            // 8192 rows

// ------------------------- scratch (device globals) -------------------------
__device__ float g_OFC[BLD*PD];
__device__ float g_H2 [BLD*PD];
__device__ float g_SS [PB*2*PD];

// bf16 split operands
__device__ __nv_bfloat16 g_qh[BLD*PD], g_ql[BLD*PD];   // raw inputs q/k/v
__device__ __nv_bfloat16 g_kh[BLD*PD], g_kl[BLD*PD];
__device__ __nv_bfloat16 g_vh[BLD*PD], g_vl[BLD*PD];
__device__ __nv_bfloat16 g_Qh[BLD*PD], g_Ql[BLD*PD];   // projected Q/K/V
__device__ __nv_bfloat16 g_Kh[BLD*PD], g_Kl[BLD*PD];
__device__ __nv_bfloat16 g_Vh[BLD*PD], g_Vl[BLD*PD];
__device__ __nv_bfloat16 g_Oh[BLD*PD], g_Ol[BLD*PD];   // attention output
__device__ __nv_bfloat16 g_HSh[BLD*PD], g_HSl[BLD*PD]; // FiLM output
// 5 transposed+split weights: [n][k] layout, 512*512 each
__device__ __nv_bfloat16 g_Wth[5*PD*PD], g_Wtl[5*PD*PD];

// ------------------------- helpers ------------------------------------------
static __device__ __forceinline__ uint32_t stoa(const void* p) {
    uint32_t a;
    asm("{ .reg .u64 t; cvta.to.shared.u64 t, %1; cvt.u32.u64 %0, t; }"
        : "=r"(a) : "l"(p));
    return a;
}
static __device__ __forceinline__ void bsplit(float x, ushort& h, ushort& l) {
    __nv_bfloat16 hb = __float2bfloat16_rn(x);
    h = __bfloat16_as_ushort(hb);
    float r = x - __bfloat162float(hb);
    l = __bfloat16_as_ushort(__float2bfloat16_rn(r));
}

#define LDSM4(r, addr) \
    asm volatile("ldmatrix.sync.aligned.m8n8.x4.shared.b16 {%0,%1,%2,%3}, [%4];" \
        : "=r"((r)[0]),"=r"((r)[1]),"=r"((r)[2]),"=r"((r)[3]) : "r"(addr))

#define LDSMT4(r, addr) \
    asm volatile("ldmatrix.sync.aligned.m8n8.x4.trans.shared.b16 {%0,%1,%2,%3}, [%4];" \
        : "=r"((r)[0]),"=r"((r)[1]),"=r"((r)[2]),"=r"((r)[3]) : "r"(addr))

#define MMABF16(d, a, b0, b1) \
    asm volatile("mma.sync.aligned.m16n8k16.row.col.f32.bf16.bf16.f32 " \
        "{%0,%1,%2,%3}, {%4,%5,%6,%7}, {%8,%9}, {%0,%1,%2,%3};" \
        : "+f"((d)[0]),"+f"((d)[1]),"+f"((d)[2]),"+f"((d)[3]) \
        : "r"((a)[0]),"r"((a)[1]),"r"((a)[2]),"r"((a)[3]), "r"(b0),"r"(b1))

#define CPA16(dst, src) \
    asm volatile("cp.async.ca.shared.global [%0], [%1], 16;" :: "r"(dst), "l"(src))
#define CPCOMMIT() asm volatile("cp.async.commit_group;" ::: "memory")
#define CPWAIT0()  asm volatile("cp.async.wait_group 0;"  ::: "memory")

// ==================== weight prep: W[k][n] -> Wt[n][k] hi/lo =================
__global__ __launch_bounds__(256)
void wprep(const float* __restrict__ W0, const float* __restrict__ W1,
           const float* __restrict__ W2, const float* __restrict__ W3,
           const float* __restrict__ W4,
           __nv_bfloat16* __restrict__ Wth, __nv_bfloat16* __restrict__ Wtl) {
    const int z = blockIdx.z;
    const float* W = z == 0 ? W0 : z == 1 ? W1 : z == 2 ? W2 : z == 3 ? W3 : W4;
    __nv_bfloat16* oh = Wth + (size_t)z * PD * PD;
    __nv_bfloat16* ol = Wtl + (size_t)z * PD * PD;
    __shared__ float tile[32][33];
    const int k0 = blockIdx.x * 32, n0 = blockIdx.y * 32;
    const int tx = threadIdx.x & 31, ty = threadIdx.x >> 5;
    #pragma unroll
    for (int i = 0; i < 4; i++)
        tile[ty + 8 * i][tx] = W[(size_t)(k0 + ty + 8 * i) * PD + n0 + tx];
    __syncthreads();
    #pragma unroll
    for (int i = 0; i < 4; i++) {
        int n = n0 + ty + 8 * i, k = k0 + tx;
        ushort h, l;
        bsplit(tile[tx][ty + 8 * i], h, l);
        oh[(size_t)n * PD + k] = __ushort_as_bfloat16(h);
        ol[(size_t)n * PD + k] = __ushort_as_bfloat16(l);
    }
}

// ==================== split q/k/v fp32 -> bf16 hi/lo =========================
__global__ __launch_bounds__(256)
void split3(const float* __restrict__ x0, const float* __restrict__ x1,
            const float* __restrict__ x2,
            __nv_bfloat16* __restrict__ h0, __nv_bfloat16* __restrict__ l0,
            __nv_bfloat16* __restrict__ h1, __nv_bfloat16* __restrict__ l1,
            __nv_bfloat16* __restrict__ h2, __nv_bfloat16* __restrict__ l2) {
    const int z = blockIdx.z;
    const float* in = z == 0 ? x0 : z == 1 ? x1 : x2;
    __nv_bfloat16* oh = z == 0 ? h0 : z == 1 ? h1 : h2;
    __nv_bfloat16* ol = z == 0 ? l0 : z == 1 ? l1 : l2;
    size_t i = ((size_t)blockIdx.x * 256 + threadIdx.x) * 4;
    float4 f = *(const float4*)&in[i];
    ushort h[4], l[4];
    bsplit(f.x, h[0], l[0]); bsplit(f.y, h[1], l[1]);
    bsplit(f.z, h[2], l[2]); bsplit(f.w, h[3], l[3]);
    uint2 hv = make_uint2((uint32_t)h[0] | ((uint32_t)h[1] << 16),
                          (uint32_t)h[2] | ((uint32_t)h[3] << 16));
    uint2 lv = make_uint2((uint32_t)l[0] | ((uint32_t)l[1] << 16),
                          (uint32_t)l[2] | ((uint32_t)l[3] << 16));
    *(uint2*)&oh[i] = hv;
    *(uint2*)&ol[i] = lv;
}

// ==================== bf16-split mma.sync GEMM ===============================
// C = A@W + bias via 3 bf16 MMA terms. Optionally writes fp32 C and/or bf16
// hi/lo split outputs (Csh/Csl).
#define GS_ROW 40
#define GS_ARR (128*GS_ROW)                 // 5120 halves
#define GS_BUF (4*GS_ARR)                   // 20480 halves
#define SMEM_GEMM (2*GS_BUF*2)              // 81920 bytes

__global__ __launch_bounds__(256, 2)
void gemm_bf16(const __nv_bfloat16* __restrict__ Ah0, const __nv_bfloat16* __restrict__ Al0,
               const __nv_bfloat16* __restrict__ Ah1, const __nv_bfloat16* __restrict__ Al1,
               const __nv_bfloat16* __restrict__ Ah2, const __nv_bfloat16* __restrict__ Al2,
               const __nv_bfloat16* __restrict__ Bh0, const __nv_bfloat16* __restrict__ Bl0,
               const __nv_bfloat16* __restrict__ Bh1, const __nv_bfloat16* __restrict__ Bl1,
               const __nv_bfloat16* __restrict__ Bh2, const __nv_bfloat16* __restrict__ Bl2,
               const float* __restrict__ bias0, const float* __restrict__ bias1,
               const float* __restrict__ bias2,
               float* __restrict__ C0, float* __restrict__ C1, float* __restrict__ C2,
               __nv_bfloat16* __restrict__ Sh0, __nv_bfloat16* __restrict__ Sl0,
               __nv_bfloat16* __restrict__ Sh1, __nv_bfloat16* __restrict__ Sl1,
               __nv_bfloat16* __restrict__ Sh2, __nv_bfloat16* __restrict__ Sl2) {
    extern __shared__ __nv_bfloat16 hsm[];
    const int z = blockIdx.z;
    const __nv_bfloat16* Ah = z == 0 ? Ah0 : z == 1 ? Ah1 : Ah2;
    const __nv_bfloat16* Al = z == 0 ? Al0 : z == 1 ? Al1 : Al2;
    const __nv_bfloat16* Bh = z == 0 ? Bh0 : z == 1 ? Bh1 : Bh2;
    const __nv_bfloat16* Bl = z == 0 ? Bl0 : z == 1 ? Bl1 : Bl2;
    const float* bias = z == 0 ? bias0 : z == 1 ? bias1 : bias2;
    float* C          = z == 0 ? C0 : z == 1 ? C1 : C2;
    __nv_bfloat16* Sh = z == 0 ? Sh0 : z == 1 ? Sh1 : Sh2;
    __nv_bfloat16* Sl = z == 0 ? Sl0 : z == 1 ? Sl1 : Sl2;

    const int cb0 = blockIdx.x * 128;
    const int rb0 = blockIdx.y * 128;
    const int t = threadIdx.x;
    const int wid = t >> 5, lane = t & 31;
    const int wm = wid & 1, wn = wid >> 1;
    const uint32_t sb = stoa(hsm);

    const int srow = t >> 1, sh16 = (t & 1) * 16;
    const size_t aoff = (size_t)(rb0 + srow) * PD + sh16;
    const size_t boff = (size_t)(cb0 + srow) * PD + sh16;
    const uint32_t sdst = (uint32_t)(srow * GS_ROW + sh16) * 2;

    float d[4][4][4];
    #pragma unroll
    for (int i = 0; i < 4; i++)
        #pragma unroll
        for (int j = 0; j < 4; j++)
            #pragma unroll
            for (int r = 0; r < 4; r++) d[i][j][r] = 0.f;

    auto stage = [&](int c, int buf) {
        const uint32_t base = sb + (uint32_t)buf * GS_BUF * 2 + sdst;
        const __nv_bfloat16* s;
        s = Ah + aoff + c * 32;
        CPA16(base,                  s); CPA16(base + 16,                  s + 8);
        s = Al + aoff + c * 32;
        CPA16(base + GS_ARR*2,       s); CPA16(base + GS_ARR*2 + 16,       s + 8);
        s = Bh + boff + c * 32;
        CPA16(base + 2*GS_ARR*2,     s); CPA16(base + 2*GS_ARR*2 + 16,     s + 8);
        s = Bl + boff + c * 32;
        CPA16(base + 3*GS_ARR*2,     s); CPA16(base + 3*GS_ARR*2 + 16,     s + 8);
    };

    const uint32_t lro = (uint32_t)((lane & 15) * GS_ROW + (lane >> 4) * 8) * 2;

    stage(0, 0);
    CPCOMMIT();
    for (int c = 0; c < 16; c++) {
        CPWAIT0();
        __syncthreads();
        if (c < 15) { stage(c + 1, (c + 1) & 1); CPCOMMIT(); }
        const uint32_t ab = sb + (uint32_t)(c & 1) * GS_BUF * 2;
        const uint32_t bbh = ab + 2 * GS_ARR * 2;
        #pragma unroll
        for (int ks = 0; ks < 2; ks++) {
            uint32_t bh[4][2], bl[4][2];
            #pragma unroll
            for (int j2 = 0; j2 < 2; j2++) {
                uint32_t tb[4];
                uint32_t ba = bbh + (uint32_t)((wn*32 + j2*16) * GS_ROW + ks*16) * 2 + lro;
                LDSM4(tb, ba);
                bh[j2*2][0] = tb[0]; bh[j2*2][1] = tb[2];
                bh[j2*2+1][0] = tb[1]; bh[j2*2+1][1] = tb[3];
                LDSM4(tb, ba + GS_ARR*2);
                bl[j2*2][0] = tb[0]; bl[j2*2][1] = tb[2];
                bl[j2*2+1][0] = tb[1]; bl[j2*2+1][1] = tb[3];
            }
            #pragma unroll
            for (int mi = 0; mi < 4; mi++) {
                uint32_t ah[4], al[4];
                uint32_t aa = ab + (uint32_t)((wm*64 + mi*16) * GS_ROW + ks*16) * 2 + lro;
                LDSM4(ah, aa);
                LDSM4(al, aa + GS_ARR*2);
                #pragma unroll
                for (int nj = 0; nj < 4; nj++) {
                    MMABF16(d[mi][nj], ah, bh[nj][0], bh[nj][1]);
                    MMABF16(d[mi][nj], ah, bl[nj][0], bl[nj][1]);
                    MMABF16(d[mi][nj], al, bh[nj][0], bh[nj][1]);
                }
            }
        }
    }

    const int g = lane >> 2, tq = lane & 3;
    #pragma unroll
    for (int mi = 0; mi < 4; mi++) {
        const int row = rb0 + wm*64 + mi*16 + g;
        #pragma unroll
        for (int nj = 0; nj < 4; nj++) {
            const int col = cb0 + wn*32 + nj*8 + tq*2;
            float2 bv = *(const float2*)&bias[col];
            float o0 = d[mi][nj][0] + bv.x, o1 = d[mi][nj][1] + bv.y;
            float o2 = d[mi][nj][2] + bv.x, o3 = d[mi][nj][3] + bv.y;
            if (C) {
                *(float2*)&C[(size_t)row * PD + col]       = make_float2(o0, o1);
                *(float2*)&C[(size_t)(row + 8) * PD + col] = make_float2(o2, o3);
            }
            if (Sh) {
                ushort h0,l0,h1,l1,h2,l2,h3,l3;
                bsplit(o0,h0,l0); bsplit(o1,h1,l1);
                bsplit(o2,h2,l2); bsplit(o3,h3,l3);
                *(uint32_t*)&Sh[(size_t)row * PD + col]       = (uint32_t)h0 | ((uint32_t)h1 << 16);
                *(uint32_t*)&Sl[(size_t)row * PD + col]       = (uint32_t)l0 | ((uint32_t)l1 << 16);
                *(uint32_t*)&Sh[(size_t)(row + 8) * PD + col] = (uint32_t)h2 | ((uint32_t)h3 << 16);
                *(uint32_t*)&Sl[(size_t)(row + 8) * PD + col] = (uint32_t)l2 | ((uint32_t)l3 << 16);
            }
        }
    }
}

// ------------------------- FiLM scale/shift prep ----------------------------
__global__ __launch_bounds__(128)
void film_prep(const float* __restrict__ latent, const float* __restrict__ Ws1,
               const float* __restrict__ bs1, float* __restrict__ ss) {
    const int b = blockIdx.y;
    const int col = blockIdx.x * 128 + threadIdx.x;
    __shared__ float ls[512];
    for (int i = threadIdx.x; i < 512; i += 128) {
        float x = latent[(size_t)b * 512 + i];
        ls[i] = x / (1.f + __expf(-x));
    }
    __syncthreads();
    float sum = 0.f;
    #pragma unroll 8
    for (int k = 0; k < 512; k++) sum += ls[k] * Ws1[(size_t)k * 1024 + col];
    ss[(size_t)b * 1024 + col] = sum + bs1[col];
}

// ------------------------- block reduce helper ------------------------------
__device__ __forceinline__ float2 blockReduceSum2(float s1, float s2) {
    __shared__ float sh[8];
    #pragma unroll
    for (int off = 16; off; off >>= 1) {
        s1 += __shfl_xor_sync(0xffffffffu, s1, off);
        s2 += __shfl_xor_sync(0xffffffffu, s2, off);
    }
    const int w = threadIdx.x >> 5;
    if ((threadIdx.x & 31) == 0) { sh[w * 2] = s1; sh[w * 2 + 1] = s2; }
    __syncthreads();
    float a = 0.f, b = 0.f;
    const int nw = blockDim.x >> 5;
    for (int i = 0; i < nw; i++) { a += sh[i * 2]; b += sh[i * 2 + 1]; }
    return make_float2(a, b);
}

// --------- FiLM apply: LN -> FiLM -> SiLU, fused bf16 split output ----------
__global__ __launch_bounds__(128)
void film_apply(const float* __restrict__ ofc, const float* __restrict__ ss,
                const float* __restrict__ g, const float* __restrict__ be,
                __nv_bfloat16* __restrict__ hsh, __nv_bfloat16* __restrict__ hsl) {
    const int row = blockIdx.x;
    const int b = row >> 10;
    const int t = threadIdx.x;
    const float* xr = ofc + (size_t)row * 512;
    float x[4]; float s1 = 0.f, s2 = 0.f;
    #pragma unroll
    for (int i = 0; i < 4; i++) {
        x[i] = xr[t + i * 128];
        s1 += x[i]; s2 += x[i] * x[i];
    }
    float2 r = blockReduceSum2(s1, s2);
    const float mean = r.x * (1.f / 512.f);
    const float var  = r.y * (1.f / 512.f) - mean * mean;
    const float rstd = rsqrtf(var + 1e-5f);
    const float* ssb = ss + (size_t)b * 1024;
    #pragma unroll
    for (int i = 0; i < 4; i++) {
        const int c = t + i * 128;
        float ln = (x[i] - mean) * rstd * g[c] + be[c];
        float h = ln * (1.f + ssb[c]) + ssb[512 + c];
        h = h / (1.f + __expf(-h));
        ushort hh, ll;
        bsplit(h, hh, ll);
        hsh[(size_t)row * 512 + c] = __ushort_as_bfloat16(hh);
        hsl[(size_t)row * 512 + c] = __ushort_as_bfloat16(ll);
    }
}

// ------------------------- final: LN(h2 + residual) -------------------------
__global__ __launch_bounds__(128)
void final_ln(const float* __restrict__ h2, const float* __restrict__ resid,
              const float* __restrict__ g, const float* __restrict__ be,
              float* __restrict__ out) {
    const int row = blockIdx.x;
    const int t = threadIdx.x;
    const float* hr = h2 + (size_t)row * 512;
    const float* rr = resid + (size_t)row * 512;
    float x[4]; float s1 = 0.f, s2 = 0.f;
    #pragma unroll
    for (int i = 0; i < 4; i++) {
        x[i] = hr[t + i * 128] + rr[t + i * 128];
        s1 += x[i]; s2 += x[i] * x[i];
    }
    float2 r = blockReduceSum2(s1, s2);
    const float mean = r.x * (1.f / 512.f);
    const float var  = r.y * (1.f / 512.f) - mean * mean;
    const float rstd = rsqrtf(var + 1e-6f);
    float* orow = out + (size_t)row * 512;
    #pragma unroll
    for (int i = 0; i < 4; i++) {
        const int c = t + i * 128;
        orow[c] = (x[i] - mean) * rstd * g[c] + be[c];
    }
}

// =================== tensorized attention (bf16-split MMA) ===================
// One CTA per (b, h, 32 q rows). smem (bytes):
//   [0, 131072)        S scores fp32 [32][1024]; after softmax each 4KB row is
//                      overwritten in place with P_hi (2KB) + P_lo (2KB), bf16,
//                      XOR-swizzled by ((row&7)<<4) at 16B granularity.
//   [131072, 140288)   Q hi/lo [32][72 halves] (144 B padded rows)
//   [140288, 214016)   2 x double buffer for K/V chunks: [128][72] hi + lo
#define AT_QH  131072u
#define AT_QL  135680u
#define AT_KV  140288u
#define AT_KVB 36864u
#define AT_SPL 18432u
#define AT_SMEM 214016

__global__ __launch_bounds__(256, 1)
void attn_mma(const __nv_bfloat16* __restrict__ Qh, const __nv_bfloat16* __restrict__ Ql,
              const __nv_bfloat16* __restrict__ Kh, const __nv_bfloat16* __restrict__ Kl,
              const __nv_bfloat16* __restrict__ Vh, const __nv_bfloat16* __restrict__ Vl,
              float* __restrict__ attn,
              __nv_bfloat16* __restrict__ Oh, __nv_bfloat16* __restrict__ Ol) {
    extern __shared__ char smem[];
    const uint32_t sb = stoa(smem);
    float* s_s = (float*)smem;

    const int b = blockIdx.z, h = blockIdx.y;
    const int q0 = blockIdx.x * 32;
    const int t = threadIdx.x;
    const int w = t >> 5, lane = t & 31;

    // ---- stage Q (32 rows x 128B x hi/lo), one cp.async 16B unit per thread per split
    {
        int row = t >> 3, seg = t & 7;
        size_t src = (size_t)(b * 1024 + q0 + row) * 512 + h * 64 + seg * 8;
        CPA16(sb + AT_QH + row * 144 + seg * 16, Qh + src);
        CPA16(sb + AT_QL + row * 144 + seg * 16, Ql + src);
    }
    // ---- stage K/V chunk helper: 128 rows x 128B, hi+lo
    auto stageKV = [&](const __nv_bfloat16* Xh, const __nv_bfloat16* Xl, int c, int buf) {
        int row = t >> 1, hf = t & 1;
        size_t src = (size_t)(b * 1024 + c * 128 + row) * 512 + h * 64 + hf * 32;
        uint32_t dst = sb + AT_KV + (uint32_t)buf * AT_KVB + row * 144 + hf * 64;
        #pragma unroll
        for (int i = 0; i < 4; i++) {
            CPA16(dst + i * 16,          Xh + src + i * 8);
            CPA16(dst + AT_SPL + i * 16, Xl + src + i * 8);
        }
    };

    stageKV(Kh, Kl, 0, 0);
    CPCOMMIT();
    CPWAIT0();
    __syncthreads();

    // ---- preload Q fragments: [split][mi][ks][4]
    uint32_t qa[2][2][4][4];
    #pragma unroll
    for (int s = 0; s < 2; s++)
        #pragma unroll
        for (int mi = 0; mi < 2; mi++)
            #pragma unroll
            for (int ks = 0; ks < 4; ks++) {
                uint32_t a = sb + (s ? AT_QL : AT_QH)
                           + (mi * 16 + (lane & 15)) * 144 + ks * 32 + (lane >> 4) * 16;
                LDSM4(qa[s][mi][ks], a);
            }

    // ---- Phase 1: S = (Q K^T) * 0.125 ----
    for (int c = 0; c < 8; c++) {
        if (c > 0) { CPWAIT0(); __syncthreads(); }
        if (c < 7) { stageKV(Kh, Kl, c + 1, (c + 1) & 1); CPCOMMIT(); }
        const uint32_t kb = sb + AT_KV + (uint32_t)(c & 1) * AT_KVB;
        float acc[2][2][4];
        #pragma unroll
        for (int mi = 0; mi < 2; mi++)
            #pragma unroll
            for (int nj = 0; nj < 2; nj++)
                #pragma unroll
                for (int r = 0; r < 4; r++) acc[mi][nj][r] = 0.f;
        #pragma unroll
        for (int ks = 0; ks < 4; ks++) {
            uint32_t kh4[4], kl4[4];
            uint32_t ka = kb + (w * 16 + (lane & 15)) * 144 + ks * 32 + (lane >> 4) * 16;
            LDSM4(kh4, ka);
            LDSM4(kl4, ka + AT_SPL);
            #pragma unroll
            for (int mi = 0; mi < 2; mi++) {
                MMABF16(acc[mi][0], qa[0][mi][ks], kh4[0], kh4[2]);
                MMABF16(acc[mi][1], qa[0][mi][ks], kh4[1], kh4[3]);
                MMABF16(acc[mi][0], qa[0][mi][ks], kl4[0], kl4[2]);
                MMABF16(acc[mi][1], qa[0][mi][ks], kl4[1], kl4[3]);
                MMABF16(acc[mi][0], qa[1][mi][ks], kh4[0], kh4[2]);
                MMABF16(acc[mi][1], qa[1][mi][ks], kh4[1], kh4[3]);
            }
        }
        #pragma unroll
        for (int mi = 0; mi < 2; mi++) {
            const int row = mi * 16 + (lane >> 2);
            #pragma unroll
            for (int nj = 0; nj < 2; nj++) {
                const int col = c * 128 + w * 16 + nj * 8 + (lane & 3) * 2;
                *(float2*)&s_s[(size_t)row * 1024 + col] =
                    make_float2(acc[mi][nj][0] * 0.125f, acc[mi][nj][1] * 0.125f);
                *(float2*)&s_s[(size_t)(row + 8) * 1024 + col] =
                    make_float2(acc[mi][nj][2] * 0.125f, acc[mi][nj][3] * 0.125f);
            }
        }
    }
    __syncthreads();

    // prefetch V chunk 0 while softmax runs
    stageKV(Vh, Vl, 0, 0);
    CPCOMMIT();

    // ---- Phase 2: softmax; write attn; convert P -> bf16 hi/lo in place ----
    float* attn_b = attn + (((size_t)(b * 8 + h)) * 1024 + q0) * 1024;
    #pragma unroll 1
    for (int i = 0; i < 4; i++) {
        const int r = 4 * w + i;
        const float* srow = s_s + (size_t)r * 1024;
        float2 pv[16];
        #pragma unroll
        for (int j = 0; j < 16; j++)
            pv[j] = *(const float2*)&srow[j * 64 + 2 * lane];
        float mx = -1e30f;
        #pragma unroll
        for (int j = 0; j < 16; j++)
            mx = fmaxf(mx, fmaxf(pv[j].x, pv[j].y));
        #pragma unroll
        for (int off = 16; off; off >>= 1)
            mx = fmaxf(mx, __shfl_xor_sync(0xffffffffu, mx, off));
        float sum = 0.f;
        #pragma unroll
        for (int j = 0; j < 16; j++) {
            pv[j].x = __expf(pv[j].x - mx);
            pv[j].y = __expf(pv[j].y - mx);
            sum += pv[j].x + pv[j].y;
        }
        #pragma unroll
        for (int off = 16; off; off >>= 1)
            sum += __shfl_xor_sync(0xffffffffu, sum, off);
        const float inv = 1.f / sum;
        float* arow = attn_b + (size_t)r * 1024;
        char* rowb = smem + (size_t)r * 4096;
        const uint32_t sw = (uint32_t)((r & 7) << 4);
        #pragma unroll
        for (int j = 0; j < 16; j++) {
            float p0 = pv[j].x * inv, p1 = pv[j].y * inv;
            *(float2*)&arow[j * 64 + 2 * lane] = make_float2(p0, p1);
            ushort h0, l0, h1, l1;
            bsplit(p0, h0, l0);
            bsplit(p1, h1, l1);
            uint32_t off = ((uint32_t)(j * 128 + lane * 4)) ^ sw;
            *(uint32_t*)(rowb + off)        = (uint32_t)h0 | ((uint32_t)h1 << 16);
            *(uint32_t*)(rowb + 2048 + off) = (uint32_t)l0 | ((uint32_t)l1 << 16);
        }
    }

    CPWAIT0();
    __syncthreads();

    // ---- Phase 3: O = P @ V (8-warp k-split) ----
    float oacc[2][8][4];
    #pragma unroll
    for (int mi = 0; mi < 2; mi++)
        #pragma unroll
        for (int nj = 0; nj < 8; nj++)
            #pragma unroll
            for (int r = 0; r < 4; r++) oacc[mi][nj][r] = 0.f;

    for (int c = 0; c < 8; c++) {
        if (c > 0) { CPWAIT0(); __syncthreads(); }
        if (c < 7) { stageKV(Vh, Vl, c + 1, (c + 1) & 1); CPCOMMIT(); }
        const uint32_t vb = sb + AT_KV + (uint32_t)(c & 1) * AT_KVB;
        const int k0 = c * 128 + w * 16;
        // A fragments from swizzled P
        uint32_t pa[2][2][4];   // [split][mi][4]
        #pragma unroll
        for (int s = 0; s < 2; s++)
            #pragma unroll
            for (int mi = 0; mi < 2; mi++) {
                const int row = mi * 16 + (lane & 15);
                uint32_t off = ((uint32_t)(2 * k0 + (lane >> 4) * 16)) ^ ((uint32_t)((row & 7) << 4));
                LDSM4(pa[s][mi], sb + (uint32_t)row * 4096 + (uint32_t)s * 2048 + off);
            }
        #pragma unroll
        for (int dd = 0; dd < 4; dd++) {
            uint32_t vbh[4], vbl[4];
            uint32_t va = vb + (w * 16 + (lane & 15)) * 144 + dd * 32 + (lane >> 4) * 16;
            LDSMT4(vbh, va);
            LDSMT4(vbl, va + AT_SPL);
            #pragma unroll
            for (int mi = 0; mi < 2; mi++) {
                MMABF16(oacc[mi][dd*2],   pa[0][mi], vbh[0], vbh[1]);
                MMABF16(oacc[mi][dd*2+1], pa[0][mi], vbh[2], vbh[3]);
                MMABF16(oacc[mi][dd*2],   pa[0][mi], vbl[0], vbl[1]);
                MMABF16(oacc[mi][dd*2+1], pa[0][mi], vbl[2], vbl[3]);
                MMABF16(oacc[mi][dd*2],   pa[1][mi], vbh[0], vbh[1]);
                MMABF16(oacc[mi][dd*2+1], pa[1][mi], vbh[2], vbh[3]);
            }
        }
    }
    __syncthreads();   // all warps done with V buffers before scratch reuse

    // ---- cross-warp O reduction in smem (reuse KV region) ----
    float* scr = (float*)(smem + AT_KV);
    #pragma unroll
    for (int mi = 0; mi < 2; mi++) {
        const int q = mi * 16 + (lane >> 2);
        #pragma unroll
        for (int nj = 0; nj < 8; nj++) {
            const int d = nj * 8 + (lane & 3) * 2;
            *(float2*)&scr[w * 2048 + q * 64 + d] =
                make_float2(oacc[mi][nj][0], oacc[mi][nj][1]);
            *(float2*)&scr[w * 2048 + (q + 8) * 64 + d] =
                make_float2(oacc[mi][nj][2], oacc[mi][nj][3]);
        }
    }
    __syncthreads();
    {
        const int base = t * 8;
        const int q = base >> 6, d = base & 63;
        float r8[8];
        #pragma unroll
        for (int j = 0; j < 8; j++) r8[j] = 0.f;
        #pragma unroll
        for (int ww = 0; ww < 8; ww++) {
            float4 a = *(float4*)&scr[ww * 2048 + base];
            float4 c = *(float4*)&scr[ww * 2048 + base + 4];
            r8[0] += a.x; r8[1] += a.y; r8[2] += a.z; r8[3] += a.w;
            r8[4] += c.x; r8[5] += c.y; r8[6] += c.z; r8[7] += c.w;
        }
        ushort hh[8], ll[8];
        #pragma unroll
        for (int j = 0; j < 8; j++) bsplit(r8[j], hh[j], ll[j]);
        uint4 hv, lv;
        hv.x = (uint32_t)hh[0] | ((uint32_t)hh[1] << 16);
        hv.y = (uint32_t)hh[2] | ((uint32_t)hh[3] << 16);
        hv.z = (uint32_t)hh[4] | ((uint32_t)hh[5] << 16);
        hv.w = (uint32_t)hh[6] | ((uint32_t)hh[7] << 16);
        lv.x = (uint32_t)ll[0] | ((uint32_t)ll[1] << 16);
        lv.y = (uint32_t)ll[2] | ((uint32_t)ll[3] << 16);
        lv.z = (uint32_t)ll[4] | ((uint32_t)ll[5] << 16);
        lv.w = (uint32_t)ll[6] | ((uint32_t)ll[7] << 16);
        const size_t orow = (size_t)(b * 1024 + q0 + q) * 512 + h * 64 + d;
        *(uint4*)&Oh[orow] = hv;
        *(uint4*)&Ol[orow] = lv;
    }
}

// ------------------------- launch -------------------------------------------
extern "C" void kernel_launch(void* const* d_in, const int* in_sizes, int n_in,
                              void* d_out, int out_size) {
    const float* q      = (const float*)d_in[0];
    const float* k      = (const float*)d_in[1];
    const float* v      = (const float*)d_in[2];
    const float* latent = (const float*)d_in[3];
    const float* Wq     = (const float*)d_in[4];
    const float* bq     = (const float*)d_in[5];
    const float* Wk     = (const float*)d_in[6];
    const float* bk     = (const float*)d_in[7];
    const float* Wv     = (const float*)d_in[8];
    const float* bv     = (const float*)d_in[9];
    const float* Wfc    = (const float*)d_in[10];
    const float* bfc    = (const float*)d_in[11];
    const float* Ws1    = (const float*)d_in[12];
    const float* bs1    = (const float*)d_in[13];
    const float* Ws2    = (const float*)d_in[14];
    const float* bs2    = (const float*)d_in[15];
    const float* en_g   = (const float*)d_in[16];
    const float* en_b   = (const float*)d_in[17];
    const float* ln_g   = (const float*)d_in[18];
    const float* ln_b   = (const float*)d_in[19];

    float* out  = (float*)d_out;                       // [B,L,D]
    float* attn = out + (size_t)BLD * PD;              // [B,H,L,L]

    float *gOFC, *gH2, *gSS;
    cudaGetSymbolAddress((void**)&gOFC, g_OFC);
    cudaGetSymbolAddress((void**)&gH2,  g_H2);
    cudaGetSymbolAddress((void**)&gSS,  g_SS);

    __nv_bfloat16 *qh,*ql,*kh,*kl,*vh,*vl;
    __nv_bfloat16 *Qh,*Ql,*Kh,*Kl,*Vh,*Vl,*Oh,*Ol,*HSh,*HSl,*Wth,*Wtl;
    cudaGetSymbolAddress((void**)&qh, g_qh);  cudaGetSymbolAddress((void**)&ql, g_ql);
    cudaGetSymbolAddress((void**)&kh, g_kh);  cudaGetSymbolAddress((void**)&kl, g_kl);
    cudaGetSymbolAddress((void**)&vh, g_vh);  cudaGetSymbolAddress((void**)&vl, g_vl);
    cudaGetSymbolAddress((void**)&Qh, g_Qh);  cudaGetSymbolAddress((void**)&Ql, g_Ql);
    cudaGetSymbolAddress((void**)&Kh, g_Kh);  cudaGetSymbolAddress((void**)&Kl, g_Kl);
    cudaGetSymbolAddress((void**)&Vh, g_Vh);  cudaGetSymbolAddress((void**)&Vl, g_Vl);
    cudaGetSymbolAddress((void**)&Oh, g_Oh);  cudaGetSymbolAddress((void**)&Ol, g_Ol);
    cudaGetSymbolAddress((void**)&HSh, g_HSh); cudaGetSymbolAddress((void**)&HSl, g_HSl);
    cudaGetSymbolAddress((void**)&Wth, g_Wth); cudaGetSymbolAddress((void**)&Wtl, g_Wtl);

    cudaFuncSetAttribute(attn_mma,
                         cudaFuncAttributeMaxDynamicSharedMemorySize, AT_SMEM);
    cudaFuncSetAttribute(gemm_bf16,
                         cudaFuncAttributeMaxDynamicSharedMemorySize, SMEM_GEMM);

    const size_t WSZ = (size_t)PD * PD;

    wprep<<<dim3(16, 16, 5), 256>>>(Wq, Wk, Wv, Wfc, Ws2, Wth, Wtl);
    split3<<<dim3(4096, 1, 3), 256>>>(q, k, v, qh, ql, kh, kl, vh, vl);
    film_prep<<<dim3(8, PB), 128>>>(latent, Ws1, bs1, gSS);

    // QKV projections -> bf16 split outputs only
    gemm_bf16<<<dim3(4, 64, 3), 256, SMEM_GEMM>>>(
        qh, ql, kh, kl, vh, vl,
        Wth, Wtl, Wth + WSZ, Wtl + WSZ, Wth + 2*WSZ, Wtl + 2*WSZ,
        bq, bk, bv,
        nullptr, nullptr, nullptr,
        Qh, Ql, Kh, Kl, Vh, Vl);

    attn_mma<<<dim3(PL / 32, PH, PB), 256, AT_SMEM>>>(
        Qh, Ql, Kh, Kl, Vh, Vl, attn, Oh, Ol);

    // FC -> fp32
    gemm_bf16<<<dim3(4, 64, 1), 256, SMEM_GEMM>>>(
        Oh, Ol, Oh, Ol, Oh, Ol,
        Wth + 3*WSZ, Wtl + 3*WSZ, Wth + 3*WSZ, Wtl + 3*WSZ, Wth + 3*WSZ, Wtl + 3*WSZ,
        bfc, bfc, bfc, gOFC, gOFC, gOFC,
        nullptr, nullptr, nullptr, nullptr, nullptr, nullptr);

    film_apply<<<BLD, 128>>>(gOFC, gSS, en_g, en_b, HSh, HSl);

    // S2 -> fp32
    gemm_bf16<<<dim3(4, 64, 1), 256, SMEM_GEMM>>>(
        HSh, HSl, HSh, HSl, HSh, HSl,
        Wth + 4*WSZ, Wtl + 4*WSZ, Wth + 4*WSZ, Wtl + 4*WSZ, Wth + 4*WSZ, Wtl + 4*WSZ,
        bs2, bs2, bs2, gH2, gH2, gH2,
        nullptr, nullptr, nullptr, nullptr, nullptr, nullptr);

    final_ln<<<BLD, 128>>>(gH2, q, ln_g, ln_b, out);
}

// round 14
// speedup vs baseline: 3.6524x; 1.3094x over previous
#include <cuda_runtime.h>
#include <cuda_bf16.h>
#include <cstddef>
#include <cstdint>

// Problem constants
#define PB 8
#define PL 1024
#define PD 512
#define PH 8
#define BLD (PB*PL)            // 8192 rows

// ------------------------- scratch (device globals) -------------------------
__device__ float g_OFC[BLD*PD];
__device__ float g_H2 [BLD*PD];
__device__ float g_SS [PB*2*PD];

// bf16 split operands
__device__ __nv_bfloat16 g_qh[BLD*PD], g_ql[BLD*PD];   // raw inputs q/k/v
__device__ __nv_bfloat16 g_kh[BLD*PD], g_kl[BLD*PD];
__device__ __nv_bfloat16 g_vh[BLD*PD], g_vl[BLD*PD];
__device__ __nv_bfloat16 g_Qh[BLD*PD], g_Ql[BLD*PD];   // projected Q/K/V
__device__ __nv_bfloat16 g_Kh[BLD*PD], g_Kl[BLD*PD];
__device__ __nv_bfloat16 g_Vh[BLD*PD], g_Vl[BLD*PD];
__device__ __nv_bfloat16 g_Oh[BLD*PD], g_Ol[BLD*PD];   // attention output
__device__ __nv_bfloat16 g_HSh[BLD*PD], g_HSl[BLD*PD]; // FiLM output
// 5 transposed+split weights: [n][k] layout, 512*512 each
__device__ __nv_bfloat16 g_Wth[5*PD*PD], g_Wtl[5*PD*PD];

// ------------------------- helpers ------------------------------------------
static __device__ __forceinline__ uint32_t stoa(const void* p) {
    uint32_t a;
    asm("{ .reg .u64 t; cvta.to.shared.u64 t, %1; cvt.u32.u64 %0, t; }"
        : "=r"(a) : "l"(p));
    return a;
}
static __device__ __forceinline__ void bsplit(float x, ushort& h, ushort& l) {
    __nv_bfloat16 hb = __float2bfloat16_rn(x);
    h = __bfloat16_as_ushort(hb);
    float r = x - __bfloat162float(hb);
    l = __bfloat16_as_ushort(__float2bfloat16_rn(r));
}

#define LDSM4(r, addr) \
    asm volatile("ldmatrix.sync.aligned.m8n8.x4.shared.b16 {%0,%1,%2,%3}, [%4];" \
        : "=r"((r)[0]),"=r"((r)[1]),"=r"((r)[2]),"=r"((r)[3]) : "r"(addr))

#define LDSMT4(r, addr) \
    asm volatile("ldmatrix.sync.aligned.m8n8.x4.trans.shared.b16 {%0,%1,%2,%3}, [%4];" \
        : "=r"((r)[0]),"=r"((r)[1]),"=r"((r)[2]),"=r"((r)[3]) : "r"(addr))

#define MMABF16(d, a, b0, b1) \
    asm volatile("mma.sync.aligned.m16n8k16.row.col.f32.bf16.bf16.f32 " \
        "{%0,%1,%2,%3}, {%4,%5,%6,%7}, {%8,%9}, {%0,%1,%2,%3};" \
        : "+f"((d)[0]),"+f"((d)[1]),"+f"((d)[2]),"+f"((d)[3]) \
        : "r"((a)[0]),"r"((a)[1]),"r"((a)[2]),"r"((a)[3]), "r"(b0),"r"(b1))

#define CPA16(dst, src) \
    asm volatile("cp.async.ca.shared.global [%0], [%1], 16;" :: "r"(dst), "l"(src))
#define CPCOMMIT() asm volatile("cp.async.commit_group;" ::: "memory")
#define CPWAIT0()  asm volatile("cp.async.wait_group 0;"  ::: "memory")
#define CPWAIT1()  asm volatile("cp.async.wait_group 1;"  ::: "memory")

// ==================== weight prep: W[k][n] -> Wt[n][k] hi/lo =================
__global__ __launch_bounds__(256)
void wprep(const float* __restrict__ W0, const float* __restrict__ W1,
           const float* __restrict__ W2, const float* __restrict__ W3,
           const float* __restrict__ W4,
           __nv_bfloat16* __restrict__ Wth, __nv_bfloat16* __restrict__ Wtl) {
    const int z = blockIdx.z;
    const float* W = z == 0 ? W0 : z == 1 ? W1 : z == 2 ? W2 : z == 3 ? W3 : W4;
    __nv_bfloat16* oh = Wth + (size_t)z * PD * PD;
    __nv_bfloat16* ol = Wtl + (size_t)z * PD * PD;
    __shared__ float tile[32][33];
    const int k0 = blockIdx.x * 32, n0 = blockIdx.y * 32;
    const int tx = threadIdx.x & 31, ty = threadIdx.x >> 5;
    #pragma unroll
    for (int i = 0; i < 4; i++)
        tile[ty + 8 * i][tx] = W[(size_t)(k0 + ty + 8 * i) * PD + n0 + tx];
    __syncthreads();
    #pragma unroll
    for (int i = 0; i < 4; i++) {
        int n = n0 + ty + 8 * i, k = k0 + tx;
        ushort h, l;
        bsplit(tile[tx][ty + 8 * i], h, l);
        oh[(size_t)n * PD + k] = __ushort_as_bfloat16(h);
        ol[(size_t)n * PD + k] = __ushort_as_bfloat16(l);
    }
}

// ==================== split q/k/v fp32 -> bf16 hi/lo =========================
__global__ __launch_bounds__(256)
void split3(const float* __restrict__ x0, const float* __restrict__ x1,
            const float* __restrict__ x2,
            __nv_bfloat16* __restrict__ h0, __nv_bfloat16* __restrict__ l0,
            __nv_bfloat16* __restrict__ h1, __nv_bfloat16* __restrict__ l1,
            __nv_bfloat16* __restrict__ h2, __nv_bfloat16* __restrict__ l2) {
    const int z = blockIdx.z;
    const float* in = z == 0 ? x0 : z == 1 ? x1 : x2;
    __nv_bfloat16* oh = z == 0 ? h0 : z == 1 ? h1 : h2;
    __nv_bfloat16* ol = z == 0 ? l0 : z == 1 ? l1 : l2;
    size_t i = ((size_t)blockIdx.x * 256 + threadIdx.x) * 4;
    float4 f = *(const float4*)&in[i];
    ushort h[4], l[4];
    bsplit(f.x, h[0], l[0]); bsplit(f.y, h[1], l[1]);
    bsplit(f.z, h[2], l[2]); bsplit(f.w, h[3], l[3]);
    uint2 hv = make_uint2((uint32_t)h[0] | ((uint32_t)h[1] << 16),
                          (uint32_t)h[2] | ((uint32_t)h[3] << 16));
    uint2 lv = make_uint2((uint32_t)l[0] | ((uint32_t)l[1] << 16),
                          (uint32_t)l[2] | ((uint32_t)l[3] << 16));
    *(uint2*)&oh[i] = hv;
    *(uint2*)&ol[i] = lv;
}

// ==================== bf16-split mma.sync GEMM ===============================
#define GS_ROW 40
#define GS_ARR (128*GS_ROW)                 // 5120 halves
#define GS_BUF (4*GS_ARR)                   // 20480 halves
#define SMEM_GEMM (2*GS_BUF*2)              // 81920 bytes

__global__ __launch_bounds__(256, 2)
void gemm_bf16(const __nv_bfloat16* __restrict__ Ah0, const __nv_bfloat16* __restrict__ Al0,
               const __nv_bfloat16* __restrict__ Ah1, const __nv_bfloat16* __restrict__ Al1,
               const __nv_bfloat16* __restrict__ Ah2, const __nv_bfloat16* __restrict__ Al2,
               const __nv_bfloat16* __restrict__ Bh0, const __nv_bfloat16* __restrict__ Bl0,
               const __nv_bfloat16* __restrict__ Bh1, const __nv_bfloat16* __restrict__ Bl1,
               const __nv_bfloat16* __restrict__ Bh2, const __nv_bfloat16* __restrict__ Bl2,
               const float* __restrict__ bias0, const float* __restrict__ bias1,
               const float* __restrict__ bias2,
               float* __restrict__ C0, float* __restrict__ C1, float* __restrict__ C2,
               __nv_bfloat16* __restrict__ Sh0, __nv_bfloat16* __restrict__ Sl0,
               __nv_bfloat16* __restrict__ Sh1, __nv_bfloat16* __restrict__ Sl1,
               __nv_bfloat16* __restrict__ Sh2, __nv_bfloat16* __restrict__ Sl2) {
    extern __shared__ __nv_bfloat16 hsm[];
    const int z = blockIdx.z;
    const __nv_bfloat16* Ah = z == 0 ? Ah0 : z == 1 ? Ah1 : Ah2;
    const __nv_bfloat16* Al = z == 0 ? Al0 : z == 1 ? Al1 : Al2;
    const __nv_bfloat16* Bh = z == 0 ? Bh0 : z == 1 ? Bh1 : Bh2;
    const __nv_bfloat16* Bl = z == 0 ? Bl0 : z == 1 ? Bl1 : Bl2;
    const float* bias = z == 0 ? bias0 : z == 1 ? bias1 : bias2;
    float* C          = z == 0 ? C0 : z == 1 ? C1 : C2;
    __nv_bfloat16* Sh = z == 0 ? Sh0 : z == 1 ? Sh1 : Sh2;
    __nv_bfloat16* Sl = z == 0 ? Sl0 : z == 1 ? Sl1 : Sl2;

    const int cb0 = blockIdx.x * 128;
    const int rb0 = blockIdx.y * 128;
    const int t = threadIdx.x;
    const int wid = t >> 5, lane = t & 31;
    const int wm = wid & 1, wn = wid >> 1;
    const uint32_t sb = stoa(hsm);

    const int srow = t >> 1, sh16 = (t & 1) * 16;
    const size_t aoff = (size_t)(rb0 + srow) * PD + sh16;
    const size_t boff = (size_t)(cb0 + srow) * PD + sh16;
    const uint32_t sdst = (uint32_t)(srow * GS_ROW + sh16) * 2;

    float d[4][4][4];
    #pragma unroll
    for (int i = 0; i < 4; i++)
        #pragma unroll
        for (int j = 0; j < 4; j++)
            #pragma unroll
            for (int r = 0; r < 4; r++) d[i][j][r] = 0.f;

    auto stage = [&](int c, int buf) {
        const uint32_t base = sb + (uint32_t)buf * GS_BUF * 2 + sdst;
        const __nv_bfloat16* s;
        s = Ah + aoff + c * 32;
        CPA16(base,                  s); CPA16(base + 16,                  s + 8);
        s = Al + aoff + c * 32;
        CPA16(base + GS_ARR*2,       s); CPA16(base + GS_ARR*2 + 16,       s + 8);
        s = Bh + boff + c * 32;
        CPA16(base + 2*GS_ARR*2,     s); CPA16(base + 2*GS_ARR*2 + 16,     s + 8);
        s = Bl + boff + c * 32;
        CPA16(base + 3*GS_ARR*2,     s); CPA16(base + 3*GS_ARR*2 + 16,     s + 8);
    };

    const uint32_t lro = (uint32_t)((lane & 15) * GS_ROW + (lane >> 4) * 8) * 2;

    stage(0, 0);
    CPCOMMIT();
    for (int c = 0; c < 16; c++) {
        CPWAIT0();
        __syncthreads();
        if (c < 15) { stage(c + 1, (c + 1) & 1); CPCOMMIT(); }
        const uint32_t ab = sb + (uint32_t)(c & 1) * GS_BUF * 2;
        const uint32_t bbh = ab + 2 * GS_ARR * 2;
        #pragma unroll
        for (int ks = 0; ks < 2; ks++) {
            uint32_t bh[4][2], bl[4][2];
            #pragma unroll
            for (int j2 = 0; j2 < 2; j2++) {
                uint32_t tb[4];
                uint32_t ba = bbh + (uint32_t)((wn*32 + j2*16) * GS_ROW + ks*16) * 2 + lro;
                LDSM4(tb, ba);
                bh[j2*2][0] = tb[0]; bh[j2*2][1] = tb[2];
                bh[j2*2+1][0] = tb[1]; bh[j2*2+1][1] = tb[3];
                LDSM4(tb, ba + GS_ARR*2);
                bl[j2*2][0] = tb[0]; bl[j2*2][1] = tb[2];
                bl[j2*2+1][0] = tb[1]; bl[j2*2+1][1] = tb[3];
            }
            #pragma unroll
            for (int mi = 0; mi < 4; mi++) {
                uint32_t ah[4], al[4];
                uint32_t aa = ab + (uint32_t)((wm*64 + mi*16) * GS_ROW + ks*16) * 2 + lro;
                LDSM4(ah, aa);
                LDSM4(al, aa + GS_ARR*2);
                #pragma unroll
                for (int nj = 0; nj < 4; nj++) {
                    MMABF16(d[mi][nj], ah, bh[nj][0], bh[nj][1]);
                    MMABF16(d[mi][nj], ah, bl[nj][0], bl[nj][1]);
                    MMABF16(d[mi][nj], al, bh[nj][0], bh[nj][1]);
                }
            }
        }
    }

    const int g = lane >> 2, tq = lane & 3;
    #pragma unroll
    for (int mi = 0; mi < 4; mi++) {
        const int row = rb0 + wm*64 + mi*16 + g;
        #pragma unroll
        for (int nj = 0; nj < 4; nj++) {
            const int col = cb0 + wn*32 + nj*8 + tq*2;
            float2 bv = *(const float2*)&bias[col];
            float o0 = d[mi][nj][0] + bv.x, o1 = d[mi][nj][1] + bv.y;
            float o2 = d[mi][nj][2] + bv.x, o3 = d[mi][nj][3] + bv.y;
            if (C) {
                *(float2*)&C[(size_t)row * PD + col]       = make_float2(o0, o1);
                *(float2*)&C[(size_t)(row + 8) * PD + col] = make_float2(o2, o3);
            }
            if (Sh) {
                ushort h0,l0,h1,l1,h2,l2,h3,l3;
                bsplit(o0,h0,l0); bsplit(o1,h1,l1);
                bsplit(o2,h2,l2); bsplit(o3,h3,l3);
                *(uint32_t*)&Sh[(size_t)row * PD + col]       = (uint32_t)h0 | ((uint32_t)h1 << 16);
                *(uint32_t*)&Sl[(size_t)row * PD + col]       = (uint32_t)l0 | ((uint32_t)l1 << 16);
                *(uint32_t*)&Sh[(size_t)(row + 8) * PD + col] = (uint32_t)h2 | ((uint32_t)h3 << 16);
                *(uint32_t*)&Sl[(size_t)(row + 8) * PD + col] = (uint32_t)l2 | ((uint32_t)l3 << 16);
            }
        }
    }
}

// ------------------------- FiLM scale/shift prep ----------------------------
__global__ __launch_bounds__(128)
void film_prep(const float* __restrict__ latent, const float* __restrict__ Ws1,
               const float* __restrict__ bs1, float* __restrict__ ss) {
    const int b = blockIdx.y;
    const int col = blockIdx.x * 128 + threadIdx.x;
    __shared__ float ls[512];
    for (int i = threadIdx.x; i < 512; i += 128) {
        float x = latent[(size_t)b * 512 + i];
        ls[i] = x / (1.f + __expf(-x));
    }
    __syncthreads();
    float sum = 0.f;
    #pragma unroll 8
    for (int k = 0; k < 512; k++) sum += ls[k] * Ws1[(size_t)k * 1024 + col];
    ss[(size_t)b * 1024 + col] = sum + bs1[col];
}

// ------------------------- block reduce helper ------------------------------
__device__ __forceinline__ float2 blockReduceSum2(float s1, float s2) {
    __shared__ float sh[8];
    #pragma unroll
    for (int off = 16; off; off >>= 1) {
        s1 += __shfl_xor_sync(0xffffffffu, s1, off);
        s2 += __shfl_xor_sync(0xffffffffu, s2, off);
    }
    const int w = threadIdx.x >> 5;
    if ((threadIdx.x & 31) == 0) { sh[w * 2] = s1; sh[w * 2 + 1] = s2; }
    __syncthreads();
    float a = 0.f, b = 0.f;
    const int nw = blockDim.x >> 5;
    for (int i = 0; i < nw; i++) { a += sh[i * 2]; b += sh[i * 2 + 1]; }
    return make_float2(a, b);
}

// --------- FiLM apply: LN -> FiLM -> SiLU, fused bf16 split output ----------
__global__ __launch_bounds__(128)
void film_apply(const float* __restrict__ ofc, const float* __restrict__ ss,
                const float* __restrict__ g, const float* __restrict__ be,
                __nv_bfloat16* __restrict__ hsh, __nv_bfloat16* __restrict__ hsl) {
    const int row = blockIdx.x;
    const int b = row >> 10;
    const int t = threadIdx.x;
    const float* xr = ofc + (size_t)row * 512;
    float x[4]; float s1 = 0.f, s2 = 0.f;
    #pragma unroll
    for (int i = 0; i < 4; i++) {
        x[i] = xr[t + i * 128];
        s1 += x[i]; s2 += x[i] * x[i];
    }
    float2 r = blockReduceSum2(s1, s2);
    const float mean = r.x * (1.f / 512.f);
    const float var  = r.y * (1.f / 512.f) - mean * mean;
    const float rstd = rsqrtf(var + 1e-5f);
    const float* ssb = ss + (size_t)b * 1024;
    #pragma unroll
    for (int i = 0; i < 4; i++) {
        const int c = t + i * 128;
        float ln = (x[i] - mean) * rstd * g[c] + be[c];
        float h = ln * (1.f + ssb[c]) + ssb[512 + c];
        h = h / (1.f + __expf(-h));
        ushort hh, ll;
        bsplit(h, hh, ll);
        hsh[(size_t)row * 512 + c] = __ushort_as_bfloat16(hh);
        hsl[(size_t)row * 512 + c] = __ushort_as_bfloat16(ll);
    }
}

// ------------------------- final: LN(h2 + residual) -------------------------
__global__ __launch_bounds__(128)
void final_ln(const float* __restrict__ h2, const float* __restrict__ resid,
              const float* __restrict__ g, const float* __restrict__ be,
              float* __restrict__ out) {
    const int row = blockIdx.x;
    const int t = threadIdx.x;
    const float* hr = h2 + (size_t)row * 512;
    const float* rr = resid + (size_t)row * 512;
    float x[4]; float s1 = 0.f, s2 = 0.f;
    #pragma unroll
    for (int i = 0; i < 4; i++) {
        x[i] = hr[t + i * 128] + rr[t + i * 128];
        s1 += x[i]; s2 += x[i] * x[i];
    }
    float2 r = blockReduceSum2(s1, s2);
    const float mean = r.x * (1.f / 512.f);
    const float var  = r.y * (1.f / 512.f) - mean * mean;
    const float rstd = rsqrtf(var + 1e-6f);
    float* orow = out + (size_t)row * 512;
    #pragma unroll
    for (int i = 0; i < 4; i++) {
        const int c = t + i * 128;
        orow[c] = (x[i] - mean) * rstd * g[c] + be[c];
    }
}

// ============ tensorized attention, register-resident S (FA-style) ==========
// One CTA per (b, h, 32 q rows). S never touches smem: QK^T C-fragments stay
// in registers, softmax is in-register with tiny cross-warp reductions, P
// hi/lo A-fragments are packed in registers (C-layout == A-layout), PV uses
// ldmatrix.trans on V. K/V chunks: 4-buffer cp.async pipeline, depth 2.
// smem: [0,9216) Q stage (2 x 32 x 144B); also reduction scratch (phase 2)
//       [10240, 10240+4*36864) K/V buffers (hi at +0, lo at +18432 each)
#define AT_QHO 0u
#define AT_QLO 4608u
#define AT_KV  10240u
#define AT_KVB 36864u
#define AT_SPL 18432u
#define AT_SMEM (10240 + 4*36864)

__global__ __launch_bounds__(256, 1)
void attn_mma(const __nv_bfloat16* __restrict__ Qh, const __nv_bfloat16* __restrict__ Ql,
              const __nv_bfloat16* __restrict__ Kh, const __nv_bfloat16* __restrict__ Kl,
              const __nv_bfloat16* __restrict__ Vh, const __nv_bfloat16* __restrict__ Vl,
              float* __restrict__ attn,
              __nv_bfloat16* __restrict__ Oh, __nv_bfloat16* __restrict__ Ol) {
    extern __shared__ char smem[];
    const uint32_t sb = stoa(smem);

    const int b = blockIdx.z, h = blockIdx.y;
    const int q0 = blockIdx.x * 32;
    const int t = threadIdx.x;
    const int w = t >> 5, lane = t & 31;
    const int g = lane >> 2, tq = lane & 3;

    // ---- stage Q (32 rows x 128B x hi/lo)
    {
        int row = t >> 3, seg = t & 7;
        size_t src = (size_t)(b * 1024 + q0 + row) * 512 + h * 64 + seg * 8;
        CPA16(sb + AT_QHO + row * 144 + seg * 16, Qh + src);
        CPA16(sb + AT_QLO + row * 144 + seg * 16, Ql + src);
    }
    auto stageKV = [&](const __nv_bfloat16* Xh, const __nv_bfloat16* Xl, int c, int buf) {
        int row = t >> 1, hf = t & 1;
        size_t src = (size_t)(b * 1024 + c * 128 + row) * 512 + h * 64 + hf * 32;
        uint32_t dst = sb + AT_KV + (uint32_t)buf * AT_KVB + row * 144 + hf * 64;
        #pragma unroll
        for (int i = 0; i < 4; i++) {
            CPA16(dst + i * 16,          Xh + src + i * 8);
            CPA16(dst + AT_SPL + i * 16, Xl + src + i * 8);
        }
    };

    stageKV(Kh, Kl, 0, 0);   // group 0: Q + K0
    CPCOMMIT();
    stageKV(Kh, Kl, 1, 1);   // group 1: K1
    CPCOMMIT();
    CPWAIT1();               // Q + K0 ready
    __syncthreads();

    // ---- preload Q fragments: [split][mi][ks][4]
    uint32_t qa[2][2][4][4];
    #pragma unroll
    for (int s = 0; s < 2; s++)
        #pragma unroll
        for (int mi = 0; mi < 2; mi++)
            #pragma unroll
            for (int ks = 0; ks < 4; ks++) {
                uint32_t a = sb + (s ? AT_QLO : AT_QHO)
                           + (mi * 16 + (lane & 15)) * 144 + ks * 32 + (lane >> 4) * 16;
                LDSM4(qa[s][mi][ks], a);
            }

    // ---- Phase 1: S = Q K^T, all chunks, accumulators stay in registers ----
    float acc[8][2][2][4];
    #pragma unroll
    for (int c = 0; c < 8; c++)
        #pragma unroll
        for (int mi = 0; mi < 2; mi++)
            #pragma unroll
            for (int nj = 0; nj < 2; nj++)
                #pragma unroll
                for (int r = 0; r < 4; r++) acc[c][mi][nj][r] = 0.f;

    #pragma unroll
    for (int c = 0; c < 8; c++) {
        if (c > 0) {
            if (c < 7) { CPWAIT1(); } else { CPWAIT0(); }
            __syncthreads();
        }
        if (c + 2 < 8) { stageKV(Kh, Kl, c + 2, (c + 2) & 3); CPCOMMIT(); }
        const uint32_t kb = sb + AT_KV + (uint32_t)(c & 3) * AT_KVB;
        #pragma unroll
        for (int ks = 0; ks < 4; ks++) {
            uint32_t kh4[4], kl4[4];
            uint32_t ka = kb + (w * 16 + (lane & 15)) * 144 + ks * 32 + (lane >> 4) * 16;
            LDSM4(kh4, ka);
            LDSM4(kl4, ka + AT_SPL);
            #pragma unroll
            for (int mi = 0; mi < 2; mi++) {
                MMABF16(acc[c][mi][0], qa[0][mi][ks], kh4[0], kh4[2]);
                MMABF16(acc[c][mi][1], qa[0][mi][ks], kh4[1], kh4[3]);
                MMABF16(acc[c][mi][0], qa[0][mi][ks], kl4[0], kl4[2]);
                MMABF16(acc[c][mi][1], qa[0][mi][ks], kl4[1], kl4[3]);
                MMABF16(acc[c][mi][0], qa[1][mi][ks], kh4[0], kh4[2]);
                MMABF16(acc[c][mi][1], qa[1][mi][ks], kh4[1], kh4[3]);
            }
        }
    }

    // prefetch V chunks 0,1 while softmax runs (bufs 0,1 last read at c=4,5)
    stageKV(Vh, Vl, 0, 0); CPCOMMIT();
    stageKV(Vh, Vl, 1, 1); CPCOMMIT();

    // ---- Phase 2: in-register softmax; row stats via smem [32][8] ----------
    float* red = (float*)smem;       // max at [0,256), sum at [256,512)
    float mxv[2][2], inv[2][2];
    #pragma unroll
    for (int mi = 0; mi < 2; mi++)
        #pragma unroll
        for (int hf = 0; hf < 2; hf++) {
            float m = -1e30f;
            #pragma unroll
            for (int c = 0; c < 8; c++)
                #pragma unroll
                for (int nj = 0; nj < 2; nj++)
                    m = fmaxf(m, fmaxf(acc[c][mi][nj][hf*2], acc[c][mi][nj][hf*2+1]));
            m = fmaxf(m, __shfl_xor_sync(0xffffffffu, m, 1));
            m = fmaxf(m, __shfl_xor_sync(0xffffffffu, m, 2));
            if (tq == 0) red[(mi*16 + hf*8 + g) * 8 + w] = m;
        }
    __syncthreads();
    #pragma unroll
    for (int mi = 0; mi < 2; mi++)
        #pragma unroll
        for (int hf = 0; hf < 2; hf++) {
            const int row = mi*16 + hf*8 + g;
            float m = red[row*8];
            #pragma unroll
            for (int ww = 1; ww < 8; ww++) m = fmaxf(m, red[row*8 + ww]);
            mxv[mi][hf] = m;
        }
    #pragma unroll
    for (int mi = 0; mi < 2; mi++)
        #pragma unroll
        for (int hf = 0; hf < 2; hf++) {
            float s = 0.f;
            #pragma unroll
            for (int c = 0; c < 8; c++)
                #pragma unroll
                for (int nj = 0; nj < 2; nj++)
                    #pragma unroll
                    for (int kk = 0; kk < 2; kk++) {
                        float& v = acc[c][mi][nj][hf*2 + kk];
                        v = __expf((v - mxv[mi][hf]) * 0.125f);
                        s += v;
                    }
            s += __shfl_xor_sync(0xffffffffu, s, 1);
            s += __shfl_xor_sync(0xffffffffu, s, 2);
            if (tq == 0) red[256 + (mi*16 + hf*8 + g) * 8 + w] = s;
        }
    __syncthreads();
    #pragma unroll
    for (int mi = 0; mi < 2; mi++)
        #pragma unroll
        for (int hf = 0; hf < 2; hf++) {
            const int row = mi*16 + hf*8 + g;
            float s = 0.f;
            #pragma unroll
            for (int ww = 0; ww < 8; ww++) s += red[256 + row*8 + ww];
            inv[mi][hf] = 1.f / s;
        }

    // ---- normalize, write attn, pack P hi/lo A-fragments in registers -----
    float* attn_b = attn + (((size_t)(b * 8 + h)) * 1024 + q0) * 1024;
    uint32_t pah[8][2][4], pal[8][2][4];
    #pragma unroll
    for (int c = 0; c < 8; c++)
        #pragma unroll
        for (int mi = 0; mi < 2; mi++) {
            const int row0 = mi * 16 + g;
            const int col = c * 128 + w * 16 + tq * 2;
            float p00 = acc[c][mi][0][0] * inv[mi][0];
            float p01 = acc[c][mi][0][1] * inv[mi][0];
            float p02 = acc[c][mi][0][2] * inv[mi][1];
            float p03 = acc[c][mi][0][3] * inv[mi][1];
            float p10 = acc[c][mi][1][0] * inv[mi][0];
            float p11 = acc[c][mi][1][1] * inv[mi][0];
            float p12 = acc[c][mi][1][2] * inv[mi][1];
            float p13 = acc[c][mi][1][3] * inv[mi][1];
            *(float2*)&attn_b[(size_t)row0 * 1024 + col]           = make_float2(p00, p01);
            *(float2*)&attn_b[(size_t)(row0 + 8) * 1024 + col]     = make_float2(p02, p03);
            *(float2*)&attn_b[(size_t)row0 * 1024 + col + 8]       = make_float2(p10, p11);
            *(float2*)&attn_b[(size_t)(row0 + 8) * 1024 + col + 8] = make_float2(p12, p13);
            ushort h00,l00,h01,l01,h02,l02,h03,l03;
            ushort h10,l10,h11,l11,h12,l12,h13,l13;
            bsplit(p00,h00,l00); bsplit(p01,h01,l01);
            bsplit(p02,h02,l02); bsplit(p03,h03,l03);
            bsplit(p10,h10,l10); bsplit(p11,h11,l11);
            bsplit(p12,h12,l12); bsplit(p13,h13,l13);
            pah[c][mi][0] = (uint32_t)h00 | ((uint32_t)h01 << 16);
            pah[c][mi][1] = (uint32_t)h02 | ((uint32_t)h03 << 16);
            pah[c][mi][2] = (uint32_t)h10 | ((uint32_t)h11 << 16);
            pah[c][mi][3] = (uint32_t)h12 | ((uint32_t)h13 << 16);
            pal[c][mi][0] = (uint32_t)l00 | ((uint32_t)l01 << 16);
            pal[c][mi][1] = (uint32_t)l02 | ((uint32_t)l03 << 16);
            pal[c][mi][2] = (uint32_t)l10 | ((uint32_t)l11 << 16);
            pal[c][mi][3] = (uint32_t)l12 | ((uint32_t)l13 << 16);
        }

    // ---- Phase 3: O = P @ V (8-warp k-split, regs A-frags, ldsm.trans V) ---
    float oacc[2][8][4];
    #pragma unroll
    for (int mi = 0; mi < 2; mi++)
        #pragma unroll
        for (int nj = 0; nj < 8; nj++)
            #pragma unroll
            for (int r = 0; r < 4; r++) oacc[mi][nj][r] = 0.f;

    CPWAIT1();               // V0 ready
    __syncthreads();
    #pragma unroll
    for (int c = 0; c < 8; c++) {
        if (c > 0) {
            if (c < 7) { CPWAIT1(); } else { CPWAIT0(); }
            __syncthreads();
        }
        if (c + 2 < 8) { stageKV(Vh, Vl, c + 2, (c + 2) & 3); CPCOMMIT(); }
        const uint32_t vb = sb + AT_KV + (uint32_t)(c & 3) * AT_KVB;
        #pragma unroll
        for (int dd = 0; dd < 4; dd++) {
            uint32_t vbh[4], vbl[4];
            uint32_t va = vb + (w * 16 + (lane & 15)) * 144 + dd * 32 + (lane >> 4) * 16;
            LDSMT4(vbh, va);
            LDSMT4(vbl, va + AT_SPL);
            #pragma unroll
            for (int mi = 0; mi < 2; mi++) {
                MMABF16(oacc[mi][dd*2],   pah[c][mi], vbh[0], vbh[1]);
                MMABF16(oacc[mi][dd*2+1], pah[c][mi], vbh[2], vbh[3]);
                MMABF16(oacc[mi][dd*2],   pah[c][mi], vbl[0], vbl[1]);
                MMABF16(oacc[mi][dd*2+1], pah[c][mi], vbl[2], vbl[3]);
                MMABF16(oacc[mi][dd*2],   pal[c][mi], vbh[0], vbh[1]);
                MMABF16(oacc[mi][dd*2+1], pal[c][mi], vbh[2], vbh[3]);
            }
        }
    }
    __syncthreads();   // all warps done with V buffers before scratch reuse

    // ---- cross-warp O reduction in smem (reuse KV region) ----
    float* scr = (float*)(smem + AT_KV);
    #pragma unroll
    for (int mi = 0; mi < 2; mi++) {
        const int q = mi * 16 + g;
        #pragma unroll
        for (int nj = 0; nj < 8; nj++) {
            const int d = nj * 8 + tq * 2;
            *(float2*)&scr[w * 2048 + q * 64 + d] =
                make_float2(oacc[mi][nj][0], oacc[mi][nj][1]);
            *(float2*)&scr[w * 2048 + (q + 8) * 64 + d] =
                make_float2(oacc[mi][nj][2], oacc[mi][nj][3]);
        }
    }
    __syncthreads();
    {
        const int base = t * 8;
        const int q = base >> 6, d = base & 63;
        float r8[8];
        #pragma unroll
        for (int j = 0; j < 8; j++) r8[j] = 0.f;
        #pragma unroll
        for (int ww = 0; ww < 8; ww++) {
            float4 a = *(float4*)&scr[ww * 2048 + base];
            float4 c = *(float4*)&scr[ww * 2048 + base + 4];
            r8[0] += a.x; r8[1] += a.y; r8[2] += a.z; r8[3] += a.w;
            r8[4] += c.x; r8[5] += c.y; r8[6] += c.z; r8[7] += c.w;
        }
        ushort hh[8], ll[8];
        #pragma unroll
        for (int j = 0; j < 8; j++) bsplit(r8[j], hh[j], ll[j]);
        uint4 hv, lv;
        hv.x = (uint32_t)hh[0] | ((uint32_t)hh[1] << 16);
        hv.y = (uint32_t)hh[2] | ((uint32_t)hh[3] << 16);
        hv.z = (uint32_t)hh[4] | ((uint32_t)hh[5] << 16);
        hv.w = (uint32_t)hh[6] | ((uint32_t)hh[7] << 16);
        lv.x = (uint32_t)ll[0] | ((uint32_t)ll[1] << 16);
        lv.y = (uint32_t)ll[2] | ((uint32_t)ll[3] << 16);
        lv.z = (uint32_t)ll[4] | ((uint32_t)ll[5] << 16);
        lv.w = (uint32_t)ll[6] | ((uint32_t)ll[7] << 16);
        const size_t orow = (size_t)(b * 1024 + q0 + q) * 512 + h * 64 + d;
        *(uint4*)&Oh[orow] = hv;
        *(uint4*)&Ol[orow] = lv;
    }
}

// ------------------------- launch -------------------------------------------
extern "C" void kernel_launch(void* const* d_in, const int* in_sizes, int n_in,
                              void* d_out, int out_size) {
    const float* q      = (const float*)d_in[0];
    const float* k      = (const float*)d_in[1];
    const float* v      = (const float*)d_in[2];
    const float* latent = (const float*)d_in[3];
    const float* Wq     = (const float*)d_in[4];
    const float* bq     = (const float*)d_in[5];
    const float* Wk     = (const float*)d_in[6];
    const float* bk     = (const float*)d_in[7];
    const float* Wv     = (const float*)d_in[8];
    const float* bv     = (const float*)d_in[9];
    const float* Wfc    = (const float*)d_in[10];
    const float* bfc    = (const float*)d_in[11];
    const float* Ws1    = (const float*)d_in[12];
    const float* bs1    = (const float*)d_in[13];
    const float* Ws2    = (const float*)d_in[14];
    const float* bs2    = (const float*)d_in[15];
    const float* en_g   = (const float*)d_in[16];
    const float* en_b   = (const float*)d_in[17];
    const float* ln_g   = (const float*)d_in[18];
    const float* ln_b   = (const float*)d_in[19];

    float* out  = (float*)d_out;                       // [B,L,D]
    float* attn = out + (size_t)BLD * PD;              // [B,H,L,L]

    float *gOFC, *gH2, *gSS;
    cudaGetSymbolAddress((void**)&gOFC, g_OFC);
    cudaGetSymbolAddress((void**)&gH2,  g_H2);
    cudaGetSymbolAddress((void**)&gSS,  g_SS);

    __nv_bfloat16 *qh,*ql,*kh,*kl,*vh,*vl;
    __nv_bfloat16 *Qh,*Ql,*Kh,*Kl,*Vh,*Vl,*Oh,*Ol,*HSh,*HSl,*Wth,*Wtl;
    cudaGetSymbolAddress((void**)&qh, g_qh);  cudaGetSymbolAddress((void**)&ql, g_ql);
    cudaGetSymbolAddress((void**)&kh, g_kh);  cudaGetSymbolAddress((void**)&kl, g_kl);
    cudaGetSymbolAddress((void**)&vh, g_vh);  cudaGetSymbolAddress((void**)&vl, g_vl);
    cudaGetSymbolAddress((void**)&Qh, g_Qh);  cudaGetSymbolAddress((void**)&Ql, g_Ql);
    cudaGetSymbolAddress((void**)&Kh, g_Kh);  cudaGetSymbolAddress((void**)&Kl, g_Kl);
    cudaGetSymbolAddress((void**)&Vh, g_Vh);  cudaGetSymbolAddress((void**)&Vl, g_Vl);
    cudaGetSymbolAddress((void**)&Oh, g_Oh);  cudaGetSymbolAddress((void**)&Ol, g_Ol);
    cudaGetSymbolAddress((void**)&HSh, g_HSh); cudaGetSymbolAddress((void**)&HSl, g_HSl);
    cudaGetSymbolAddress((void**)&Wth, g_Wth); cudaGetSymbolAddress((void**)&Wtl, g_Wtl);

    cudaFuncSetAttribute(attn_mma,
                         cudaFuncAttributeMaxDynamicSharedMemorySize, AT_SMEM);
    cudaFuncSetAttribute(gemm_bf16,
                         cudaFuncAttributeMaxDynamicSharedMemorySize, SMEM_GEMM);

    const size_t WSZ = (size_t)PD * PD;

    wprep<<<dim3(16, 16, 5), 256>>>(Wq, Wk, Wv, Wfc, Ws2, Wth, Wtl);
    split3<<<dim3(4096, 1, 3), 256>>>(q, k, v, qh, ql, kh, kl, vh, vl);
    film_prep<<<dim3(8, PB), 128>>>(latent, Ws1, bs1, gSS);

    // QKV projections -> bf16 split outputs only
    gemm_bf16<<<dim3(4, 64, 3), 256, SMEM_GEMM>>>(
        qh, ql, kh, kl, vh, vl,
        Wth, Wtl, Wth + WSZ, Wtl + WSZ, Wth + 2*WSZ, Wtl + 2*WSZ,
        bq, bk, bv,
        nullptr, nullptr, nullptr,
        Qh, Ql, Kh, Kl, Vh, Vl);

    attn_mma<<<dim3(PL / 32, PH, PB), 256, AT_SMEM>>>(
        Qh, Ql, Kh, Kl, Vh, Vl, attn, Oh, Ol);

    // FC -> fp32
    gemm_bf16<<<dim3(4, 64, 1), 256, SMEM_GEMM>>>(
        Oh, Ol, Oh, Ol, Oh, Ol,
        Wth + 3*WSZ, Wtl + 3*WSZ, Wth + 3*WSZ, Wtl + 3*WSZ, Wth + 3*WSZ, Wtl + 3*WSZ,
        bfc, bfc, bfc, gOFC, gOFC, gOFC,
        nullptr, nullptr, nullptr, nullptr, nullptr, nullptr);

    film_apply<<<BLD, 128>>>(gOFC, gSS, en_g, en_b, HSh, HSl);

    // S2 -> fp32
    gemm_bf16<<<dim3(4, 64, 1), 256, SMEM_GEMM>>>(
        HSh, HSl, HSh, HSl, HSh, HSl,
        Wth + 4*WSZ, Wtl + 4*WSZ, Wth + 4*WSZ, Wtl + 4*WSZ, Wth + 4*WSZ, Wtl + 4*WSZ,
        bs2, bs2, bs2, gH2, gH2, gH2,
        nullptr, nullptr, nullptr, nullptr, nullptr, nullptr);

    final_ln<<<BLD, 128>>>(gH2, q, ln_g, ln_b, out);
}

// round 15
// speedup vs baseline: 3.6553x; 1.0008x over previous
#include <cuda_runtime.h>
#include <cuda_bf16.h>
#include <cstddef>
#include <cstdint>

// Problem constants
#define PB 8
#define PL 1024
#define PD 512
#define PH 8
#define BLD (PB*PL)            // 8192 rows

// ------------------------- scratch (device globals) -------------------------
__device__ float g_OFC[BLD*PD];
__device__ float g_H2 [BLD*PD];
__device__ float g_SS [PB*2*PD];

// bf16 split operands
__device__ __nv_bfloat16 g_qh[BLD*PD], g_ql[BLD*PD];   // raw inputs q/k/v
__device__ __nv_bfloat16 g_kh[BLD*PD], g_kl[BLD*PD];
__device__ __nv_bfloat16 g_vh[BLD*PD], g_vl[BLD*PD];
__device__ __nv_bfloat16 g_Qh[BLD*PD], g_Ql[BLD*PD];   // projected Q/K/V
__device__ __nv_bfloat16 g_Kh[BLD*PD], g_Kl[BLD*PD];
__device__ __nv_bfloat16 g_Vh[BLD*PD], g_Vl[BLD*PD];
__device__ __nv_bfloat16 g_Oh[BLD*PD], g_Ol[BLD*PD];   // attention output
__device__ __nv_bfloat16 g_HSh[BLD*PD], g_HSl[BLD*PD]; // FiLM output
// 5 transposed+split weights: [n][k] layout, 512*512 each
__device__ __nv_bfloat16 g_Wth[5*PD*PD], g_Wtl[5*PD*PD];

// ------------------------- helpers ------------------------------------------
static __device__ __forceinline__ uint32_t stoa(const void* p) {
    uint32_t a;
    asm("{ .reg .u64 t; cvta.to.shared.u64 t, %1; cvt.u32.u64 %0, t; }"
        : "=r"(a) : "l"(p));
    return a;
}
static __device__ __forceinline__ void bsplit(float x, ushort& h, ushort& l) {
    __nv_bfloat16 hb = __float2bfloat16_rn(x);
    h = __bfloat16_as_ushort(hb);
    float r = x - __bfloat162float(hb);
    l = __bfloat16_as_ushort(__float2bfloat16_rn(r));
}

#define LDSM4(r, addr) \
    asm volatile("ldmatrix.sync.aligned.m8n8.x4.shared.b16 {%0,%1,%2,%3}, [%4];" \
        : "=r"((r)[0]),"=r"((r)[1]),"=r"((r)[2]),"=r"((r)[3]) : "r"(addr))

#define LDSMT4(r, addr) \
    asm volatile("ldmatrix.sync.aligned.m8n8.x4.trans.shared.b16 {%0,%1,%2,%3}, [%4];" \
        : "=r"((r)[0]),"=r"((r)[1]),"=r"((r)[2]),"=r"((r)[3]) : "r"(addr))

#define MMABF16(d, a, b0, b1) \
    asm volatile("mma.sync.aligned.m16n8k16.row.col.f32.bf16.bf16.f32 " \
        "{%0,%1,%2,%3}, {%4,%5,%6,%7}, {%8,%9}, {%0,%1,%2,%3};" \
        : "+f"((d)[0]),"+f"((d)[1]),"+f"((d)[2]),"+f"((d)[3]) \
        : "r"((a)[0]),"r"((a)[1]),"r"((a)[2]),"r"((a)[3]), "r"(b0),"r"(b1))

#define CPA16(dst, src) \
    asm volatile("cp.async.ca.shared.global [%0], [%1], 16;" :: "r"(dst), "l"(src))
#define CPCOMMIT() asm volatile("cp.async.commit_group;" ::: "memory")
#define CPWAIT0()  asm volatile("cp.async.wait_group 0;"  ::: "memory")
#define CPWAIT1()  asm volatile("cp.async.wait_group 1;"  ::: "memory")

// ==================== weight prep: W[k][n] -> Wt[n][k] hi/lo =================
__global__ __launch_bounds__(256)
void wprep(const float* __restrict__ W0, const float* __restrict__ W1,
           const float* __restrict__ W2, const float* __restrict__ W3,
           const float* __restrict__ W4,
           __nv_bfloat16* __restrict__ Wth, __nv_bfloat16* __restrict__ Wtl) {
    const int z = blockIdx.z;
    const float* W = z == 0 ? W0 : z == 1 ? W1 : z == 2 ? W2 : z == 3 ? W3 : W4;
    __nv_bfloat16* oh = Wth + (size_t)z * PD * PD;
    __nv_bfloat16* ol = Wtl + (size_t)z * PD * PD;
    __shared__ float tile[32][33];
    const int k0 = blockIdx.x * 32, n0 = blockIdx.y * 32;
    const int tx = threadIdx.x & 31, ty = threadIdx.x >> 5;
    #pragma unroll
    for (int i = 0; i < 4; i++)
        tile[ty + 8 * i][tx] = W[(size_t)(k0 + ty + 8 * i) * PD + n0 + tx];
    __syncthreads();
    #pragma unroll
    for (int i = 0; i < 4; i++) {
        int n = n0 + ty + 8 * i, k = k0 + tx;
        ushort h, l;
        bsplit(tile[tx][ty + 8 * i], h, l);
        oh[(size_t)n * PD + k] = __ushort_as_bfloat16(h);
        ol[(size_t)n * PD + k] = __ushort_as_bfloat16(l);
    }
}

// ==================== split q/k/v fp32 -> bf16 hi/lo =========================
__global__ __launch_bounds__(256)
void split3(const float* __restrict__ x0, const float* __restrict__ x1,
            const float* __restrict__ x2,
            __nv_bfloat16* __restrict__ h0, __nv_bfloat16* __restrict__ l0,
            __nv_bfloat16* __restrict__ h1, __nv_bfloat16* __restrict__ l1,
            __nv_bfloat16* __restrict__ h2, __nv_bfloat16* __restrict__ l2) {
    const int z = blockIdx.z;
    const float* in = z == 0 ? x0 : z == 1 ? x1 : x2;
    __nv_bfloat16* oh = z == 0 ? h0 : z == 1 ? h1 : h2;
    __nv_bfloat16* ol = z == 0 ? l0 : z == 1 ? l1 : l2;
    size_t i = ((size_t)blockIdx.x * 256 + threadIdx.x) * 4;
    float4 f = *(const float4*)&in[i];
    ushort h[4], l[4];
    bsplit(f.x, h[0], l[0]); bsplit(f.y, h[1], l[1]);
    bsplit(f.z, h[2], l[2]); bsplit(f.w, h[3], l[3]);
    uint2 hv = make_uint2((uint32_t)h[0] | ((uint32_t)h[1] << 16),
                          (uint32_t)h[2] | ((uint32_t)h[3] << 16));
    uint2 lv = make_uint2((uint32_t)l[0] | ((uint32_t)l[1] << 16),
                          (uint32_t)l[2] | ((uint32_t)l[3] << 16));
    *(uint2*)&oh[i] = hv;
    *(uint2*)&ol[i] = lv;
}

// ==================== bf16-split mma.sync GEMM ===============================
#define GS_ROW 40
#define GS_ARR (128*GS_ROW)                 // 5120 halves
#define GS_BUF (4*GS_ARR)                   // 20480 halves
#define SMEM_GEMM (2*GS_BUF*2)              // 81920 bytes

__global__ __launch_bounds__(256, 2)
void gemm_bf16(const __nv_bfloat16* __restrict__ Ah0, const __nv_bfloat16* __restrict__ Al0,
               const __nv_bfloat16* __restrict__ Ah1, const __nv_bfloat16* __restrict__ Al1,
               const __nv_bfloat16* __restrict__ Ah2, const __nv_bfloat16* __restrict__ Al2,
               const __nv_bfloat16* __restrict__ Bh0, const __nv_bfloat16* __restrict__ Bl0,
               const __nv_bfloat16* __restrict__ Bh1, const __nv_bfloat16* __restrict__ Bl1,
               const __nv_bfloat16* __restrict__ Bh2, const __nv_bfloat16* __restrict__ Bl2,
               const float* __restrict__ bias0, const float* __restrict__ bias1,
               const float* __restrict__ bias2,
               float* __restrict__ C0, float* __restrict__ C1, float* __restrict__ C2,
               __nv_bfloat16* __restrict__ Sh0, __nv_bfloat16* __restrict__ Sl0,
               __nv_bfloat16* __restrict__ Sh1, __nv_bfloat16* __restrict__ Sl1,
               __nv_bfloat16* __restrict__ Sh2, __nv_bfloat16* __restrict__ Sl2) {
    extern __shared__ __nv_bfloat16 hsm[];
    const int z = blockIdx.z;
    const __nv_bfloat16* Ah = z == 0 ? Ah0 : z == 1 ? Ah1 : Ah2;
    const __nv_bfloat16* Al = z == 0 ? Al0 : z == 1 ? Al1 : Al2;
    const __nv_bfloat16* Bh = z == 0 ? Bh0 : z == 1 ? Bh1 : Bh2;
    const __nv_bfloat16* Bl = z == 0 ? Bl0 : z == 1 ? Bl1 : Bl2;
    const float* bias = z == 0 ? bias0 : z == 1 ? bias1 : bias2;
    float* C          = z == 0 ? C0 : z == 1 ? C1 : C2;
    __nv_bfloat16* Sh = z == 0 ? Sh0 : z == 1 ? Sh1 : Sh2;
    __nv_bfloat16* Sl = z == 0 ? Sl0 : z == 1 ? Sl1 : Sl2;

    const int cb0 = blockIdx.x * 128;
    const int rb0 = blockIdx.y * 128;
    const int t = threadIdx.x;
    const int wid = t >> 5, lane = t & 31;
    const int wm = wid & 1, wn = wid >> 1;
    const uint32_t sb = stoa(hsm);

    const int srow = t >> 1, sh16 = (t & 1) * 16;
    const size_t aoff = (size_t)(rb0 + srow) * PD + sh16;
    const size_t boff = (size_t)(cb0 + srow) * PD + sh16;
    const uint32_t sdst = (uint32_t)(srow * GS_ROW + sh16) * 2;

    float d[4][4][4];
    #pragma unroll
    for (int i = 0; i < 4; i++)
        #pragma unroll
        for (int j = 0; j < 4; j++)
            #pragma unroll
            for (int r = 0; r < 4; r++) d[i][j][r] = 0.f;

    auto stage = [&](int c, int buf) {
        const uint32_t base = sb + (uint32_t)buf * GS_BUF * 2 + sdst;
        const __nv_bfloat16* s;
        s = Ah + aoff + c * 32;
        CPA16(base,                  s); CPA16(base + 16,                  s + 8);
        s = Al + aoff + c * 32;
        CPA16(base + GS_ARR*2,       s); CPA16(base + GS_ARR*2 + 16,       s + 8);
        s = Bh + boff + c * 32;
        CPA16(base + 2*GS_ARR*2,     s); CPA16(base + 2*GS_ARR*2 + 16,     s + 8);
        s = Bl + boff + c * 32;
        CPA16(base + 3*GS_ARR*2,     s); CPA16(base + 3*GS_ARR*2 + 16,     s + 8);
    };

    const uint32_t lro = (uint32_t)((lane & 15) * GS_ROW + (lane >> 4) * 8) * 2;

    stage(0, 0);
    CPCOMMIT();
    for (int c = 0; c < 16; c++) {
        CPWAIT0();
        __syncthreads();
        if (c < 15) { stage(c + 1, (c + 1) & 1); CPCOMMIT(); }
        const uint32_t ab = sb + (uint32_t)(c & 1) * GS_BUF * 2;
        const uint32_t bbh = ab + 2 * GS_ARR * 2;
        #pragma unroll
        for (int ks = 0; ks < 2; ks++) {
            uint32_t bh[4][2], bl[4][2];
            #pragma unroll
            for (int j2 = 0; j2 < 2; j2++) {
                uint32_t tb[4];
                uint32_t ba = bbh + (uint32_t)((wn*32 + j2*16) * GS_ROW + ks*16) * 2 + lro;
                LDSM4(tb, ba);
                bh[j2*2][0] = tb[0]; bh[j2*2][1] = tb[2];
                bh[j2*2+1][0] = tb[1]; bh[j2*2+1][1] = tb[3];
                LDSM4(tb, ba + GS_ARR*2);
                bl[j2*2][0] = tb[0]; bl[j2*2][1] = tb[2];
                bl[j2*2+1][0] = tb[1]; bl[j2*2+1][1] = tb[3];
            }
            #pragma unroll
            for (int mi = 0; mi < 4; mi++) {
                uint32_t ah[4], al[4];
                uint32_t aa = ab + (uint32_t)((wm*64 + mi*16) * GS_ROW + ks*16) * 2 + lro;
                LDSM4(ah, aa);
                LDSM4(al, aa + GS_ARR*2);
                #pragma unroll
                for (int nj = 0; nj < 4; nj++) {
                    MMABF16(d[mi][nj], ah, bh[nj][0], bh[nj][1]);
                    MMABF16(d[mi][nj], ah, bl[nj][0], bl[nj][1]);
                    MMABF16(d[mi][nj], al, bh[nj][0], bh[nj][1]);
                }
            }
        }
    }

    const int g = lane >> 2, tq = lane & 3;
    #pragma unroll
    for (int mi = 0; mi < 4; mi++) {
        const int row = rb0 + wm*64 + mi*16 + g;
        #pragma unroll
        for (int nj = 0; nj < 4; nj++) {
            const int col = cb0 + wn*32 + nj*8 + tq*2;
            float2 bv = *(const float2*)&bias[col];
            float o0 = d[mi][nj][0] + bv.x, o1 = d[mi][nj][1] + bv.y;
            float o2 = d[mi][nj][2] + bv.x, o3 = d[mi][nj][3] + bv.y;
            if (C) {
                *(float2*)&C[(size_t)row * PD + col]       = make_float2(o0, o1);
                *(float2*)&C[(size_t)(row + 8) * PD + col] = make_float2(o2, o3);
            }
            if (Sh) {
                ushort h0,l0,h1,l1,h2,l2,h3,l3;
                bsplit(o0,h0,l0); bsplit(o1,h1,l1);
                bsplit(o2,h2,l2); bsplit(o3,h3,l3);
                *(uint32_t*)&Sh[(size_t)row * PD + col]       = (uint32_t)h0 | ((uint32_t)h1 << 16);
                *(uint32_t*)&Sl[(size_t)row * PD + col]       = (uint32_t)l0 | ((uint32_t)l1 << 16);
                *(uint32_t*)&Sh[(size_t)(row + 8) * PD + col] = (uint32_t)h2 | ((uint32_t)h3 << 16);
                *(uint32_t*)&Sl[(size_t)(row + 8) * PD + col] = (uint32_t)l2 | ((uint32_t)l3 << 16);
            }
        }
    }
}

// ------------------------- FiLM scale/shift prep ----------------------------
__global__ __launch_bounds__(128)
void film_prep(const float* __restrict__ latent, const float* __restrict__ Ws1,
               const float* __restrict__ bs1, float* __restrict__ ss) {
    const int b = blockIdx.y;
    const int col = blockIdx.x * 128 + threadIdx.x;
    __shared__ float ls[512];
    for (int i = threadIdx.x; i < 512; i += 128) {
        float x = latent[(size_t)b * 512 + i];
        ls[i] = x / (1.f + __expf(-x));
    }
    __syncthreads();
    float sum = 0.f;
    #pragma unroll 8
    for (int k = 0; k < 512; k++) sum += ls[k] * Ws1[(size_t)k * 1024 + col];
    ss[(size_t)b * 1024 + col] = sum + bs1[col];
}

// ------------------------- block reduce helper ------------------------------
__device__ __forceinline__ float2 blockReduceSum2(float s1, float s2) {
    __shared__ float sh[8];
    #pragma unroll
    for (int off = 16; off; off >>= 1) {
        s1 += __shfl_xor_sync(0xffffffffu, s1, off);
        s2 += __shfl_xor_sync(0xffffffffu, s2, off);
    }
    const int w = threadIdx.x >> 5;
    if ((threadIdx.x & 31) == 0) { sh[w * 2] = s1; sh[w * 2 + 1] = s2; }
    __syncthreads();
    float a = 0.f, b = 0.f;
    const int nw = blockDim.x >> 5;
    for (int i = 0; i < nw; i++) { a += sh[i * 2]; b += sh[i * 2 + 1]; }
    return make_float2(a, b);
}

// --------- FiLM apply: LN -> FiLM -> SiLU, fused bf16 split output ----------
__global__ __launch_bounds__(128)
void film_apply(const float* __restrict__ ofc, const float* __restrict__ ss,
                const float* __restrict__ g, const float* __restrict__ be,
                __nv_bfloat16* __restrict__ hsh, __nv_bfloat16* __restrict__ hsl) {
    const int row = blockIdx.x;
    const int b = row >> 10;
    const int t = threadIdx.x;
    const float* xr = ofc + (size_t)row * 512;
    float x[4]; float s1 = 0.f, s2 = 0.f;
    #pragma unroll
    for (int i = 0; i < 4; i++) {
        x[i] = xr[t + i * 128];
        s1 += x[i]; s2 += x[i] * x[i];
    }
    float2 r = blockReduceSum2(s1, s2);
    const float mean = r.x * (1.f / 512.f);
    const float var  = r.y * (1.f / 512.f) - mean * mean;
    const float rstd = rsqrtf(var + 1e-5f);
    const float* ssb = ss + (size_t)b * 1024;
    #pragma unroll
    for (int i = 0; i < 4; i++) {
        const int c = t + i * 128;
        float ln = (x[i] - mean) * rstd * g[c] + be[c];
        float h = ln * (1.f + ssb[c]) + ssb[512 + c];
        h = h / (1.f + __expf(-h));
        ushort hh, ll;
        bsplit(h, hh, ll);
        hsh[(size_t)row * 512 + c] = __ushort_as_bfloat16(hh);
        hsl[(size_t)row * 512 + c] = __ushort_as_bfloat16(ll);
    }
}

// ------------------------- final: LN(h2 + residual) -------------------------
__global__ __launch_bounds__(128)
void final_ln(const float* __restrict__ h2, const float* __restrict__ resid,
              const float* __restrict__ g, const float* __restrict__ be,
              float* __restrict__ out) {
    const int row = blockIdx.x;
    const int t = threadIdx.x;
    const float* hr = h2 + (size_t)row * 512;
    const float* rr = resid + (size_t)row * 512;
    float x[4]; float s1 = 0.f, s2 = 0.f;
    #pragma unroll
    for (int i = 0; i < 4; i++) {
        x[i] = hr[t + i * 128] + rr[t + i * 128];
        s1 += x[i]; s2 += x[i] * x[i];
    }
    float2 r = blockReduceSum2(s1, s2);
    const float mean = r.x * (1.f / 512.f);
    const float var  = r.y * (1.f / 512.f) - mean * mean;
    const float rstd = rsqrtf(var + 1e-6f);
    float* orow = out + (size_t)row * 512;
    #pragma unroll
    for (int i = 0; i < 4; i++) {
        const int c = t + i * 128;
        orow[c] = (x[i] - mean) * rstd * g[c] + be[c];
    }
}

// ============ tensorized attention, register-resident S (FA-style) ==========
// One CTA per (b, h, 32 q rows). S (exp'd, unnormalized) stays in registers
// end-to-end. Phase 3 materializes P just-in-time per V-chunk: normalize ->
// write attn columns -> bsplit into transient fragments -> PV MMAs. This
// keeps peak live registers ~240 (no spills) and overlaps the attn STG
// traffic with tensor work.
#define AT_QHO 0u
#define AT_QLO 4608u
#define AT_KV  10240u
#define AT_KVB 36864u
#define AT_SPL 18432u
#define AT_SMEM (10240 + 4*36864)

__global__ __launch_bounds__(256, 1)
void attn_mma(const __nv_bfloat16* __restrict__ Qh, const __nv_bfloat16* __restrict__ Ql,
              const __nv_bfloat16* __restrict__ Kh, const __nv_bfloat16* __restrict__ Kl,
              const __nv_bfloat16* __restrict__ Vh, const __nv_bfloat16* __restrict__ Vl,
              float* __restrict__ attn,
              __nv_bfloat16* __restrict__ Oh, __nv_bfloat16* __restrict__ Ol) {
    extern __shared__ char smem[];
    const uint32_t sb = stoa(smem);

    const int b = blockIdx.z, h = blockIdx.y;
    const int q0 = blockIdx.x * 32;
    const int t = threadIdx.x;
    const int w = t >> 5, lane = t & 31;
    const int g = lane >> 2, tq = lane & 3;

    // ---- stage Q (32 rows x 128B x hi/lo)
    {
        int row = t >> 3, seg = t & 7;
        size_t src = (size_t)(b * 1024 + q0 + row) * 512 + h * 64 + seg * 8;
        CPA16(sb + AT_QHO + row * 144 + seg * 16, Qh + src);
        CPA16(sb + AT_QLO + row * 144 + seg * 16, Ql + src);
    }
    auto stageKV = [&](const __nv_bfloat16* Xh, const __nv_bfloat16* Xl, int c, int buf) {
        int row = t >> 1, hf = t & 1;
        size_t src = (size_t)(b * 1024 + c * 128 + row) * 512 + h * 64 + hf * 32;
        uint32_t dst = sb + AT_KV + (uint32_t)buf * AT_KVB + row * 144 + hf * 64;
        #pragma unroll
        for (int i = 0; i < 4; i++) {
            CPA16(dst + i * 16,          Xh + src + i * 8);
            CPA16(dst + AT_SPL + i * 16, Xl + src + i * 8);
        }
    };

    stageKV(Kh, Kl, 0, 0);   // group 0: Q + K0
    CPCOMMIT();
    stageKV(Kh, Kl, 1, 1);   // group 1: K1
    CPCOMMIT();
    CPWAIT1();               // Q + K0 ready
    __syncthreads();

    // ---- preload Q fragments: [split][mi][ks][4]
    uint32_t qa[2][2][4][4];
    #pragma unroll
    for (int s = 0; s < 2; s++)
        #pragma unroll
        for (int mi = 0; mi < 2; mi++)
            #pragma unroll
            for (int ks = 0; ks < 4; ks++) {
                uint32_t a = sb + (s ? AT_QLO : AT_QHO)
                           + (mi * 16 + (lane & 15)) * 144 + ks * 32 + (lane >> 4) * 16;
                LDSM4(qa[s][mi][ks], a);
            }

    // ---- Phase 1: S = Q K^T, all chunks, accumulators stay in registers ----
    float acc[8][2][2][4];
    #pragma unroll
    for (int c = 0; c < 8; c++)
        #pragma unroll
        for (int mi = 0; mi < 2; mi++)
            #pragma unroll
            for (int nj = 0; nj < 2; nj++)
                #pragma unroll
                for (int r = 0; r < 4; r++) acc[c][mi][nj][r] = 0.f;

    #pragma unroll
    for (int c = 0; c < 8; c++) {
        if (c > 0) {
            if (c < 7) { CPWAIT1(); } else { CPWAIT0(); }
            __syncthreads();
        }
        if (c + 2 < 8) { stageKV(Kh, Kl, c + 2, (c + 2) & 3); CPCOMMIT(); }
        const uint32_t kb = sb + AT_KV + (uint32_t)(c & 3) * AT_KVB;
        #pragma unroll
        for (int ks = 0; ks < 4; ks++) {
            uint32_t kh4[4], kl4[4];
            uint32_t ka = kb + (w * 16 + (lane & 15)) * 144 + ks * 32 + (lane >> 4) * 16;
            LDSM4(kh4, ka);
            LDSM4(kl4, ka + AT_SPL);
            #pragma unroll
            for (int mi = 0; mi < 2; mi++) {
                MMABF16(acc[c][mi][0], qa[0][mi][ks], kh4[0], kh4[2]);
                MMABF16(acc[c][mi][1], qa[0][mi][ks], kh4[1], kh4[3]);
                MMABF16(acc[c][mi][0], qa[0][mi][ks], kl4[0], kl4[2]);
                MMABF16(acc[c][mi][1], qa[0][mi][ks], kl4[1], kl4[3]);
                MMABF16(acc[c][mi][0], qa[1][mi][ks], kh4[0], kh4[2]);
                MMABF16(acc[c][mi][1], qa[1][mi][ks], kh4[1], kh4[3]);
            }
        }
    }

    // prefetch V chunks 0,1 while softmax runs (bufs 0,1 last read at c=4,5)
    stageKV(Vh, Vl, 0, 0); CPCOMMIT();
    stageKV(Vh, Vl, 1, 1); CPCOMMIT();

    // ---- Phase 2: in-register softmax stats; row stats via smem [32][8] ----
    float* red = (float*)smem;       // max at [0,256), sum at [256,512)
    float mxv[2][2], inv[2][2];
    #pragma unroll
    for (int mi = 0; mi < 2; mi++)
        #pragma unroll
        for (int hf = 0; hf < 2; hf++) {
            float m = -1e30f;
            #pragma unroll
            for (int c = 0; c < 8; c++)
                #pragma unroll
                for (int nj = 0; nj < 2; nj++)
                    m = fmaxf(m, fmaxf(acc[c][mi][nj][hf*2], acc[c][mi][nj][hf*2+1]));
            m = fmaxf(m, __shfl_xor_sync(0xffffffffu, m, 1));
            m = fmaxf(m, __shfl_xor_sync(0xffffffffu, m, 2));
            if (tq == 0) red[(mi*16 + hf*8 + g) * 8 + w] = m;
        }
    __syncthreads();
    #pragma unroll
    for (int mi = 0; mi < 2; mi++)
        #pragma unroll
        for (int hf = 0; hf < 2; hf++) {
            const int row = mi*16 + hf*8 + g;
            float m = red[row*8];
            #pragma unroll
            for (int ww = 1; ww < 8; ww++) m = fmaxf(m, red[row*8 + ww]);
            mxv[mi][hf] = m;
        }
    #pragma unroll
    for (int mi = 0; mi < 2; mi++)
        #pragma unroll
        for (int hf = 0; hf < 2; hf++) {
            float s = 0.f;
            #pragma unroll
            for (int c = 0; c < 8; c++)
                #pragma unroll
                for (int nj = 0; nj < 2; nj++)
                    #pragma unroll
                    for (int kk = 0; kk < 2; kk++) {
                        float& v = acc[c][mi][nj][hf*2 + kk];
                        v = __expf((v - mxv[mi][hf]) * 0.125f);
                        s += v;
                    }
            s += __shfl_xor_sync(0xffffffffu, s, 1);
            s += __shfl_xor_sync(0xffffffffu, s, 2);
            if (tq == 0) red[256 + (mi*16 + hf*8 + g) * 8 + w] = s;
        }
    __syncthreads();
    #pragma unroll
    for (int mi = 0; mi < 2; mi++)
        #pragma unroll
        for (int hf = 0; hf < 2; hf++) {
            const int row = mi*16 + hf*8 + g;
            float s = 0.f;
            #pragma unroll
            for (int ww = 0; ww < 8; ww++) s += red[256 + row*8 + ww];
            inv[mi][hf] = 1.f / s;
        }

    // ---- Phase 3: per V-chunk JIT — normalize acc[c], write attn, pack P,
    //      then PV MMAs. P fragments are transient (32 regs), acc[c] dies
    //      incrementally, STG overlaps tensor work.
    float oacc[2][8][4];
    #pragma unroll
    for (int mi = 0; mi < 2; mi++)
        #pragma unroll
        for (int nj = 0; nj < 8; nj++)
            #pragma unroll
            for (int r = 0; r < 4; r++) oacc[mi][nj][r] = 0.f;

    float* attn_b = attn + (((size_t)(b * 8 + h)) * 1024 + q0) * 1024;

    CPWAIT1();               // V0 ready
    __syncthreads();
    #pragma unroll
    for (int c = 0; c < 8; c++) {
        if (c > 0) {
            if (c < 7) { CPWAIT1(); } else { CPWAIT0(); }
            __syncthreads();
        }
        if (c + 2 < 8) { stageKV(Vh, Vl, c + 2, (c + 2) & 3); CPCOMMIT(); }

        // JIT P materialization for this chunk
        uint32_t pah[2][4], pal[2][4];
        #pragma unroll
        for (int mi = 0; mi < 2; mi++) {
            const int row0 = mi * 16 + g;
            const int col = c * 128 + w * 16 + tq * 2;
            float p00 = acc[c][mi][0][0] * inv[mi][0];
            float p01 = acc[c][mi][0][1] * inv[mi][0];
            float p02 = acc[c][mi][0][2] * inv[mi][1];
            float p03 = acc[c][mi][0][3] * inv[mi][1];
            float p10 = acc[c][mi][1][0] * inv[mi][0];
            float p11 = acc[c][mi][1][1] * inv[mi][0];
            float p12 = acc[c][mi][1][2] * inv[mi][1];
            float p13 = acc[c][mi][1][3] * inv[mi][1];
            *(float2*)&attn_b[(size_t)row0 * 1024 + col]           = make_float2(p00, p01);
            *(float2*)&attn_b[(size_t)(row0 + 8) * 1024 + col]     = make_float2(p02, p03);
            *(float2*)&attn_b[(size_t)row0 * 1024 + col + 8]       = make_float2(p10, p11);
            *(float2*)&attn_b[(size_t)(row0 + 8) * 1024 + col + 8] = make_float2(p12, p13);
            ushort h00,l00,h01,l01,h02,l02,h03,l03;
            ushort h10,l10,h11,l11,h12,l12,h13,l13;
            bsplit(p00,h00,l00); bsplit(p01,h01,l01);
            bsplit(p02,h02,l02); bsplit(p03,h03,l03);
            bsplit(p10,h10,l10); bsplit(p11,h11,l11);
            bsplit(p12,h12,l12); bsplit(p13,h13,l13);
            pah[mi][0] = (uint32_t)h00 | ((uint32_t)h01 << 16);
            pah[mi][1] = (uint32_t)h02 | ((uint32_t)h03 << 16);
            pah[mi][2] = (uint32_t)h10 | ((uint32_t)h11 << 16);
            pah[mi][3] = (uint32_t)h12 | ((uint32_t)h13 << 16);
            pal[mi][0] = (uint32_t)l00 | ((uint32_t)l01 << 16);
            pal[mi][1] = (uint32_t)l02 | ((uint32_t)l03 << 16);
            pal[mi][2] = (uint32_t)l10 | ((uint32_t)l11 << 16);
            pal[mi][3] = (uint32_t)l12 | ((uint32_t)l13 << 16);
        }

        const uint32_t vb = sb + AT_KV + (uint32_t)(c & 3) * AT_KVB;
        #pragma unroll
        for (int dd = 0; dd < 4; dd++) {
            uint32_t vbh[4], vbl[4];
            uint32_t va = vb + (w * 16 + (lane & 15)) * 144 + dd * 32 + (lane >> 4) * 16;
            LDSMT4(vbh, va);
            LDSMT4(vbl, va + AT_SPL);
            #pragma unroll
            for (int mi = 0; mi < 2; mi++) {
                MMABF16(oacc[mi][dd*2],   pah[mi], vbh[0], vbh[1]);
                MMABF16(oacc[mi][dd*2+1], pah[mi], vbh[2], vbh[3]);
                MMABF16(oacc[mi][dd*2],   pah[mi], vbl[0], vbl[1]);
                MMABF16(oacc[mi][dd*2+1], pah[mi], vbl[2], vbl[3]);
                MMABF16(oacc[mi][dd*2],   pal[mi], vbh[0], vbh[1]);
                MMABF16(oacc[mi][dd*2+1], pal[mi], vbh[2], vbh[3]);
            }
        }
    }
    __syncthreads();   // all warps done with V buffers before scratch reuse

    // ---- cross-warp O reduction in smem (reuse KV region) ----
    float* scr = (float*)(smem + AT_KV);
    #pragma unroll
    for (int mi = 0; mi < 2; mi++) {
        const int q = mi * 16 + g;
        #pragma unroll
        for (int nj = 0; nj < 8; nj++) {
            const int d = nj * 8 + tq * 2;
            *(float2*)&scr[w * 2048 + q * 64 + d] =
                make_float2(oacc[mi][nj][0], oacc[mi][nj][1]);
            *(float2*)&scr[w * 2048 + (q + 8) * 64 + d] =
                make_float2(oacc[mi][nj][2], oacc[mi][nj][3]);
        }
    }
    __syncthreads();
    {
        const int base = t * 8;
        const int q = base >> 6, d = base & 63;
        float r8[8];
        #pragma unroll
        for (int j = 0; j < 8; j++) r8[j] = 0.f;
        #pragma unroll
        for (int ww = 0; ww < 8; ww++) {
            float4 a = *(float4*)&scr[ww * 2048 + base];
            float4 c = *(float4*)&scr[ww * 2048 + base + 4];
            r8[0] += a.x; r8[1] += a.y; r8[2] += a.z; r8[3] += a.w;
            r8[4] += c.x; r8[5] += c.y; r8[6] += c.z; r8[7] += c.w;
        }
        ushort hh[8], ll[8];
        #pragma unroll
        for (int j = 0; j < 8; j++) bsplit(r8[j], hh[j], ll[j]);
        uint4 hv, lv;
        hv.x = (uint32_t)hh[0] | ((uint32_t)hh[1] << 16);
        hv.y = (uint32_t)hh[2] | ((uint32_t)hh[3] << 16);
        hv.z = (uint32_t)hh[4] | ((uint32_t)hh[5] << 16);
        hv.w = (uint32_t)hh[6] | ((uint32_t)hh[7] << 16);
        lv.x = (uint32_t)ll[0] | ((uint32_t)ll[1] << 16);
        lv.y = (uint32_t)ll[2] | ((uint32_t)ll[3] << 16);
        lv.z = (uint32_t)ll[4] | ((uint32_t)ll[5] << 16);
        lv.w = (uint32_t)ll[6] | ((uint32_t)ll[7] << 16);
        const size_t orow = (size_t)(b * 1024 + q0 + q) * 512 + h * 64 + d;
        *(uint4*)&Oh[orow] = hv;
        *(uint4*)&Ol[orow] = lv;
    }
}

// ------------------------- launch -------------------------------------------
extern "C" void kernel_launch(void* const* d_in, const int* in_sizes, int n_in,
                              void* d_out, int out_size) {
    const float* q      = (const float*)d_in[0];
    const float* k      = (const float*)d_in[1];
    const float* v      = (const float*)d_in[2];
    const float* latent = (const float*)d_in[3];
    const float* Wq     = (const float*)d_in[4];
    const float* bq     = (const float*)d_in[5];
    const float* Wk     = (const float*)d_in[6];
    const float* bk     = (const float*)d_in[7];
    const float* Wv     = (const float*)d_in[8];
    const float* bv     = (const float*)d_in[9];
    const float* Wfc    = (const float*)d_in[10];
    const float* bfc    = (const float*)d_in[11];
    const float* Ws1    = (const float*)d_in[12];
    const float* bs1    = (const float*)d_in[13];
    const float* Ws2    = (const float*)d_in[14];
    const float* bs2    = (const float*)d_in[15];
    const float* en_g   = (const float*)d_in[16];
    const float* en_b   = (const float*)d_in[17];
    const float* ln_g   = (const float*)d_in[18];
    const float* ln_b   = (const float*)d_in[19];

    float* out  = (float*)d_out;                       // [B,L,D]
    float* attn = out + (size_t)BLD * PD;              // [B,H,L,L]

    float *gOFC, *gH2, *gSS;
    cudaGetSymbolAddress((void**)&gOFC, g_OFC);
    cudaGetSymbolAddress((void**)&gH2,  g_H2);
    cudaGetSymbolAddress((void**)&gSS,  g_SS);

    __nv_bfloat16 *qh,*ql,*kh,*kl,*vh,*vl;
    __nv_bfloat16 *Qh,*Ql,*Kh,*Kl,*Vh,*Vl,*Oh,*Ol,*HSh,*HSl,*Wth,*Wtl;
    cudaGetSymbolAddress((void**)&qh, g_qh);  cudaGetSymbolAddress((void**)&ql, g_ql);
    cudaGetSymbolAddress((void**)&kh, g_kh);  cudaGetSymbolAddress((void**)&kl, g_kl);
    cudaGetSymbolAddress((void**)&vh, g_vh);  cudaGetSymbolAddress((void**)&vl, g_vl);
    cudaGetSymbolAddress((void**)&Qh, g_Qh);  cudaGetSymbolAddress((void**)&Ql, g_Ql);
    cudaGetSymbolAddress((void**)&Kh, g_Kh);  cudaGetSymbolAddress((void**)&Kl, g_Kl);
    cudaGetSymbolAddress((void**)&Vh, g_Vh);  cudaGetSymbolAddress((void**)&Vl, g_Vl);
    cudaGetSymbolAddress((void**)&Oh, g_Oh);  cudaGetSymbolAddress((void**)&Ol, g_Ol);
    cudaGetSymbolAddress((void**)&HSh, g_HSh); cudaGetSymbolAddress((void**)&HSl, g_HSl);
    cudaGetSymbolAddress((void**)&Wth, g_Wth); cudaGetSymbolAddress((void**)&Wtl, g_Wtl);

    cudaFuncSetAttribute(attn_mma,
                         cudaFuncAttributeMaxDynamicSharedMemorySize, AT_SMEM);
    cudaFuncSetAttribute(gemm_bf16,
                         cudaFuncAttributeMaxDynamicSharedMemorySize, SMEM_GEMM);

    const size_t WSZ = (size_t)PD * PD;

    wprep<<<dim3(16, 16, 5), 256>>>(Wq, Wk, Wv, Wfc, Ws2, Wth, Wtl);
    split3<<<dim3(4096, 1, 3), 256>>>(q, k, v, qh, ql, kh, kl, vh, vl);
    film_prep<<<dim3(8, PB), 128>>>(latent, Ws1, bs1, gSS);

    // QKV projections -> bf16 split outputs only
    gemm_bf16<<<dim3(4, 64, 3), 256, SMEM_GEMM>>>(
        qh, ql, kh, kl, vh, vl,
        Wth, Wtl, Wth + WSZ, Wtl + WSZ, Wth + 2*WSZ, Wtl + 2*WSZ,
        bq, bk, bv,
        nullptr, nullptr, nullptr,
        Qh, Ql, Kh, Kl, Vh, Vl);

    attn_mma<<<dim3(PL / 32, PH, PB), 256, AT_SMEM>>>(
        Qh, Ql, Kh, Kl, Vh, Vl, attn, Oh, Ol);

    // FC -> fp32
    gemm_bf16<<<dim3(4, 64, 1), 256, SMEM_GEMM>>>(
        Oh, Ol, Oh, Ol, Oh, Ol,
        Wth + 3*WSZ, Wtl + 3*WSZ, Wth + 3*WSZ, Wtl + 3*WSZ, Wth + 3*WSZ, Wtl + 3*WSZ,
        bfc, bfc, bfc, gOFC, gOFC, gOFC,
        nullptr, nullptr, nullptr, nullptr, nullptr, nullptr);

    film_apply<<<BLD, 128>>>(gOFC, gSS, en_g, en_b, HSh, HSl);

    // S2 -> fp32
    gemm_bf16<<<dim3(4, 64, 1), 256, SMEM_GEMM>>>(
        HSh, HSl, HSh, HSl, HSh, HSl,
        Wth + 4*WSZ, Wtl + 4*WSZ, Wth + 4*WSZ, Wtl + 4*WSZ, Wth + 4*WSZ, Wtl + 4*WSZ,
        bs2, bs2, bs2, gH2, gH2, gH2,
        nullptr, nullptr, nullptr, nullptr, nullptr, nullptr);

    final_ln<<<BLD, 128>>>(gH2, q, ln_g, ln_b, out);
}

// round 16
// speedup vs baseline: 3.7035x; 1.0132x over previous
#include <cuda_runtime.h>
#include <cuda_bf16.h>
#include <cstddef>
#include <cstdint>

// Problem constants
#define PB 8
#define PL 1024
#define PD 512
#define PH 8
#define BLD (PB*PL)            // 8192 rows

// ------------------------- scratch (device globals) -------------------------
__device__ float g_OFC[BLD*PD];
__device__ float g_H2 [BLD*PD];
__device__ float g_SS [PB*2*PD];

// bf16 split operands
__device__ __nv_bfloat16 g_qh[BLD*PD], g_ql[BLD*PD];   // raw inputs q/k/v
__device__ __nv_bfloat16 g_kh[BLD*PD], g_kl[BLD*PD];
__device__ __nv_bfloat16 g_vh[BLD*PD], g_vl[BLD*PD];
__device__ __nv_bfloat16 g_Qh[BLD*PD], g_Ql[BLD*PD];   // projected Q/K/V
__device__ __nv_bfloat16 g_Kh[BLD*PD], g_Kl[BLD*PD];
__device__ __nv_bfloat16 g_Vh[BLD*PD], g_Vl[BLD*PD];
__device__ __nv_bfloat16 g_Oh[BLD*PD], g_Ol[BLD*PD];   // attention output
__device__ __nv_bfloat16 g_HSh[BLD*PD], g_HSl[BLD*PD]; // FiLM output
// 5 transposed+split weights: [n][k] layout, 512*512 each
__device__ __nv_bfloat16 g_Wth[5*PD*PD], g_Wtl[5*PD*PD];

// ------------------------- helpers ------------------------------------------
static __device__ __forceinline__ uint32_t stoa(const void* p) {
    uint32_t a;
    asm("{ .reg .u64 t; cvta.to.shared.u64 t, %1; cvt.u32.u64 %0, t; }"
        : "=r"(a) : "l"(p));
    return a;
}
static __device__ __forceinline__ void bsplit(float x, ushort& h, ushort& l) {
    __nv_bfloat16 hb = __float2bfloat16_rn(x);
    h = __bfloat16_as_ushort(hb);
    float r = x - __bfloat162float(hb);
    l = __bfloat16_as_ushort(__float2bfloat16_rn(r));
}

#define LDSM4(r, addr) \
    asm volatile("ldmatrix.sync.aligned.m8n8.x4.shared.b16 {%0,%1,%2,%3}, [%4];" \
        : "=r"((r)[0]),"=r"((r)[1]),"=r"((r)[2]),"=r"((r)[3]) : "r"(addr))

#define LDSMT4(r, addr) \
    asm volatile("ldmatrix.sync.aligned.m8n8.x4.trans.shared.b16 {%0,%1,%2,%3}, [%4];" \
        : "=r"((r)[0]),"=r"((r)[1]),"=r"((r)[2]),"=r"((r)[3]) : "r"(addr))

#define MMABF16(d, a, b0, b1) \
    asm volatile("mma.sync.aligned.m16n8k16.row.col.f32.bf16.bf16.f32 " \
        "{%0,%1,%2,%3}, {%4,%5,%6,%7}, {%8,%9}, {%0,%1,%2,%3};" \
        : "+f"((d)[0]),"+f"((d)[1]),"+f"((d)[2]),"+f"((d)[3]) \
        : "r"((a)[0]),"r"((a)[1]),"r"((a)[2]),"r"((a)[3]), "r"(b0),"r"(b1))

#define CPA16(dst, src) \
    asm volatile("cp.async.ca.shared.global [%0], [%1], 16;" :: "r"(dst), "l"(src))
#define CPCOMMIT() asm volatile("cp.async.commit_group;" ::: "memory")
#define CPWAIT0()  asm volatile("cp.async.wait_group 0;"  ::: "memory")
#define CPWAIT1()  asm volatile("cp.async.wait_group 1;"  ::: "memory")

// ==================== weight prep: W[k][n] -> Wt[n][k] hi/lo =================
__global__ __launch_bounds__(256)
void wprep(const float* __restrict__ W0, const float* __restrict__ W1,
           const float* __restrict__ W2, const float* __restrict__ W3,
           const float* __restrict__ W4,
           __nv_bfloat16* __restrict__ Wth, __nv_bfloat16* __restrict__ Wtl) {
    const int z = blockIdx.z;
    const float* W = z == 0 ? W0 : z == 1 ? W1 : z == 2 ? W2 : z == 3 ? W3 : W4;
    __nv_bfloat16* oh = Wth + (size_t)z * PD * PD;
    __nv_bfloat16* ol = Wtl + (size_t)z * PD * PD;
    __shared__ float tile[32][33];
    const int k0 = blockIdx.x * 32, n0 = blockIdx.y * 32;
    const int tx = threadIdx.x & 31, ty = threadIdx.x >> 5;
    #pragma unroll
    for (int i = 0; i < 4; i++)
        tile[ty + 8 * i][tx] = W[(size_t)(k0 + ty + 8 * i) * PD + n0 + tx];
    __syncthreads();
    #pragma unroll
    for (int i = 0; i < 4; i++) {
        int n = n0 + ty + 8 * i, k = k0 + tx;
        ushort h, l;
        bsplit(tile[tx][ty + 8 * i], h, l);
        oh[(size_t)n * PD + k] = __ushort_as_bfloat16(h);
        ol[(size_t)n * PD + k] = __ushort_as_bfloat16(l);
    }
}

// ==================== split q/k/v fp32 -> bf16 hi/lo =========================
__global__ __launch_bounds__(256)
void split3(const float* __restrict__ x0, const float* __restrict__ x1,
            const float* __restrict__ x2,
            __nv_bfloat16* __restrict__ h0, __nv_bfloat16* __restrict__ l0,
            __nv_bfloat16* __restrict__ h1, __nv_bfloat16* __restrict__ l1,
            __nv_bfloat16* __restrict__ h2, __nv_bfloat16* __restrict__ l2) {
    const int z = blockIdx.z;
    const float* in = z == 0 ? x0 : z == 1 ? x1 : x2;
    __nv_bfloat16* oh = z == 0 ? h0 : z == 1 ? h1 : h2;
    __nv_bfloat16* ol = z == 0 ? l0 : z == 1 ? l1 : l2;
    size_t i = ((size_t)blockIdx.x * 256 + threadIdx.x) * 4;
    float4 f = *(const float4*)&in[i];
    ushort h[4], l[4];
    bsplit(f.x, h[0], l[0]); bsplit(f.y, h[1], l[1]);
    bsplit(f.z, h[2], l[2]); bsplit(f.w, h[3], l[3]);
    uint2 hv = make_uint2((uint32_t)h[0] | ((uint32_t)h[1] << 16),
                          (uint32_t)h[2] | ((uint32_t)h[3] << 16));
    uint2 lv = make_uint2((uint32_t)l[0] | ((uint32_t)l[1] << 16),
                          (uint32_t)l[2] | ((uint32_t)l[3] << 16));
    *(uint2*)&oh[i] = hv;
    *(uint2*)&ol[i] = lv;
}

// ==================== bf16-split mma.sync GEMM ===============================
#define GS_ROW 40
#define GS_ARR (128*GS_ROW)                 // 5120 halves
#define GS_BUF (4*GS_ARR)                   // 20480 halves
#define SMEM_GEMM (2*GS_BUF*2)              // 81920 bytes

__global__ __launch_bounds__(256, 2)
void gemm_bf16(const __nv_bfloat16* __restrict__ Ah0, const __nv_bfloat16* __restrict__ Al0,
               const __nv_bfloat16* __restrict__ Ah1, const __nv_bfloat16* __restrict__ Al1,
               const __nv_bfloat16* __restrict__ Ah2, const __nv_bfloat16* __restrict__ Al2,
               const __nv_bfloat16* __restrict__ Bh0, const __nv_bfloat16* __restrict__ Bl0,
               const __nv_bfloat16* __restrict__ Bh1, const __nv_bfloat16* __restrict__ Bl1,
               const __nv_bfloat16* __restrict__ Bh2, const __nv_bfloat16* __restrict__ Bl2,
               const float* __restrict__ bias0, const float* __restrict__ bias1,
               const float* __restrict__ bias2,
               float* __restrict__ C0, float* __restrict__ C1, float* __restrict__ C2,
               __nv_bfloat16* __restrict__ Sh0, __nv_bfloat16* __restrict__ Sl0,
               __nv_bfloat16* __restrict__ Sh1, __nv_bfloat16* __restrict__ Sl1,
               __nv_bfloat16* __restrict__ Sh2, __nv_bfloat16* __restrict__ Sl2) {
    extern __shared__ __nv_bfloat16 hsm[];
    const int z = blockIdx.z;
    const __nv_bfloat16* Ah = z == 0 ? Ah0 : z == 1 ? Ah1 : Ah2;
    const __nv_bfloat16* Al = z == 0 ? Al0 : z == 1 ? Al1 : Al2;
    const __nv_bfloat16* Bh = z == 0 ? Bh0 : z == 1 ? Bh1 : Bh2;
    const __nv_bfloat16* Bl = z == 0 ? Bl0 : z == 1 ? Bl1 : Bl2;
    const float* bias = z == 0 ? bias0 : z == 1 ? bias1 : bias2;
    float* C          = z == 0 ? C0 : z == 1 ? C1 : C2;
    __nv_bfloat16* Sh = z == 0 ? Sh0 : z == 1 ? Sh1 : Sh2;
    __nv_bfloat16* Sl = z == 0 ? Sl0 : z == 1 ? Sl1 : Sl2;

    const int cb0 = blockIdx.x * 128;
    const int rb0 = blockIdx.y * 128;
    const int t = threadIdx.x;
    const int wid = t >> 5, lane = t & 31;
    const int wm = wid & 1, wn = wid >> 1;
    const uint32_t sb = stoa(hsm);

    const int srow = t >> 1, sh16 = (t & 1) * 16;
    const size_t aoff = (size_t)(rb0 + srow) * PD + sh16;
    const size_t boff = (size_t)(cb0 + srow) * PD + sh16;
    const uint32_t sdst = (uint32_t)(srow * GS_ROW + sh16) * 2;

    float d[4][4][4];
    #pragma unroll
    for (int i = 0; i < 4; i++)
        #pragma unroll
        for (int j = 0; j < 4; j++)
            #pragma unroll
            for (int r = 0; r < 4; r++) d[i][j][r] = 0.f;

    auto stage = [&](int c, int buf) {
        const uint32_t base = sb + (uint32_t)buf * GS_BUF * 2 + sdst;
        const __nv_bfloat16* s;
        s = Ah + aoff + c * 32;
        CPA16(base,                  s); CPA16(base + 16,                  s + 8);
        s = Al + aoff + c * 32;
        CPA16(base + GS_ARR*2,       s); CPA16(base + GS_ARR*2 + 16,       s + 8);
        s = Bh + boff + c * 32;
        CPA16(base + 2*GS_ARR*2,     s); CPA16(base + 2*GS_ARR*2 + 16,     s + 8);
        s = Bl + boff + c * 32;
        CPA16(base + 3*GS_ARR*2,     s); CPA16(base + 3*GS_ARR*2 + 16,     s + 8);
    };

    const uint32_t lro = (uint32_t)((lane & 15) * GS_ROW + (lane >> 4) * 8) * 2;

    stage(0, 0);
    CPCOMMIT();
    for (int c = 0; c < 16; c++) {
        CPWAIT0();
        __syncthreads();
        if (c < 15) { stage(c + 1, (c + 1) & 1); CPCOMMIT(); }
        const uint32_t ab = sb + (uint32_t)(c & 1) * GS_BUF * 2;
        const uint32_t bbh = ab + 2 * GS_ARR * 2;
        #pragma unroll
        for (int ks = 0; ks < 2; ks++) {
            uint32_t bh[4][2], bl[4][2];
            #pragma unroll
            for (int j2 = 0; j2 < 2; j2++) {
                uint32_t tb[4];
                uint32_t ba = bbh + (uint32_t)((wn*32 + j2*16) * GS_ROW + ks*16) * 2 + lro;
                LDSM4(tb, ba);
                bh[j2*2][0] = tb[0]; bh[j2*2][1] = tb[2];
                bh[j2*2+1][0] = tb[1]; bh[j2*2+1][1] = tb[3];
                LDSM4(tb, ba + GS_ARR*2);
                bl[j2*2][0] = tb[0]; bl[j2*2][1] = tb[2];
                bl[j2*2+1][0] = tb[1]; bl[j2*2+1][1] = tb[3];
            }
            #pragma unroll
            for (int mi = 0; mi < 4; mi++) {
                uint32_t ah[4], al[4];
                uint32_t aa = ab + (uint32_t)((wm*64 + mi*16) * GS_ROW + ks*16) * 2 + lro;
                LDSM4(ah, aa);
                LDSM4(al, aa + GS_ARR*2);
                #pragma unroll
                for (int nj = 0; nj < 4; nj++) {
                    MMABF16(d[mi][nj], ah, bh[nj][0], bh[nj][1]);
                    MMABF16(d[mi][nj], ah, bl[nj][0], bl[nj][1]);
                    MMABF16(d[mi][nj], al, bh[nj][0], bh[nj][1]);
                }
            }
        }
    }

    const int g = lane >> 2, tq = lane & 3;
    #pragma unroll
    for (int mi = 0; mi < 4; mi++) {
        const int row = rb0 + wm*64 + mi*16 + g;
        #pragma unroll
        for (int nj = 0; nj < 4; nj++) {
            const int col = cb0 + wn*32 + nj*8 + tq*2;
            float2 bv = *(const float2*)&bias[col];
            float o0 = d[mi][nj][0] + bv.x, o1 = d[mi][nj][1] + bv.y;
            float o2 = d[mi][nj][2] + bv.x, o3 = d[mi][nj][3] + bv.y;
            if (C) {
                *(float2*)&C[(size_t)row * PD + col]       = make_float2(o0, o1);
                *(float2*)&C[(size_t)(row + 8) * PD + col] = make_float2(o2, o3);
            }
            if (Sh) {
                ushort h0,l0,h1,l1,h2,l2,h3,l3;
                bsplit(o0,h0,l0); bsplit(o1,h1,l1);
                bsplit(o2,h2,l2); bsplit(o3,h3,l3);
                *(uint32_t*)&Sh[(size_t)row * PD + col]       = (uint32_t)h0 | ((uint32_t)h1 << 16);
                *(uint32_t*)&Sl[(size_t)row * PD + col]       = (uint32_t)l0 | ((uint32_t)l1 << 16);
                *(uint32_t*)&Sh[(size_t)(row + 8) * PD + col] = (uint32_t)h2 | ((uint32_t)h3 << 16);
                *(uint32_t*)&Sl[(size_t)(row + 8) * PD + col] = (uint32_t)l2 | ((uint32_t)l3 << 16);
            }
        }
    }
}

// ------------------------- FiLM scale/shift prep ----------------------------
__global__ __launch_bounds__(128)
void film_prep(const float* __restrict__ latent, const float* __restrict__ Ws1,
               const float* __restrict__ bs1, float* __restrict__ ss) {
    const int b = blockIdx.y;
    const int col = blockIdx.x * 128 + threadIdx.x;
    __shared__ float ls[512];
    for (int i = threadIdx.x; i < 512; i += 128) {
        float x = latent[(size_t)b * 512 + i];
        ls[i] = x / (1.f + __expf(-x));
    }
    __syncthreads();
    float sum = 0.f;
    #pragma unroll 8
    for (int k = 0; k < 512; k++) sum += ls[k] * Ws1[(size_t)k * 1024 + col];
    ss[(size_t)b * 1024 + col] = sum + bs1[col];
}

// ------------------------- block reduce helper ------------------------------
__device__ __forceinline__ float2 blockReduceSum2(float s1, float s2) {
    __shared__ float sh[8];
    #pragma unroll
    for (int off = 16; off; off >>= 1) {
        s1 += __shfl_xor_sync(0xffffffffu, s1, off);
        s2 += __shfl_xor_sync(0xffffffffu, s2, off);
    }
    const int w = threadIdx.x >> 5;
    if ((threadIdx.x & 31) == 0) { sh[w * 2] = s1; sh[w * 2 + 1] = s2; }
    __syncthreads();
    float a = 0.f, b = 0.f;
    const int nw = blockDim.x >> 5;
    for (int i = 0; i < nw; i++) { a += sh[i * 2]; b += sh[i * 2 + 1]; }
    return make_float2(a, b);
}

// --------- FiLM apply: LN -> FiLM -> SiLU, fused bf16 split output ----------
__global__ __launch_bounds__(128)
void film_apply(const float* __restrict__ ofc, const float* __restrict__ ss,
                const float* __restrict__ g, const float* __restrict__ be,
                __nv_bfloat16* __restrict__ hsh, __nv_bfloat16* __restrict__ hsl) {
    const int row = blockIdx.x;
    const int b = row >> 10;
    const int t = threadIdx.x;
    const float* xr = ofc + (size_t)row * 512;
    float x[4]; float s1 = 0.f, s2 = 0.f;
    #pragma unroll
    for (int i = 0; i < 4; i++) {
        x[i] = xr[t + i * 128];
        s1 += x[i]; s2 += x[i] * x[i];
    }
    float2 r = blockReduceSum2(s1, s2);
    const float mean = r.x * (1.f / 512.f);
    const float var  = r.y * (1.f / 512.f) - mean * mean;
    const float rstd = rsqrtf(var + 1e-5f);
    const float* ssb = ss + (size_t)b * 1024;
    #pragma unroll
    for (int i = 0; i < 4; i++) {
        const int c = t + i * 128;
        float ln = (x[i] - mean) * rstd * g[c] + be[c];
        float h = ln * (1.f + ssb[c]) + ssb[512 + c];
        h = h / (1.f + __expf(-h));
        ushort hh, ll;
        bsplit(h, hh, ll);
        hsh[(size_t)row * 512 + c] = __ushort_as_bfloat16(hh);
        hsl[(size_t)row * 512 + c] = __ushort_as_bfloat16(ll);
    }
}

// ------------------------- final: LN(h2 + residual) -------------------------
__global__ __launch_bounds__(128)
void final_ln(const float* __restrict__ h2, const float* __restrict__ resid,
              const float* __restrict__ g, const float* __restrict__ be,
              float* __restrict__ out) {
    const int row = blockIdx.x;
    const int t = threadIdx.x;
    const float* hr = h2 + (size_t)row * 512;
    const float* rr = resid + (size_t)row * 512;
    float x[4]; float s1 = 0.f, s2 = 0.f;
    #pragma unroll
    for (int i = 0; i < 4; i++) {
        x[i] = hr[t + i * 128] + rr[t + i * 128];
        s1 += x[i]; s2 += x[i] * x[i];
    }
    float2 r = blockReduceSum2(s1, s2);
    const float mean = r.x * (1.f / 512.f);
    const float var  = r.y * (1.f / 512.f) - mean * mean;
    const float rstd = rsqrtf(var + 1e-6f);
    float* orow = out + (size_t)row * 512;
    #pragma unroll
    for (int i = 0; i < 4; i++) {
        const int c = t + i * 128;
        orow[c] = (x[i] - mean) * rstd * g[c] + be[c];
    }
}

// ============ tensorized attention, register-resident S (FA-style) ==========
// One CTA per (b, h, 32 q rows). S (exp'd, unnormalized) stays in registers.
// KEY (this round): K/V staging is warp-private by row — warp w stages and
// consumes exactly rows 16w..16w+15 of every buffer — so per-chunk block
// barriers are replaced by per-warp cp.async waits + __syncwarp(). Warps
// free-run their own depth-2 pipelines and hide each other's latency.
// Block syncs remain only for: Q staging (cross-warp), softmax row stats,
// and the final O reduction scratch.
#define AT_QHO 0u
#define AT_QLO 4608u
#define AT_KV  10240u
#define AT_KVB 36864u
#define AT_SPL 18432u
#define AT_SMEM (10240 + 4*36864)

__global__ __launch_bounds__(256, 1)
void attn_mma(const __nv_bfloat16* __restrict__ Qh, const __nv_bfloat16* __restrict__ Ql,
              const __nv_bfloat16* __restrict__ Kh, const __nv_bfloat16* __restrict__ Kl,
              const __nv_bfloat16* __restrict__ Vh, const __nv_bfloat16* __restrict__ Vl,
              float* __restrict__ attn,
              __nv_bfloat16* __restrict__ Oh, __nv_bfloat16* __restrict__ Ol) {
    extern __shared__ char smem[];
    const uint32_t sb = stoa(smem);

    const int b = blockIdx.z, h = blockIdx.y;
    const int q0 = blockIdx.x * 32;
    const int t = threadIdx.x;
    const int w = t >> 5, lane = t & 31;
    const int g = lane >> 2, tq = lane & 3;

    // ---- stage Q (32 rows x 128B x hi/lo) — cross-warp, needs block sync
    {
        int row = t >> 3, seg = t & 7;
        size_t src = (size_t)(b * 1024 + q0 + row) * 512 + h * 64 + seg * 8;
        CPA16(sb + AT_QHO + row * 144 + seg * 16, Qh + src);
        CPA16(sb + AT_QLO + row * 144 + seg * 16, Ql + src);
    }
    // warp w stages rows 16w..16w+15 (row = t>>1) — exactly the rows it reads
    auto stageKV = [&](const __nv_bfloat16* Xh, const __nv_bfloat16* Xl, int c, int buf) {
        int row = t >> 1, hf = t & 1;
        size_t src = (size_t)(b * 1024 + c * 128 + row) * 512 + h * 64 + hf * 32;
        uint32_t dst = sb + AT_KV + (uint32_t)buf * AT_KVB + row * 144 + hf * 64;
        #pragma unroll
        for (int i = 0; i < 4; i++) {
            CPA16(dst + i * 16,          Xh + src + i * 8);
            CPA16(dst + AT_SPL + i * 16, Xl + src + i * 8);
        }
    };

    stageKV(Kh, Kl, 0, 0);   // group 0: Q + K0
    CPCOMMIT();
    stageKV(Kh, Kl, 1, 1);   // group 1: K1
    CPCOMMIT();
    CPWAIT1();               // Q + K0 ready
    __syncthreads();         // Q cross-warp visibility (one-time)

    // ---- preload Q fragments: [split][mi][ks][4]
    uint32_t qa[2][2][4][4];
    #pragma unroll
    for (int s = 0; s < 2; s++)
        #pragma unroll
        for (int mi = 0; mi < 2; mi++)
            #pragma unroll
            for (int ks = 0; ks < 4; ks++) {
                uint32_t a = sb + (s ? AT_QLO : AT_QHO)
                           + (mi * 16 + (lane & 15)) * 144 + ks * 32 + (lane >> 4) * 16;
                LDSM4(qa[s][mi][ks], a);
            }

    // ---- Phase 1: S = Q K^T, warp-autonomous pipeline ----
    float acc[8][2][2][4];
    #pragma unroll
    for (int c = 0; c < 8; c++)
        #pragma unroll
        for (int mi = 0; mi < 2; mi++)
            #pragma unroll
            for (int nj = 0; nj < 2; nj++)
                #pragma unroll
                for (int r = 0; r < 4; r++) acc[c][mi][nj][r] = 0.f;

    #pragma unroll
    for (int c = 0; c < 8; c++) {
        if (c > 0) {
            if (c < 7) { CPWAIT1(); } else { CPWAIT0(); }
            __syncwarp();
        }
        if (c + 2 < 8) { stageKV(Kh, Kl, c + 2, (c + 2) & 3); CPCOMMIT(); }
        const uint32_t kb = sb + AT_KV + (uint32_t)(c & 3) * AT_KVB;
        #pragma unroll
        for (int ks = 0; ks < 4; ks++) {
            uint32_t kh4[4], kl4[4];
            uint32_t ka = kb + (w * 16 + (lane & 15)) * 144 + ks * 32 + (lane >> 4) * 16;
            LDSM4(kh4, ka);
            LDSM4(kl4, ka + AT_SPL);
            #pragma unroll
            for (int mi = 0; mi < 2; mi++) {
                MMABF16(acc[c][mi][0], qa[0][mi][ks], kh4[0], kh4[2]);
                MMABF16(acc[c][mi][1], qa[0][mi][ks], kh4[1], kh4[3]);
                MMABF16(acc[c][mi][0], qa[0][mi][ks], kl4[0], kl4[2]);
                MMABF16(acc[c][mi][1], qa[0][mi][ks], kl4[1], kl4[3]);
                MMABF16(acc[c][mi][0], qa[1][mi][ks], kh4[0], kh4[2]);
                MMABF16(acc[c][mi][1], qa[1][mi][ks], kh4[1], kh4[3]);
            }
        }
    }

    // prefetch V chunks 0,1 while softmax runs (rows are warp-private, so
    // overwriting buffers 0/1 cannot race with lagging warps' K reads)
    stageKV(Vh, Vl, 0, 0); CPCOMMIT();
    stageKV(Vh, Vl, 1, 1); CPCOMMIT();

    // ---- Phase 2: in-register softmax stats; row stats via smem [32][8] ----
    float* red = (float*)smem;       // max at [0,256), sum at [256,512)
    float mxv[2][2], inv[2][2];
    #pragma unroll
    for (int mi = 0; mi < 2; mi++)
        #pragma unroll
        for (int hf = 0; hf < 2; hf++) {
            float m = -1e30f;
            #pragma unroll
            for (int c = 0; c < 8; c++)
                #pragma unroll
                for (int nj = 0; nj < 2; nj++)
                    m = fmaxf(m, fmaxf(acc[c][mi][nj][hf*2], acc[c][mi][nj][hf*2+1]));
            m = fmaxf(m, __shfl_xor_sync(0xffffffffu, m, 1));
            m = fmaxf(m, __shfl_xor_sync(0xffffffffu, m, 2));
            if (tq == 0) red[(mi*16 + hf*8 + g) * 8 + w] = m;
        }
    __syncthreads();
    #pragma unroll
    for (int mi = 0; mi < 2; mi++)
        #pragma unroll
        for (int hf = 0; hf < 2; hf++) {
            const int row = mi*16 + hf*8 + g;
            float m = red[row*8];
            #pragma unroll
            for (int ww = 1; ww < 8; ww++) m = fmaxf(m, red[row*8 + ww]);
            mxv[mi][hf] = m;
        }
    #pragma unroll
    for (int mi = 0; mi < 2; mi++)
        #pragma unroll
        for (int hf = 0; hf < 2; hf++) {
            float s = 0.f;
            #pragma unroll
            for (int c = 0; c < 8; c++)
                #pragma unroll
                for (int nj = 0; nj < 2; nj++)
                    #pragma unroll
                    for (int kk = 0; kk < 2; kk++) {
                        float& v = acc[c][mi][nj][hf*2 + kk];
                        v = __expf((v - mxv[mi][hf]) * 0.125f);
                        s += v;
                    }
            s += __shfl_xor_sync(0xffffffffu, s, 1);
            s += __shfl_xor_sync(0xffffffffu, s, 2);
            if (tq == 0) red[256 + (mi*16 + hf*8 + g) * 8 + w] = s;
        }
    __syncthreads();
    #pragma unroll
    for (int mi = 0; mi < 2; mi++)
        #pragma unroll
        for (int hf = 0; hf < 2; hf++) {
            const int row = mi*16 + hf*8 + g;
            float s = 0.f;
            #pragma unroll
            for (int ww = 0; ww < 8; ww++) s += red[256 + row*8 + ww];
            inv[mi][hf] = 1.f / s;
        }

    // ---- Phase 3: per V-chunk JIT P + PV MMAs, warp-autonomous pipeline ----
    float oacc[2][8][4];
    #pragma unroll
    for (int mi = 0; mi < 2; mi++)
        #pragma unroll
        for (int nj = 0; nj < 8; nj++)
            #pragma unroll
            for (int r = 0; r < 4; r++) oacc[mi][nj][r] = 0.f;

    float* attn_b = attn + (((size_t)(b * 8 + h)) * 1024 + q0) * 1024;

    CPWAIT1();               // V0 ready (this thread's copies)
    __syncwarp();
    #pragma unroll
    for (int c = 0; c < 8; c++) {
        if (c > 0) {
            if (c < 7) { CPWAIT1(); } else { CPWAIT0(); }
            __syncwarp();
        }
        if (c + 2 < 8) { stageKV(Vh, Vl, c + 2, (c + 2) & 3); CPCOMMIT(); }

        // JIT P materialization for this chunk
        uint32_t pah[2][4], pal[2][4];
        #pragma unroll
        for (int mi = 0; mi < 2; mi++) {
            const int row0 = mi * 16 + g;
            const int col = c * 128 + w * 16 + tq * 2;
            float p00 = acc[c][mi][0][0] * inv[mi][0];
            float p01 = acc[c][mi][0][1] * inv[mi][0];
            float p02 = acc[c][mi][0][2] * inv[mi][1];
            float p03 = acc[c][mi][0][3] * inv[mi][1];
            float p10 = acc[c][mi][1][0] * inv[mi][0];
            float p11 = acc[c][mi][1][1] * inv[mi][0];
            float p12 = acc[c][mi][1][2] * inv[mi][1];
            float p13 = acc[c][mi][1][3] * inv[mi][1];
            *(float2*)&attn_b[(size_t)row0 * 1024 + col]           = make_float2(p00, p01);
            *(float2*)&attn_b[(size_t)(row0 + 8) * 1024 + col]     = make_float2(p02, p03);
            *(float2*)&attn_b[(size_t)row0 * 1024 + col + 8]       = make_float2(p10, p11);
            *(float2*)&attn_b[(size_t)(row0 + 8) * 1024 + col + 8] = make_float2(p12, p13);
            ushort h00,l00,h01,l01,h02,l02,h03,l03;
            ushort h10,l10,h11,l11,h12,l12,h13,l13;
            bsplit(p00,h00,l00); bsplit(p01,h01,l01);
            bsplit(p02,h02,l02); bsplit(p03,h03,l03);
            bsplit(p10,h10,l10); bsplit(p11,h11,l11);
            bsplit(p12,h12,l12); bsplit(p13,h13,l13);
            pah[mi][0] = (uint32_t)h00 | ((uint32_t)h01 << 16);
            pah[mi][1] = (uint32_t)h02 | ((uint32_t)h03 << 16);
            pah[mi][2] = (uint32_t)h10 | ((uint32_t)h11 << 16);
            pah[mi][3] = (uint32_t)h12 | ((uint32_t)h13 << 16);
            pal[mi][0] = (uint32_t)l00 | ((uint32_t)l01 << 16);
            pal[mi][1] = (uint32_t)l02 | ((uint32_t)l03 << 16);
            pal[mi][2] = (uint32_t)l10 | ((uint32_t)l11 << 16);
            pal[mi][3] = (uint32_t)l12 | ((uint32_t)l13 << 16);
        }

        const uint32_t vb = sb + AT_KV + (uint32_t)(c & 3) * AT_KVB;
        #pragma unroll
        for (int dd = 0; dd < 4; dd++) {
            uint32_t vbh[4], vbl[4];
            uint32_t va = vb + (w * 16 + (lane & 15)) * 144 + dd * 32 + (lane >> 4) * 16;
            LDSMT4(vbh, va);
            LDSMT4(vbl, va + AT_SPL);
            #pragma unroll
            for (int mi = 0; mi < 2; mi++) {
                MMABF16(oacc[mi][dd*2],   pah[mi], vbh[0], vbh[1]);
                MMABF16(oacc[mi][dd*2+1], pah[mi], vbh[2], vbh[3]);
                MMABF16(oacc[mi][dd*2],   pah[mi], vbl[0], vbl[1]);
                MMABF16(oacc[mi][dd*2+1], pah[mi], vbl[2], vbl[3]);
                MMABF16(oacc[mi][dd*2],   pal[mi], vbh[0], vbh[1]);
                MMABF16(oacc[mi][dd*2+1], pal[mi], vbh[2], vbh[3]);
            }
        }
    }
    __syncthreads();   // all warps done with V buffers before scratch reuse

    // ---- cross-warp O reduction in smem (reuse KV region) ----
    float* scr = (float*)(smem + AT_KV);
    #pragma unroll
    for (int mi = 0; mi < 2; mi++) {
        const int q = mi * 16 + g;
        #pragma unroll
        for (int nj = 0; nj < 8; nj++) {
            const int d = nj * 8 + tq * 2;
            *(float2*)&scr[w * 2048 + q * 64 + d] =
                make_float2(oacc[mi][nj][0], oacc[mi][nj][1]);
            *(float2*)&scr[w * 2048 + (q + 8) * 64 + d] =
                make_float2(oacc[mi][nj][2], oacc[mi][nj][3]);
        }
    }
    __syncthreads();
    {
        const int base = t * 8;
        const int q = base >> 6, d = base & 63;
        float r8[8];
        #pragma unroll
        for (int j = 0; j < 8; j++) r8[j] = 0.f;
        #pragma unroll
        for (int ww = 0; ww < 8; ww++) {
            float4 a = *(float4*)&scr[ww * 2048 + base];
            float4 c = *(float4*)&scr[ww * 2048 + base + 4];
            r8[0] += a.x; r8[1] += a.y; r8[2] += a.z; r8[3] += a.w;
            r8[4] += c.x; r8[5] += c.y; r8[6] += c.z; r8[7] += c.w;
        }
        ushort hh[8], ll[8];
        #pragma unroll
        for (int j = 0; j < 8; j++) bsplit(r8[j], hh[j], ll[j]);
        uint4 hv, lv;
        hv.x = (uint32_t)hh[0] | ((uint32_t)hh[1] << 16);
        hv.y = (uint32_t)hh[2] | ((uint32_t)hh[3] << 16);
        hv.z = (uint32_t)hh[4] | ((uint32_t)hh[5] << 16);
        hv.w = (uint32_t)hh[6] | ((uint32_t)hh[7] << 16);
        lv.x = (uint32_t)ll[0] | ((uint32_t)ll[1] << 16);
        lv.y = (uint32_t)ll[2] | ((uint32_t)ll[3] << 16);
        lv.z = (uint32_t)ll[4] | ((uint32_t)ll[5] << 16);
        lv.w = (uint32_t)ll[6] | ((uint32_t)ll[7] << 16);
        const size_t orow = (size_t)(b * 1024 + q0 + q) * 512 + h * 64 + d;
        *(uint4*)&Oh[orow] = hv;
        *(uint4*)&Ol[orow] = lv;
    }
}

// ------------------------- launch -------------------------------------------
extern "C" void kernel_launch(void* const* d_in, const int* in_sizes, int n_in,
                              void* d_out, int out_size) {
    const float* q      = (const float*)d_in[0];
    const float* k      = (const float*)d_in[1];
    const float* v      = (const float*)d_in[2];
    const float* latent = (const float*)d_in[3];
    const float* Wq     = (const float*)d_in[4];
    const float* bq     = (const float*)d_in[5];
    const float* Wk     = (const float*)d_in[6];
    const float* bk     = (const float*)d_in[7];
    const float* Wv     = (const float*)d_in[8];
    const float* bv     = (const float*)d_in[9];
    const float* Wfc    = (const float*)d_in[10];
    const float* bfc    = (const float*)d_in[11];
    const float* Ws1    = (const float*)d_in[12];
    const float* bs1    = (const float*)d_in[13];
    const float* Ws2    = (const float*)d_in[14];
    const float* bs2    = (const float*)d_in[15];
    const float* en_g   = (const float*)d_in[16];
    const float* en_b   = (const float*)d_in[17];
    const float* ln_g   = (const float*)d_in[18];
    const float* ln_b   = (const float*)d_in[19];

    float* out  = (float*)d_out;                       // [B,L,D]
    float* attn = out + (size_t)BLD * PD;              // [B,H,L,L]

    float *gOFC, *gH2, *gSS;
    cudaGetSymbolAddress((void**)&gOFC, g_OFC);
    cudaGetSymbolAddress((void**)&gH2,  g_H2);
    cudaGetSymbolAddress((void**)&gSS,  g_SS);

    __nv_bfloat16 *qh,*ql,*kh,*kl,*vh,*vl;
    __nv_bfloat16 *Qh,*Ql,*Kh,*Kl,*Vh,*Vl,*Oh,*Ol,*HSh,*HSl,*Wth,*Wtl;
    cudaGetSymbolAddress((void**)&qh, g_qh);  cudaGetSymbolAddress((void**)&ql, g_ql);
    cudaGetSymbolAddress((void**)&kh, g_kh);  cudaGetSymbolAddress((void**)&kl, g_kl);
    cudaGetSymbolAddress((void**)&vh, g_vh);  cudaGetSymbolAddress((void**)&vl, g_vl);
    cudaGetSymbolAddress((void**)&Qh, g_Qh);  cudaGetSymbolAddress((void**)&Ql, g_Ql);
    cudaGetSymbolAddress((void**)&Kh, g_Kh);  cudaGetSymbolAddress((void**)&Kl, g_Kl);
    cudaGetSymbolAddress((void**)&Vh, g_Vh);  cudaGetSymbolAddress((void**)&Vl, g_Vl);
    cudaGetSymbolAddress((void**)&Oh, g_Oh);  cudaGetSymbolAddress((void**)&Ol, g_Ol);
    cudaGetSymbolAddress((void**)&HSh, g_HSh); cudaGetSymbolAddress((void**)&HSl, g_HSl);
    cudaGetSymbolAddress((void**)&Wth, g_Wth); cudaGetSymbolAddress((void**)&Wtl, g_Wtl);

    cudaFuncSetAttribute(attn_mma,
                         cudaFuncAttributeMaxDynamicSharedMemorySize, AT_SMEM);
    cudaFuncSetAttribute(gemm_bf16,
                         cudaFuncAttributeMaxDynamicSharedMemorySize, SMEM_GEMM);

    const size_t WSZ = (size_t)PD * PD;

    wprep<<<dim3(16, 16, 5), 256>>>(Wq, Wk, Wv, Wfc, Ws2, Wth, Wtl);
    split3<<<dim3(4096, 1, 3), 256>>>(q, k, v, qh, ql, kh, kl, vh, vl);
    film_prep<<<dim3(8, PB), 128>>>(latent, Ws1, bs1, gSS);

    // QKV projections -> bf16 split outputs only
    gemm_bf16<<<dim3(4, 64, 3), 256, SMEM_GEMM>>>(
        qh, ql, kh, kl, vh, vl,
        Wth, Wtl, Wth + WSZ, Wtl + WSZ, Wth + 2*WSZ, Wtl + 2*WSZ,
        bq, bk, bv,
        nullptr, nullptr, nullptr,
        Qh, Ql, Kh, Kl, Vh, Vl);

    attn_mma<<<dim3(PL / 32, PH, PB), 256, AT_SMEM>>>(
        Qh, Ql, Kh, Kl, Vh, Vl, attn, Oh, Ol);

    // FC -> fp32
    gemm_bf16<<<dim3(4, 64, 1), 256, SMEM_GEMM>>>(
        Oh, Ol, Oh, Ol, Oh, Ol,
        Wth + 3*WSZ, Wtl + 3*WSZ, Wth + 3*WSZ, Wtl + 3*WSZ, Wth + 3*WSZ, Wtl + 3*WSZ,
        bfc, bfc, bfc, gOFC, gOFC, gOFC,
        nullptr, nullptr, nullptr, nullptr, nullptr, nullptr);

    film_apply<<<BLD, 128>>>(gOFC, gSS, en_g, en_b, HSh, HSl);

    // S2 -> fp32
    gemm_bf16<<<dim3(4, 64, 1), 256, SMEM_GEMM>>>(
        HSh, HSl, HSh, HSl, HSh, HSl,
        Wth + 4*WSZ, Wtl + 4*WSZ, Wth + 4*WSZ, Wtl + 4*WSZ, Wth + 4*WSZ, Wtl + 4*WSZ,
        bs2, bs2, bs2, gH2, gH2, gH2,
        nullptr, nullptr, nullptr, nullptr, nullptr, nullptr);

    final_ln<<<BLD, 128>>>(gH2, q, ln_g, ln_b, out);
}